// round 6
// baseline (speedup 1.0000x reference)
#include <cuda_runtime.h>
#include <cuda_bf16.h>
#include <cuda_fp16.h>
#include <cstdint>
#include <math.h>

#define S 2048
#define D 2048
#define H 32
#define KVH 8
#define HD 64
#define NREP (H / KVH)
#define QKV_N 3072
#define KCOL 2048
#define VCOL 2560

// ---------------------------------------------------------------------------
// Device-global scratch
// ---------------------------------------------------------------------------
__device__ __nv_bfloat16 g_Xhi[S * D], g_Xlo[S * D];
__device__ __nv_bfloat16 g_WqkvThi[QKV_N * D], g_WqkvTlo[QKV_N * D];
__device__ __nv_bfloat16 g_Qhi[S * H * HD], g_Qlo[S * H * HD];
__device__ __nv_bfloat16 g_Khi[S * KVH * HD], g_Klo[S * KVH * HD];
__device__ __nv_bfloat16 g_Vhi[S * KVH * HD], g_Vlo[S * KVH * HD];
__device__ __half g_O16[S * D];
__device__ __half g_WoT16[D * D];
__device__ float g_cos[S * 32], g_sin[S * 32];

// ---------------------------------------------------------------------------
// Helpers
// ---------------------------------------------------------------------------
__device__ __forceinline__ uint32_t smem_u32(const void* p) {
  uint32_t a;
  asm("{ .reg .u64 t; cvta.to.shared.u64 t, %1; cvt.u32.u64 %0, t; }"
      : "=r"(a) : "l"(p));
  return a;
}

__device__ __forceinline__ void ldsm_x4(uint32_t* r, uint32_t addr) {
  asm volatile(
      "ldmatrix.sync.aligned.m8n8.x4.shared.b16 {%0,%1,%2,%3}, [%4];"
      : "=r"(r[0]), "=r"(r[1]), "=r"(r[2]), "=r"(r[3]) : "r"(addr));
}

__device__ __forceinline__ void ldsm_x4_trans(uint32_t* r, uint32_t addr) {
  asm volatile(
      "ldmatrix.sync.aligned.m8n8.x4.trans.shared.b16 {%0,%1,%2,%3}, [%4];"
      : "=r"(r[0]), "=r"(r[1]), "=r"(r[2]), "=r"(r[3]) : "r"(addr));
}

__device__ __forceinline__ void mma16816(float* d, const uint32_t* a,
                                         const uint32_t* b) {
  asm volatile(
      "mma.sync.aligned.m16n8k16.row.col.f32.bf16.bf16.f32 "
      "{%0,%1,%2,%3}, {%4,%5,%6,%7}, {%8,%9}, {%0,%1,%2,%3};"
      : "+f"(d[0]), "+f"(d[1]), "+f"(d[2]), "+f"(d[3])
      : "r"(a[0]), "r"(a[1]), "r"(a[2]), "r"(a[3]), "r"(b[0]), "r"(b[1]));
}

__device__ __forceinline__ void mma16816h(float* d, const uint32_t* a,
                                          const uint32_t* b) {
  asm volatile(
      "mma.sync.aligned.m16n8k16.row.col.f32.f16.f16.f32 "
      "{%0,%1,%2,%3}, {%4,%5,%6,%7}, {%8,%9}, {%0,%1,%2,%3};"
      : "+f"(d[0]), "+f"(d[1]), "+f"(d[2]), "+f"(d[3])
      : "r"(a[0]), "r"(a[1]), "r"(a[2]), "r"(a[3]), "r"(b[0]), "r"(b[1]));
}

__device__ __forceinline__ void cp_async16(uint32_t saddr, const void* gptr) {
  asm volatile("cp.async.cg.shared.global [%0], [%1], 16;" ::
                   "r"(saddr), "l"(__cvta_generic_to_global(gptr)));
}
#define CP_COMMIT() asm volatile("cp.async.commit_group;" ::: "memory")
#define CP_WAIT0() asm volatile("cp.async.wait_group 0;" ::: "memory")
#define CP_WAIT1() asm volatile("cp.async.wait_group 1;" ::: "memory")

__device__ __forceinline__ float exp2_poly(float x) {
  x = fmaxf(x, -126.0f);
  float fl = floorf(x);
  float f = x - fl;
  float p = 1.5403530393e-4f;
  p = fmaf(p, f, 1.3333558146e-3f);
  p = fmaf(p, f, 9.6181291076e-3f);
  p = fmaf(p, f, 5.5504108665e-2f);
  p = fmaf(p, f, 2.4022650696e-1f);
  p = fmaf(p, f, 6.9314718056e-1f);
  p = fmaf(p, f, 1.0f);
  return p * __int_as_float(((int)fl + 127) << 23);
}

__device__ __forceinline__ void split2(float x, __nv_bfloat16& h, __nv_bfloat16& l) {
  h = __float2bfloat16(x);
  l = __float2bfloat16(x - __bfloat162float(h));
}

__device__ __forceinline__ void split_pack2(float x, float y, uint32_t& h,
                                            uint32_t& l) {
  __nv_bfloat162 hb = __floats2bfloat162_rn(x, y);
  float xr = x - __bfloat162float(hb.x);
  float yr = y - __bfloat162float(hb.y);
  __nv_bfloat162 lb = __floats2bfloat162_rn(xr, yr);
  h = *reinterpret_cast<uint32_t*>(&hb);
  l = *reinterpret_cast<uint32_t*>(&lb);
}

// ---------------------------------------------------------------------------
// Preprocessing
// ---------------------------------------------------------------------------
__global__ void split_kernel(const float* __restrict__ in,
                             __nv_bfloat16* __restrict__ hi,
                             __nv_bfloat16* __restrict__ lo, int n4) {
  int i = blockIdx.x * blockDim.x + threadIdx.x;
  if (i >= n4) return;
  float4 v = ((const float4*)in)[i];
  __nv_bfloat16 h0, l0, h1, l1, h2, l2, h3, l3;
  split2(v.x, h0, l0); split2(v.y, h1, l1);
  split2(v.z, h2, l2); split2(v.w, h3, l3);
  __nv_bfloat162* hp = (__nv_bfloat162*)hi;
  __nv_bfloat162* lp = (__nv_bfloat162*)lo;
  hp[i * 2 + 0] = __halves2bfloat162(h0, h1);
  hp[i * 2 + 1] = __halves2bfloat162(h2, h3);
  lp[i * 2 + 0] = __halves2bfloat162(l0, l1);
  lp[i * 2 + 1] = __halves2bfloat162(l2, l3);
}

__global__ void transpose_split_kernel(const float* __restrict__ W,
                                       __nv_bfloat16* __restrict__ Thi,
                                       __nv_bfloat16* __restrict__ Tlo,
                                       int N, int K) {
  __shared__ float t[32][33];
  int n0 = blockIdx.x * 32, k0 = blockIdx.y * 32;
  int tx = threadIdx.x, ty = threadIdx.y;
#pragma unroll
  for (int i = 0; i < 4; i++)
    t[ty + i * 8][tx] = W[(size_t)(k0 + ty + i * 8) * N + n0 + tx];
  __syncthreads();
#pragma unroll
  for (int i = 0; i < 4; i++) {
    int n = ty + i * 8;
    float x = t[tx][n];
    __nv_bfloat16 h, l;
    split2(x, h, l);
    size_t o = (size_t)(n0 + n) * K + k0 + tx;
    Thi[o] = h;
    Tlo[o] = l;
  }
}

__global__ void transpose_half_kernel(const float* __restrict__ W,
                                      __half* __restrict__ T, int N, int K) {
  __shared__ float t[32][33];
  int n0 = blockIdx.x * 32, k0 = blockIdx.y * 32;
  int tx = threadIdx.x, ty = threadIdx.y;
#pragma unroll
  for (int i = 0; i < 4; i++)
    t[ty + i * 8][tx] = W[(size_t)(k0 + ty + i * 8) * N + n0 + tx];
  __syncthreads();
#pragma unroll
  for (int i = 0; i < 4; i++) {
    int n = ty + i * 8;
    T[(size_t)(n0 + n) * K + k0 + tx] = __float2half(t[tx][n]);
  }
}

__global__ void rope_table_kernel() {
  int idx = blockIdx.x * blockDim.x + threadIdx.x;
  if (idx >= S * 32) return;
  int s = idx >> 5, i = idx & 31;
  float inv = 1.0f / powf(10000.0f, (2.0f * i) / (float)HD);
  float ang = (float)s * inv;
  g_cos[idx] = cosf(ang);
  g_sin[idx] = sinf(ang);
}

// ---------------------------------------------------------------------------
// QKV projection GEMM (bf16x3) with fused RoPE + hi/lo split epilogue.
// 128x192x32 tiles, 3-stage cp.async, 1 CTA/SM, 8 warps (warp tile 32x96).
// ---------------------------------------------------------------------------
#define GBM 128
#define GBN 192
#define GKC 32
#define RS 40
#define A_TILE (128 * RS * 2)            // 10240 B
#define B_TILE (192 * RS * 2)            // 15360 B
#define Q_ST_AH 0
#define Q_ST_AL A_TILE
#define Q_ST_BH (2 * A_TILE)
#define Q_ST_BL (2 * A_TILE + B_TILE)
#define QSTAGE_B (2 * A_TILE + 2 * B_TILE)  // 51200 B
#define QKV_SMEM (3 * QSTAGE_B)             // 153600 B

__global__ __launch_bounds__(256, 1) void gemm_qkv_rope_kernel(
    const __nv_bfloat16* __restrict__ Ahi, const __nv_bfloat16* __restrict__ Alo,
    const __nv_bfloat16* __restrict__ Bhi, const __nv_bfloat16* __restrict__ Blo) {
  extern __shared__ char smem[];
  const uint32_t sbase = smem_u32(smem);
  const int tid = threadIdx.x;
  const int wid = tid >> 5;
  const int lane = tid & 31;
  const int m0 = blockIdx.y * GBM;
  const int n0 = blockIdx.x * GBN;
  const int NC = D / GKC;  // 64

  const int wm = (wid & 3) * 32;
  const int wn = (wid >> 2) * 96;
  const int lrow = lane & 7;
  const int ltile = lane >> 3;
  const int a_r = (ltile & 1) * 8 + lrow;
  const int a_c = (ltile >> 1) * 8;
  const int b_r = (ltile >> 1) * 8 + lrow;
  const int b_c = (ltile & 1) * 8;

  auto load_stage = [&](int stg, int chunk) {
    const int kc = chunk * GKC;
    uint32_t sb = sbase + stg * QSTAGE_B;
    // A hi/lo: 128 rows x 4 vec16 = 512 per array -> 2 per thread
#pragma unroll
    for (int i = 0; i < 2; i++) {
      int v = tid + i * 256;
      int r = v >> 2;
      int c = (v & 3) * 8;
      size_t g = (size_t)(m0 + r) * D + kc + c;
      uint32_t so = (uint32_t)(r * RS + c) * 2;
      cp_async16(sb + Q_ST_AH + so, Ahi + g);
      cp_async16(sb + Q_ST_AL + so, Alo + g);
    }
    // B hi/lo: 192 rows x 4 vec16 = 768 per array -> 3 per thread
#pragma unroll
    for (int i = 0; i < 3; i++) {
      int v = tid + i * 256;
      int r = v >> 2;
      int c = (v & 3) * 8;
      size_t g = (size_t)(n0 + r) * D + kc + c;
      uint32_t so = (uint32_t)(r * RS + c) * 2;
      cp_async16(sb + Q_ST_BH + so, Bhi + g);
      cp_async16(sb + Q_ST_BL + so, Blo + g);
    }
    CP_COMMIT();
  };

  float acc[2][12][4];
#pragma unroll
  for (int f = 0; f < 2; f++)
#pragma unroll
    for (int g = 0; g < 12; g++)
#pragma unroll
      for (int x = 0; x < 4; x++) acc[f][g][x] = 0.0f;

  load_stage(0, 0);
  load_stage(1, 1);

  for (int c = 0; c < NC; c++) {
    CP_WAIT1();
    __syncthreads();
    if (c + 2 < NC) load_stage((c + 2) % 3, c + 2);

    uint32_t sb = sbase + (c % 3) * QSTAGE_B;
#pragma unroll
    for (int kk = 0; kk < 2; kk++) {
      const int k0 = kk * 16;
      uint32_t ah[2][4], al[2][4];
#pragma unroll
      for (int f = 0; f < 2; f++) {
        uint32_t ar = (uint32_t)((wm + f * 16 + a_r) * RS + k0 + a_c) * 2;
        ldsm_x4(ah[f], sb + Q_ST_AH + ar);
        ldsm_x4(al[f], sb + Q_ST_AL + ar);
      }
#pragma unroll
      for (int g2 = 0; g2 < 6; g2++) {
        uint32_t br = (uint32_t)((wn + g2 * 16 + b_r) * RS + k0 + b_c) * 2;
        uint32_t rh[4], rl[4];
        ldsm_x4(rh, sb + Q_ST_BH + br);
        ldsm_x4(rl, sb + Q_ST_BL + br);
#pragma unroll
        for (int sub = 0; sub < 2; sub++) {
          int g = g2 * 2 + sub;
#pragma unroll
          for (int f = 0; f < 2; f++) {
            mma16816(acc[f][g], ah[f], rh + 2 * sub);
            mma16816(acc[f][g], ah[f], rl + 2 * sub);
            mma16816(acc[f][g], al[f], rh + 2 * sub);
          }
        }
      }
    }
    __syncthreads();
  }

  // ---- fused RoPE + split epilogue ----
  const int gid = lane >> 2, tig = lane & 3;
#pragma unroll
  for (int f = 0; f < 2; f++) {
    int rowA = m0 + wm + f * 16 + gid;
#pragma unroll
    for (int g = 0; g < 12; g++) {
      int C = n0 + wn + g * 8 + tig * 2;  // even
#pragma unroll
      for (int half = 0; half < 2; half++) {
        int s = rowA + half * 8;
        float x = acc[f][g][half * 2 + 0];
        float y = acc[f][g][half * 2 + 1];
        uint32_t hreg, lreg;
        if (C < KCOL) {  // Q: rope
          int i = (C & 63) >> 1;
          float cs = g_cos[s * 32 + i], sn = g_sin[s * 32 + i];
          float xr = x * cs - y * sn;
          float xi = x * sn + y * cs;
          split_pack2(xr, xi, hreg, lreg);
          size_t o = (size_t)s * (H * HD) + C;
          *(uint32_t*)(g_Qhi + o) = hreg;
          *(uint32_t*)(g_Qlo + o) = lreg;
        } else if (C < VCOL) {  // K: rope
          int off = C - KCOL;
          int i = (off & 63) >> 1;
          float cs = g_cos[s * 32 + i], sn = g_sin[s * 32 + i];
          float xr = x * cs - y * sn;
          float xi = x * sn + y * cs;
          split_pack2(xr, xi, hreg, lreg);
          size_t o = (size_t)s * (KVH * HD) + off;
          *(uint32_t*)(g_Khi + o) = hreg;
          *(uint32_t*)(g_Klo + o) = lreg;
        } else {  // V: split only
          int off = C - VCOL;
          split_pack2(x, y, hreg, lreg);
          size_t o = (size_t)s * (KVH * HD) + off;
          *(uint32_t*)(g_Vhi + o) = hreg;
          *(uint32_t*)(g_Vlo + o) = lreg;
        }
      }
    }
  }
}

// ---------------------------------------------------------------------------
// fp16 single-product GEMM (Wo). 128x128x32, 2-stage, 2 CTAs/SM,
// B-fragments streamed to fit the 128-register cap.
// ---------------------------------------------------------------------------
#define FBM 128
#define FBN 128
#define FTILE_B (128 * RS * 2)
#define FSTAGE_B (2 * FTILE_B)
#define GEMM16_SMEM (2 * FSTAGE_B)

__global__ __launch_bounds__(256, 2) void gemm_fp16_kernel(
    const __half* __restrict__ A, const __half* __restrict__ B,
    float* __restrict__ C, int M, int N, int K) {
  extern __shared__ char smem[];
  const uint32_t sbase = smem_u32(smem);
  const int tid = threadIdx.x;
  const int wid = tid >> 5;
  const int lane = tid & 31;
  const int m0 = blockIdx.y * FBM;
  const int n0 = blockIdx.x * FBN;
  const int NC = K / GKC;

  const int wm = (wid & 3) * 32;
  const int wn = (wid >> 2) * 64;
  const int lrow = lane & 7;
  const int ltile = lane >> 3;
  const int a_r = (ltile & 1) * 8 + lrow;
  const int a_c = (ltile >> 1) * 8;
  const int b_r = (ltile >> 1) * 8 + lrow;
  const int b_c = (ltile & 1) * 8;

  const __half* gA = A + (size_t)m0 * K;
  const __half* gB = B + (size_t)n0 * K;

  auto load_stage = [&](int stg, int chunk) {
    const int kc = chunk * GKC;
    uint32_t sb = sbase + stg * FSTAGE_B;
#pragma unroll
    for (int i = 0; i < 2; i++) {
      int v = tid + i * 256;
      int r = v >> 2;
      int c = (v & 3) * 8;
      cp_async16(sb + (uint32_t)(r * RS + c) * 2, gA + (size_t)r * K + kc + c);
      cp_async16(sb + FTILE_B + (uint32_t)(r * RS + c) * 2,
                 gB + (size_t)r * K + kc + c);
    }
    CP_COMMIT();
  };

  float acc[2][8][4];
#pragma unroll
  for (int f = 0; f < 2; f++)
#pragma unroll
    for (int g = 0; g < 8; g++)
#pragma unroll
      for (int x = 0; x < 4; x++) acc[f][g][x] = 0.0f;

  load_stage(0, 0);

  for (int c = 0; c < NC; c++) {
    CP_WAIT0();
    __syncthreads();
    if (c + 1 < NC) load_stage((c + 1) & 1, c + 1);

    uint32_t sb = sbase + (c & 1) * FSTAGE_B;
#pragma unroll
    for (int kk = 0; kk < 2; kk++) {
      const int k0 = kk * 16;
      uint32_t af[2][4];
#pragma unroll
      for (int f = 0; f < 2; f++) {
        uint32_t ar = (uint32_t)((wm + f * 16 + a_r) * RS + k0 + a_c) * 2;
        ldsm_x4(af[f], sb + ar);
      }
#pragma unroll
      for (int g2 = 0; g2 < 4; g2++) {
        uint32_t br = (uint32_t)((wn + g2 * 16 + b_r) * RS + k0 + b_c) * 2;
        uint32_t r4[4];
        ldsm_x4(r4, sb + FTILE_B + br);
#pragma unroll
        for (int f = 0; f < 2; f++) {
          mma16816h(acc[f][g2 * 2], af[f], r4);
          mma16816h(acc[f][g2 * 2 + 1], af[f], r4 + 2);
        }
      }
    }
    __syncthreads();
  }

  const int gid = lane >> 2, tig = lane & 3;
#pragma unroll
  for (int f = 0; f < 2; f++) {
#pragma unroll
    for (int g = 0; g < 8; g++) {
      int row = m0 + wm + f * 16 + gid;
      int col = n0 + wn + g * 8 + tig * 2;
      *(float2*)(C + (size_t)row * N + col) = make_float2(acc[f][g][0], acc[f][g][1]);
      *(float2*)(C + (size_t)(row + 8) * N + col) = make_float2(acc[f][g][2], acc[f][g][3]);
    }
  }
}

// ---------------------------------------------------------------------------
// Tensor-core flash attention (unchanged from R5; writes fp16 O)
// ---------------------------------------------------------------------------
#define ABQ 128
#define ABKV 64
#define ARS 72
#define Q_ELEMS (ABQ * ARS)
#define KV_TILE (ABKV * ARS)
#define KV_STAGE (4 * KV_TILE)
#define ATT_SMEM ((2 * Q_ELEMS + 2 * KV_STAGE) * 2)

__global__ __launch_bounds__(256) void attn_mma_kernel(
    const __nv_bfloat16* __restrict__ Qhi, const __nv_bfloat16* __restrict__ Qlo,
    const __nv_bfloat16* __restrict__ Khi, const __nv_bfloat16* __restrict__ Klo,
    const __nv_bfloat16* __restrict__ Vhi, const __nv_bfloat16* __restrict__ Vlo,
    __half* __restrict__ O16) {
  extern __shared__ char sbuf[];
  const uint32_t sbase = smem_u32(sbuf);
  const int tid = threadIdx.x;
  const int wid = tid >> 5;
  const int lane = tid & 31;
  const int h = blockIdx.x;
  const int kvh = h / NREP;
  const int q0 = ((int)gridDim.y - 1 - (int)blockIdx.y) * ABQ;
  const int wm = wid * 16;

  const int lrow = lane & 7;
  const int ltile = lane >> 3;
  const int a_r = (ltile & 1) * 8 + lrow;
  const int a_c = (ltile >> 1) * 8;
  const int b_r = (ltile >> 1) * 8 + lrow;
  const int b_c = (ltile & 1) * 8;
  const int gid = lane >> 2, tig = lane & 3;

  const uint32_t qhi_s = sbase;
  const uint32_t qlo_s = sbase + Q_ELEMS * 2;

#pragma unroll
  for (int i = 0; i < 4; i++) {
    int v = tid + i * 256;
    int r = v >> 3, c = v & 7;
    size_t g = (size_t)(q0 + r) * (H * HD) + h * HD + c * 8;
    uint32_t so = (uint32_t)(r * ARS + c * 8) * 2;
    cp_async16(qhi_s + so, Qhi + g);
    cp_async16(qlo_s + so, Qlo + g);
  }

  auto load_kv = [&](int stg, int kv0) {
    uint32_t base = sbase + (2 * Q_ELEMS + stg * KV_STAGE) * 2;
#pragma unroll
    for (int i = 0; i < 2; i++) {
      int v = tid + i * 256;
      int r = v >> 3, c = v & 7;
      size_t g = (size_t)(kv0 + r) * (KVH * HD) + kvh * HD + c * 8;
      uint32_t so = (uint32_t)(r * ARS + c * 8) * 2;
      cp_async16(base + 0 * KV_TILE * 2 + so, Khi + g);
      cp_async16(base + 1 * KV_TILE * 2 + so, Klo + g);
      cp_async16(base + 2 * KV_TILE * 2 + so, Vhi + g);
      cp_async16(base + 3 * KV_TILE * 2 + so, Vlo + g);
    }
    CP_COMMIT();
  };

  load_kv(0, 0);

  const int ntiles = (q0 + ABQ) / ABKV;
  float m_[2] = {-1e30f, -1e30f};
  float l_[2] = {0.0f, 0.0f};
  float o[8][4];
#pragma unroll
  for (int nf = 0; nf < 8; nf++)
#pragma unroll
    for (int j = 0; j < 4; j++) o[nf][j] = 0.0f;

  const float SCL = 0.18033688011112042f;
  const int row0 = q0 + wm + gid;

  for (int t = 0; t < ntiles; t++) {
    const int kv0 = t * ABKV;
    CP_WAIT0();
    __syncthreads();
    if (t + 1 < ntiles) load_kv((t + 1) & 1, kv0 + ABKV);

    const uint32_t kvb = sbase + (2 * Q_ELEMS + (t & 1) * KV_STAGE) * 2;

    float sc[8][4];
#pragma unroll
    for (int nf = 0; nf < 8; nf++)
#pragma unroll
      for (int j = 0; j < 4; j++) sc[nf][j] = 0.0f;

#pragma unroll
    for (int ks = 0; ks < 4; ks++) {
      const int k0 = ks * 16;
      uint32_t ah[4], al[4];
      uint32_t ar = (uint32_t)((wm + a_r) * ARS + k0 + a_c) * 2;
      ldsm_x4(ah, qhi_s + ar);
      ldsm_x4(al, qlo_s + ar);
#pragma unroll
      for (int ng = 0; ng < 4; ng++) {
        uint32_t br = kvb + (uint32_t)((ng * 16 + b_r) * ARS + k0 + b_c) * 2;
        uint32_t rh[4], rl[4];
        ldsm_x4(rh, br);
        ldsm_x4(rl, br + KV_TILE * 2);
        mma16816(sc[ng * 2], ah, rh);
        mma16816(sc[ng * 2], ah, rl);
        mma16816(sc[ng * 2], al, rh);
        mma16816(sc[ng * 2 + 1], ah, rh + 2);
        mma16816(sc[ng * 2 + 1], ah, rl + 2);
        mma16816(sc[ng * 2 + 1], al, rh + 2);
      }
    }

    const bool nomask = (kv0 + ABKV - 1 <= q0 + wm);
    if (nomask) {
#pragma unroll
      for (int nf = 0; nf < 8; nf++)
#pragma unroll
        for (int j = 0; j < 4; j++) sc[nf][j] *= SCL;
    } else {
#pragma unroll
      for (int nf = 0; nf < 8; nf++) {
        int col = kv0 + nf * 8 + tig * 2;
#pragma unroll
        for (int j = 0; j < 4; j++) {
          int cc = col + (j & 1);
          int rr = row0 + ((j >> 1) << 3);
          sc[nf][j] = (cc <= rr) ? sc[nf][j] * SCL : -1e30f;
        }
      }
    }

    float mx0 = -1e30f, mx1 = -1e30f;
#pragma unroll
    for (int nf = 0; nf < 8; nf++) {
      mx0 = fmaxf(mx0, fmaxf(sc[nf][0], sc[nf][1]));
      mx1 = fmaxf(mx1, fmaxf(sc[nf][2], sc[nf][3]));
    }
    mx0 = fmaxf(mx0, __shfl_xor_sync(0xffffffffu, mx0, 1));
    mx0 = fmaxf(mx0, __shfl_xor_sync(0xffffffffu, mx0, 2));
    mx1 = fmaxf(mx1, __shfl_xor_sync(0xffffffffu, mx1, 1));
    mx1 = fmaxf(mx1, __shfl_xor_sync(0xffffffffu, mx1, 2));
    float mn0 = fmaxf(m_[0], mx0);
    float mn1 = fmaxf(m_[1], mx1);
    float c0 = exp2_poly(m_[0] - mn0);
    float c1 = exp2_poly(m_[1] - mn1);
    m_[0] = mn0;
    m_[1] = mn1;

    float s0 = 0.0f, s1 = 0.0f;
#pragma unroll
    for (int nf = 0; nf < 8; nf++) {
      float p0 = exp2_poly(sc[nf][0] - mn0);
      float p1 = exp2_poly(sc[nf][1] - mn0);
      float p2 = exp2_poly(sc[nf][2] - mn1);
      float p3 = exp2_poly(sc[nf][3] - mn1);
      sc[nf][0] = p0; sc[nf][1] = p1; sc[nf][2] = p2; sc[nf][3] = p3;
      s0 += p0 + p1;
      s1 += p2 + p3;
    }
    l_[0] = l_[0] * c0 + s0;
    l_[1] = l_[1] * c1 + s1;
#pragma unroll
    for (int nf = 0; nf < 8; nf++) {
      o[nf][0] *= c0; o[nf][1] *= c0;
      o[nf][2] *= c1; o[nf][3] *= c1;
    }

    const uint32_t vhb = kvb + 2 * KV_TILE * 2;
#pragma unroll
    for (int ks = 0; ks < 4; ks++) {
      uint32_t phi[4], plo[4];
      split_pack2(sc[2 * ks][0], sc[2 * ks][1], phi[0], plo[0]);
      split_pack2(sc[2 * ks][2], sc[2 * ks][3], phi[1], plo[1]);
      split_pack2(sc[2 * ks + 1][0], sc[2 * ks + 1][1], phi[2], plo[2]);
      split_pack2(sc[2 * ks + 1][2], sc[2 * ks + 1][3], phi[3], plo[3]);
#pragma unroll
      for (int dg = 0; dg < 4; dg++) {
        uint32_t va = vhb + (uint32_t)((ks * 16 + a_r) * ARS + dg * 16 + a_c) * 2;
        uint32_t vh[4], vl[4];
        ldsm_x4_trans(vh, va);
        ldsm_x4_trans(vl, va + KV_TILE * 2);
        mma16816(o[dg * 2], phi, vh);
        mma16816(o[dg * 2], phi, vl);
        mma16816(o[dg * 2], plo, vh);
        mma16816(o[dg * 2 + 1], phi, vh + 2);
        mma16816(o[dg * 2 + 1], phi, vl + 2);
        mma16816(o[dg * 2 + 1], plo, vh + 2);
      }
    }
  }

  l_[0] += __shfl_xor_sync(0xffffffffu, l_[0], 1);
  l_[0] += __shfl_xor_sync(0xffffffffu, l_[0], 2);
  l_[1] += __shfl_xor_sync(0xffffffffu, l_[1], 1);
  l_[1] += __shfl_xor_sync(0xffffffffu, l_[1], 2);
  float inv0 = 1.0f / l_[0];
  float inv1 = 1.0f / l_[1];

#pragma unroll
  for (int nf = 0; nf < 8; nf++) {
    int col = h * HD + nf * 8 + tig * 2;
    *(__half2*)(O16 + (size_t)row0 * (H * HD) + col) =
        __floats2half2_rn(o[nf][0] * inv0, o[nf][1] * inv0);
    *(__half2*)(O16 + (size_t)(row0 + 8) * (H * HD) + col) =
        __floats2half2_rn(o[nf][2] * inv1, o[nf][3] * inv1);
  }
}

// ---------------------------------------------------------------------------
// Launch
// ---------------------------------------------------------------------------
extern "C" void kernel_launch(void* const* d_in, const int* in_sizes, int n_in,
                              void* d_out, int out_size) {
  const float* hs = (const float*)d_in[0];
  const float* Wq = (const float*)d_in[1];
  const float* Wk = (const float*)d_in[2];
  const float* Wv = (const float*)d_in[3];
  const float* Wo = (const float*)d_in[4];
  float* out = (float*)d_out;

  __nv_bfloat16 *Xhi, *Xlo, *WqkvThi, *WqkvTlo;
  __nv_bfloat16 *Qhi, *Qlo, *Khi, *Klo, *Vhi, *Vlo;
  __half *O16, *WoT16;
  cudaGetSymbolAddress((void**)&Xhi, g_Xhi);
  cudaGetSymbolAddress((void**)&Xlo, g_Xlo);
  cudaGetSymbolAddress((void**)&WqkvThi, g_WqkvThi);
  cudaGetSymbolAddress((void**)&WqkvTlo, g_WqkvTlo);
  cudaGetSymbolAddress((void**)&Qhi, g_Qhi);
  cudaGetSymbolAddress((void**)&Qlo, g_Qlo);
  cudaGetSymbolAddress((void**)&Khi, g_Khi);
  cudaGetSymbolAddress((void**)&Klo, g_Klo);
  cudaGetSymbolAddress((void**)&Vhi, g_Vhi);
  cudaGetSymbolAddress((void**)&Vlo, g_Vlo);
  cudaGetSymbolAddress((void**)&O16, g_O16);
  cudaGetSymbolAddress((void**)&WoT16, g_WoT16);

  // 1. split activations + rope table
  {
    int n4 = S * D / 4;
    split_kernel<<<(n4 + 255) / 256, 256>>>(hs, Xhi, Xlo, n4);
    rope_table_kernel<<<(S * 32 + 255) / 256, 256>>>();
  }

  // 2. transpose weights
  {
    dim3 blk(32, 8);
    transpose_split_kernel<<<dim3(D / 32, D / 32), blk>>>(Wq, WqkvThi, WqkvTlo, D, D);
    transpose_split_kernel<<<dim3(512 / 32, D / 32), blk>>>(
        Wk, WqkvThi + (size_t)KCOL * D, WqkvTlo + (size_t)KCOL * D, 512, D);
    transpose_split_kernel<<<dim3(512 / 32, D / 32), blk>>>(
        Wv, WqkvThi + (size_t)VCOL * D, WqkvTlo + (size_t)VCOL * D, 512, D);
    transpose_half_kernel<<<dim3(D / 32, D / 32), blk>>>(Wo, WoT16, D, D);
  }

  cudaFuncSetAttribute(gemm_qkv_rope_kernel,
                       cudaFuncAttributeMaxDynamicSharedMemorySize, QKV_SMEM);
  cudaFuncSetAttribute(gemm_fp16_kernel,
                       cudaFuncAttributeMaxDynamicSharedMemorySize, GEMM16_SMEM);

  // 3. QKV projection + fused RoPE/split (writes Q/K/V hi/lo directly)
  {
    dim3 grid(QKV_N / GBN, S / GBM);  // 16 x 16 = 256 CTAs
    gemm_qkv_rope_kernel<<<grid, 256, QKV_SMEM>>>(Xhi, Xlo, WqkvThi, WqkvTlo);
  }

  // 4. tensor-core flash attention -> fp16 O
  {
    cudaFuncSetAttribute(attn_mma_kernel,
                         cudaFuncAttributeMaxDynamicSharedMemorySize, ATT_SMEM);
    dim3 grid(H, S / ABQ);
    attn_mma_kernel<<<grid, 256, ATT_SMEM>>>(Qhi, Qlo, Khi, Klo, Vhi, Vlo, O16);
  }

  // 5. output projection (fp16)
  {
    dim3 grid(D / FBN, S / FBM);  // 16 x 16 = 256 CTAs
    gemm_fp16_kernel<<<grid, 256, GEMM16_SMEM>>>(O16, WoT16, out, S, D, D);
  }
}

// round 7
// speedup vs baseline: 1.0627x; 1.0627x over previous
#include <cuda_runtime.h>
#include <cuda_bf16.h>
#include <cuda_fp16.h>
#include <cstdint>
#include <math.h>

#define S 2048
#define D 2048
#define H 32
#define KVH 8
#define HD 64
#define NREP (H / KVH)
#define QKV_N 3072
#define KCOL 2048
#define VCOL 2560

// ---------------------------------------------------------------------------
// Device-global scratch
// ---------------------------------------------------------------------------
__device__ __nv_bfloat16 g_Xhi[S * D], g_Xlo[S * D];
__device__ __nv_bfloat16 g_WqkvThi[QKV_N * D], g_WqkvTlo[QKV_N * D];
__device__ __nv_bfloat16 g_Qhi[S * H * HD], g_Qlo[S * H * HD];
__device__ __nv_bfloat16 g_Khi[S * KVH * HD], g_Klo[S * KVH * HD];
__device__ __nv_bfloat16 g_Vhi[S * KVH * HD], g_Vlo[S * KVH * HD];
__device__ __half g_O16[S * D];
__device__ __half g_WoT16[D * D];
__device__ float g_cos[S * 32], g_sin[S * 32];

// ---------------------------------------------------------------------------
// Helpers
// ---------------------------------------------------------------------------
__device__ __forceinline__ uint32_t smem_u32(const void* p) {
  uint32_t a;
  asm("{ .reg .u64 t; cvta.to.shared.u64 t, %1; cvt.u32.u64 %0, t; }"
      : "=r"(a) : "l"(p));
  return a;
}

__device__ __forceinline__ void ldsm_x4(uint32_t* r, uint32_t addr) {
  asm volatile(
      "ldmatrix.sync.aligned.m8n8.x4.shared.b16 {%0,%1,%2,%3}, [%4];"
      : "=r"(r[0]), "=r"(r[1]), "=r"(r[2]), "=r"(r[3]) : "r"(addr));
}

__device__ __forceinline__ void ldsm_x4_trans(uint32_t* r, uint32_t addr) {
  asm volatile(
      "ldmatrix.sync.aligned.m8n8.x4.trans.shared.b16 {%0,%1,%2,%3}, [%4];"
      : "=r"(r[0]), "=r"(r[1]), "=r"(r[2]), "=r"(r[3]) : "r"(addr));
}

__device__ __forceinline__ void mma16816(float* d, const uint32_t* a,
                                         const uint32_t* b) {
  asm volatile(
      "mma.sync.aligned.m16n8k16.row.col.f32.bf16.bf16.f32 "
      "{%0,%1,%2,%3}, {%4,%5,%6,%7}, {%8,%9}, {%0,%1,%2,%3};"
      : "+f"(d[0]), "+f"(d[1]), "+f"(d[2]), "+f"(d[3])
      : "r"(a[0]), "r"(a[1]), "r"(a[2]), "r"(a[3]), "r"(b[0]), "r"(b[1]));
}

__device__ __forceinline__ void mma16816h(float* d, const uint32_t* a,
                                          const uint32_t* b) {
  asm volatile(
      "mma.sync.aligned.m16n8k16.row.col.f32.f16.f16.f32 "
      "{%0,%1,%2,%3}, {%4,%5,%6,%7}, {%8,%9}, {%0,%1,%2,%3};"
      : "+f"(d[0]), "+f"(d[1]), "+f"(d[2]), "+f"(d[3])
      : "r"(a[0]), "r"(a[1]), "r"(a[2]), "r"(a[3]), "r"(b[0]), "r"(b[1]));
}

__device__ __forceinline__ void cp_async16(uint32_t saddr, const void* gptr) {
  asm volatile("cp.async.cg.shared.global [%0], [%1], 16;" ::
                   "r"(saddr), "l"(__cvta_generic_to_global(gptr)));
}
#define CP_COMMIT() asm volatile("cp.async.commit_group;" ::: "memory")
#define CP_WAIT0() asm volatile("cp.async.wait_group 0;" ::: "memory")

__device__ __forceinline__ float exp2_poly(float x) {
  x = fmaxf(x, -126.0f);
  float fl = floorf(x);
  float f = x - fl;
  float p = 1.5403530393e-4f;
  p = fmaf(p, f, 1.3333558146e-3f);
  p = fmaf(p, f, 9.6181291076e-3f);
  p = fmaf(p, f, 5.5504108665e-2f);
  p = fmaf(p, f, 2.4022650696e-1f);
  p = fmaf(p, f, 6.9314718056e-1f);
  p = fmaf(p, f, 1.0f);
  return p * __int_as_float(((int)fl + 127) << 23);
}

__device__ __forceinline__ void split2(float x, __nv_bfloat16& h, __nv_bfloat16& l) {
  h = __float2bfloat16(x);
  l = __float2bfloat16(x - __bfloat162float(h));
}

__device__ __forceinline__ void split_pack2(float x, float y, uint32_t& h,
                                            uint32_t& l) {
  __nv_bfloat162 hb = __floats2bfloat162_rn(x, y);
  float xr = x - __bfloat162float(hb.x);
  float yr = y - __bfloat162float(hb.y);
  __nv_bfloat162 lb = __floats2bfloat162_rn(xr, yr);
  h = *reinterpret_cast<uint32_t*>(&hb);
  l = *reinterpret_cast<uint32_t*>(&lb);
}

// ---------------------------------------------------------------------------
// Preprocessing
// ---------------------------------------------------------------------------
__global__ void split_kernel(const float* __restrict__ in,
                             __nv_bfloat16* __restrict__ hi,
                             __nv_bfloat16* __restrict__ lo, int n4) {
  int i = blockIdx.x * blockDim.x + threadIdx.x;
  if (i >= n4) return;
  float4 v = ((const float4*)in)[i];
  __nv_bfloat16 h0, l0, h1, l1, h2, l2, h3, l3;
  split2(v.x, h0, l0); split2(v.y, h1, l1);
  split2(v.z, h2, l2); split2(v.w, h3, l3);
  __nv_bfloat162* hp = (__nv_bfloat162*)hi;
  __nv_bfloat162* lp = (__nv_bfloat162*)lo;
  hp[i * 2 + 0] = __halves2bfloat162(h0, h1);
  hp[i * 2 + 1] = __halves2bfloat162(h2, h3);
  lp[i * 2 + 0] = __halves2bfloat162(l0, l1);
  lp[i * 2 + 1] = __halves2bfloat162(l2, l3);
}

__global__ void transpose_split_kernel(const float* __restrict__ W,
                                       __nv_bfloat16* __restrict__ Thi,
                                       __nv_bfloat16* __restrict__ Tlo,
                                       int N, int K) {
  __shared__ float t[32][33];
  int n0 = blockIdx.x * 32, k0 = blockIdx.y * 32;
  int tx = threadIdx.x, ty = threadIdx.y;
#pragma unroll
  for (int i = 0; i < 4; i++)
    t[ty + i * 8][tx] = W[(size_t)(k0 + ty + i * 8) * N + n0 + tx];
  __syncthreads();
#pragma unroll
  for (int i = 0; i < 4; i++) {
    int n = ty + i * 8;
    float x = t[tx][n];
    __nv_bfloat16 h, l;
    split2(x, h, l);
    size_t o = (size_t)(n0 + n) * K + k0 + tx;
    Thi[o] = h;
    Tlo[o] = l;
  }
}

__global__ void transpose_half_kernel(const float* __restrict__ W,
                                      __half* __restrict__ T, int N, int K) {
  __shared__ float t[32][33];
  int n0 = blockIdx.x * 32, k0 = blockIdx.y * 32;
  int tx = threadIdx.x, ty = threadIdx.y;
#pragma unroll
  for (int i = 0; i < 4; i++)
    t[ty + i * 8][tx] = W[(size_t)(k0 + ty + i * 8) * N + n0 + tx];
  __syncthreads();
#pragma unroll
  for (int i = 0; i < 4; i++) {
    int n = ty + i * 8;
    T[(size_t)(n0 + n) * K + k0 + tx] = __float2half(t[tx][n]);
  }
}

__global__ void rope_table_kernel() {
  int idx = blockIdx.x * blockDim.x + threadIdx.x;
  if (idx >= S * 32) return;
  int s = idx >> 5, i = idx & 31;
  float inv = 1.0f / powf(10000.0f, (2.0f * i) / (float)HD);
  float ang = (float)s * inv;
  g_cos[idx] = cosf(ang);
  g_sin[idx] = sinf(ang);
}

// ---------------------------------------------------------------------------
// QKV GEMM (bf16x3, R5 config: 128x128x32, 2-stage, 2 CTA/SM) with
// fused RoPE + hi/lo split epilogue. Column regions align to 128-col tiles,
// so the Q/K/V branch is uniform per CTA.
// ---------------------------------------------------------------------------
#define GBM 128
#define GBN 128
#define GKC 32
#define RS 40
#define TILE_B (128 * RS * 2)
#define STAGE_B (4 * TILE_B)
#define GEMM_SMEM (2 * STAGE_B)

__global__ __launch_bounds__(256, 2) void gemm_qkv_rope_kernel(
    const __nv_bfloat16* __restrict__ Ahi, const __nv_bfloat16* __restrict__ Alo,
    const __nv_bfloat16* __restrict__ Bhi, const __nv_bfloat16* __restrict__ Blo) {
  extern __shared__ char smem[];
  const uint32_t sbase = smem_u32(smem);
  const int tid = threadIdx.x;
  const int wid = tid >> 5;
  const int lane = tid & 31;
  const int m0 = blockIdx.y * GBM;
  const int n0 = blockIdx.x * GBN;
  const int NC = D / GKC;

  const int wm = (wid & 3) * 32;
  const int wn = (wid >> 2) * 64;
  const int lrow = lane & 7;
  const int ltile = lane >> 3;
  const int a_r = (ltile & 1) * 8 + lrow;
  const int a_c = (ltile >> 1) * 8;
  const int b_r = (ltile >> 1) * 8 + lrow;
  const int b_c = (ltile & 1) * 8;

  const __nv_bfloat16* gA[2] = {Ahi + (size_t)m0 * D, Alo + (size_t)m0 * D};
  const __nv_bfloat16* gB[2] = {Bhi + (size_t)n0 * D, Blo + (size_t)n0 * D};

  auto load_stage = [&](int stg, int chunk) {
    const int kc = chunk * GKC;
    uint32_t sb = sbase + stg * STAGE_B;
#pragma unroll
    for (int t = 0; t < 4; t++) {
      const __nv_bfloat16* gp = (t < 2) ? gA[t] : gB[t - 2];
#pragma unroll
      for (int i = 0; i < 2; i++) {
        int v = tid + i * 256;
        int r = v >> 2;
        int c = (v & 3) * 8;
        cp_async16(sb + t * TILE_B + (uint32_t)(r * RS + c) * 2,
                   gp + (size_t)r * D + kc + c);
      }
    }
    CP_COMMIT();
  };

  float acc[2][8][4];
#pragma unroll
  for (int f = 0; f < 2; f++)
#pragma unroll
    for (int g = 0; g < 8; g++)
#pragma unroll
      for (int x = 0; x < 4; x++) acc[f][g][x] = 0.0f;

  load_stage(0, 0);

  for (int c = 0; c < NC; c++) {
    CP_WAIT0();
    __syncthreads();
    if (c + 1 < NC) load_stage((c + 1) & 1, c + 1);

    uint32_t sb = sbase + (c & 1) * STAGE_B;
#pragma unroll
    for (int kk = 0; kk < 2; kk++) {
      const int k0 = kk * 16;
      uint32_t ah[2][4], al[2][4];
#pragma unroll
      for (int f = 0; f < 2; f++) {
        uint32_t ar = (uint32_t)((wm + f * 16 + a_r) * RS + k0 + a_c) * 2;
        ldsm_x4(ah[f], sb + 0 * TILE_B + ar);
        ldsm_x4(al[f], sb + 1 * TILE_B + ar);
      }
#pragma unroll
      for (int g2 = 0; g2 < 4; g2++) {
        uint32_t br = (uint32_t)((wn + g2 * 16 + b_r) * RS + k0 + b_c) * 2;
        uint32_t rh[4], rl[4];
        ldsm_x4(rh, sb + 2 * TILE_B + br);
        ldsm_x4(rl, sb + 3 * TILE_B + br);
#pragma unroll
        for (int sub = 0; sub < 2; sub++) {
          int g = g2 * 2 + sub;
#pragma unroll
          for (int f = 0; f < 2; f++) {
            mma16816(acc[f][g], ah[f], rh + 2 * sub);
            mma16816(acc[f][g], ah[f], rl + 2 * sub);
            mma16816(acc[f][g], al[f], rh + 2 * sub);
          }
        }
      }
    }
    __syncthreads();
  }

  // ---- fused RoPE + hi/lo split epilogue (uniform region per CTA) ----
  const int gid = lane >> 2, tig = lane & 3;
  const int region = (n0 < KCOL) ? 0 : ((n0 < VCOL) ? 1 : 2);

#pragma unroll
  for (int f = 0; f < 2; f++) {
    int rowA = m0 + wm + f * 16 + gid;
#pragma unroll
    for (int g = 0; g < 8; g++) {
      int C = n0 + wn + g * 8 + tig * 2;  // even column
#pragma unroll
      for (int half = 0; half < 2; half++) {
        int s = rowA + half * 8;
        float x = acc[f][g][half * 2 + 0];
        float y = acc[f][g][half * 2 + 1];
        uint32_t hreg, lreg;
        if (region == 0) {  // Q: rope
          int i = (C & 63) >> 1;
          float cs = g_cos[s * 32 + i], sn = g_sin[s * 32 + i];
          float xr = x * cs - y * sn;
          float xi = x * sn + y * cs;
          split_pack2(xr, xi, hreg, lreg);
          size_t o = (size_t)s * (H * HD) + C;
          *(uint32_t*)(g_Qhi + o) = hreg;
          *(uint32_t*)(g_Qlo + o) = lreg;
        } else if (region == 1) {  // K: rope
          int off = C - KCOL;
          int i = (off & 63) >> 1;
          float cs = g_cos[s * 32 + i], sn = g_sin[s * 32 + i];
          float xr = x * cs - y * sn;
          float xi = x * sn + y * cs;
          split_pack2(xr, xi, hreg, lreg);
          size_t o = (size_t)s * (KVH * HD) + off;
          *(uint32_t*)(g_Khi + o) = hreg;
          *(uint32_t*)(g_Klo + o) = lreg;
        } else {  // V: split only
          int off = C - VCOL;
          split_pack2(x, y, hreg, lreg);
          size_t o = (size_t)s * (KVH * HD) + off;
          *(uint32_t*)(g_Vhi + o) = hreg;
          *(uint32_t*)(g_Vlo + o) = lreg;
        }
      }
    }
  }
}

// ---------------------------------------------------------------------------
// fp16 single-product GEMM (Wo). Streamed B fragments (low reg pressure).
// ---------------------------------------------------------------------------
#define FBM 128
#define FBN 128
#define FTILE_B (128 * RS * 2)
#define FSTAGE_B (2 * FTILE_B)
#define GEMM16_SMEM (2 * FSTAGE_B)

__global__ __launch_bounds__(256, 2) void gemm_fp16_kernel(
    const __half* __restrict__ A, const __half* __restrict__ B,
    float* __restrict__ C, int M, int N, int K) {
  extern __shared__ char smem[];
  const uint32_t sbase = smem_u32(smem);
  const int tid = threadIdx.x;
  const int wid = tid >> 5;
  const int lane = tid & 31;
  const int m0 = blockIdx.y * FBM;
  const int n0 = blockIdx.x * FBN;
  const int NC = K / GKC;

  const int wm = (wid & 3) * 32;
  const int wn = (wid >> 2) * 64;
  const int lrow = lane & 7;
  const int ltile = lane >> 3;
  const int a_r = (ltile & 1) * 8 + lrow;
  const int a_c = (ltile >> 1) * 8;
  const int b_r = (ltile >> 1) * 8 + lrow;
  const int b_c = (ltile & 1) * 8;

  const __half* gA = A + (size_t)m0 * K;
  const __half* gB = B + (size_t)n0 * K;

  auto load_stage = [&](int stg, int chunk) {
    const int kc = chunk * GKC;
    uint32_t sb = sbase + stg * FSTAGE_B;
#pragma unroll
    for (int i = 0; i < 2; i++) {
      int v = tid + i * 256;
      int r = v >> 2;
      int c = (v & 3) * 8;
      cp_async16(sb + (uint32_t)(r * RS + c) * 2, gA + (size_t)r * K + kc + c);
      cp_async16(sb + FTILE_B + (uint32_t)(r * RS + c) * 2,
                 gB + (size_t)r * K + kc + c);
    }
    CP_COMMIT();
  };

  float acc[2][8][4];
#pragma unroll
  for (int f = 0; f < 2; f++)
#pragma unroll
    for (int g = 0; g < 8; g++)
#pragma unroll
      for (int x = 0; x < 4; x++) acc[f][g][x] = 0.0f;

  load_stage(0, 0);

  for (int c = 0; c < NC; c++) {
    CP_WAIT0();
    __syncthreads();
    if (c + 1 < NC) load_stage((c + 1) & 1, c + 1);

    uint32_t sb = sbase + (c & 1) * FSTAGE_B;
#pragma unroll
    for (int kk = 0; kk < 2; kk++) {
      const int k0 = kk * 16;
      uint32_t af[2][4];
#pragma unroll
      for (int f = 0; f < 2; f++) {
        uint32_t ar = (uint32_t)((wm + f * 16 + a_r) * RS + k0 + a_c) * 2;
        ldsm_x4(af[f], sb + ar);
      }
#pragma unroll
      for (int g2 = 0; g2 < 4; g2++) {
        uint32_t br = (uint32_t)((wn + g2 * 16 + b_r) * RS + k0 + b_c) * 2;
        uint32_t r4[4];
        ldsm_x4(r4, sb + FTILE_B + br);
#pragma unroll
        for (int f = 0; f < 2; f++) {
          mma16816h(acc[f][g2 * 2], af[f], r4);
          mma16816h(acc[f][g2 * 2 + 1], af[f], r4 + 2);
        }
      }
    }
    __syncthreads();
  }

  const int gid = lane >> 2, tig = lane & 3;
#pragma unroll
  for (int f = 0; f < 2; f++) {
#pragma unroll
    for (int g = 0; g < 8; g++) {
      int row = m0 + wm + f * 16 + gid;
      int col = n0 + wn + g * 8 + tig * 2;
      *(float2*)(C + (size_t)row * N + col) = make_float2(acc[f][g][0], acc[f][g][1]);
      *(float2*)(C + (size_t)(row + 8) * N + col) = make_float2(acc[f][g][2], acc[f][g][3]);
    }
  }
}

// ---------------------------------------------------------------------------
// Tensor-core flash attention (unchanged; writes fp16 O)
// ---------------------------------------------------------------------------
#define ABQ 128
#define ABKV 64
#define ARS 72
#define Q_ELEMS (ABQ * ARS)
#define KV_TILE (ABKV * ARS)
#define KV_STAGE (4 * KV_TILE)
#define ATT_SMEM ((2 * Q_ELEMS + 2 * KV_STAGE) * 2)

__global__ __launch_bounds__(256) void attn_mma_kernel(
    const __nv_bfloat16* __restrict__ Qhi, const __nv_bfloat16* __restrict__ Qlo,
    const __nv_bfloat16* __restrict__ Khi, const __nv_bfloat16* __restrict__ Klo,
    const __nv_bfloat16* __restrict__ Vhi, const __nv_bfloat16* __restrict__ Vlo,
    __half* __restrict__ O16) {
  extern __shared__ char sbuf[];
  const uint32_t sbase = smem_u32(sbuf);
  const int tid = threadIdx.x;
  const int wid = tid >> 5;
  const int lane = tid & 31;
  const int h = blockIdx.x;
  const int kvh = h / NREP;
  const int q0 = ((int)gridDim.y - 1 - (int)blockIdx.y) * ABQ;
  const int wm = wid * 16;

  const int lrow = lane & 7;
  const int ltile = lane >> 3;
  const int a_r = (ltile & 1) * 8 + lrow;
  const int a_c = (ltile >> 1) * 8;
  const int b_r = (ltile >> 1) * 8 + lrow;
  const int b_c = (ltile & 1) * 8;
  const int gid = lane >> 2, tig = lane & 3;

  const uint32_t qhi_s = sbase;
  const uint32_t qlo_s = sbase + Q_ELEMS * 2;

#pragma unroll
  for (int i = 0; i < 4; i++) {
    int v = tid + i * 256;
    int r = v >> 3, c = v & 7;
    size_t g = (size_t)(q0 + r) * (H * HD) + h * HD + c * 8;
    uint32_t so = (uint32_t)(r * ARS + c * 8) * 2;
    cp_async16(qhi_s + so, Qhi + g);
    cp_async16(qlo_s + so, Qlo + g);
  }

  auto load_kv = [&](int stg, int kv0) {
    uint32_t base = sbase + (2 * Q_ELEMS + stg * KV_STAGE) * 2;
#pragma unroll
    for (int i = 0; i < 2; i++) {
      int v = tid + i * 256;
      int r = v >> 3, c = v & 7;
      size_t g = (size_t)(kv0 + r) * (KVH * HD) + kvh * HD + c * 8;
      uint32_t so = (uint32_t)(r * ARS + c * 8) * 2;
      cp_async16(base + 0 * KV_TILE * 2 + so, Khi + g);
      cp_async16(base + 1 * KV_TILE * 2 + so, Klo + g);
      cp_async16(base + 2 * KV_TILE * 2 + so, Vhi + g);
      cp_async16(base + 3 * KV_TILE * 2 + so, Vlo + g);
    }
    CP_COMMIT();
  };

  load_kv(0, 0);

  const int ntiles = (q0 + ABQ) / ABKV;
  float m_[2] = {-1e30f, -1e30f};
  float l_[2] = {0.0f, 0.0f};
  float o[8][4];
#pragma unroll
  for (int nf = 0; nf < 8; nf++)
#pragma unroll
    for (int j = 0; j < 4; j++) o[nf][j] = 0.0f;

  const float SCL = 0.18033688011112042f;
  const int row0 = q0 + wm + gid;

  for (int t = 0; t < ntiles; t++) {
    const int kv0 = t * ABKV;
    CP_WAIT0();
    __syncthreads();
    if (t + 1 < ntiles) load_kv((t + 1) & 1, kv0 + ABKV);

    const uint32_t kvb = sbase + (2 * Q_ELEMS + (t & 1) * KV_STAGE) * 2;

    float sc[8][4];
#pragma unroll
    for (int nf = 0; nf < 8; nf++)
#pragma unroll
      for (int j = 0; j < 4; j++) sc[nf][j] = 0.0f;

#pragma unroll
    for (int ks = 0; ks < 4; ks++) {
      const int k0 = ks * 16;
      uint32_t ah[4], al[4];
      uint32_t ar = (uint32_t)((wm + a_r) * ARS + k0 + a_c) * 2;
      ldsm_x4(ah, qhi_s + ar);
      ldsm_x4(al, qlo_s + ar);
#pragma unroll
      for (int ng = 0; ng < 4; ng++) {
        uint32_t br = kvb + (uint32_t)((ng * 16 + b_r) * ARS + k0 + b_c) * 2;
        uint32_t rh[4], rl[4];
        ldsm_x4(rh, br);
        ldsm_x4(rl, br + KV_TILE * 2);
        mma16816(sc[ng * 2], ah, rh);
        mma16816(sc[ng * 2], ah, rl);
        mma16816(sc[ng * 2], al, rh);
        mma16816(sc[ng * 2 + 1], ah, rh + 2);
        mma16816(sc[ng * 2 + 1], ah, rl + 2);
        mma16816(sc[ng * 2 + 1], al, rh + 2);
      }
    }

    const bool nomask = (kv0 + ABKV - 1 <= q0 + wm);
    if (nomask) {
#pragma unroll
      for (int nf = 0; nf < 8; nf++)
#pragma unroll
        for (int j = 0; j < 4; j++) sc[nf][j] *= SCL;
    } else {
#pragma unroll
      for (int nf = 0; nf < 8; nf++) {
        int col = kv0 + nf * 8 + tig * 2;
#pragma unroll
        for (int j = 0; j < 4; j++) {
          int cc = col + (j & 1);
          int rr = row0 + ((j >> 1) << 3);
          sc[nf][j] = (cc <= rr) ? sc[nf][j] * SCL : -1e30f;
        }
      }
    }

    float mx0 = -1e30f, mx1 = -1e30f;
#pragma unroll
    for (int nf = 0; nf < 8; nf++) {
      mx0 = fmaxf(mx0, fmaxf(sc[nf][0], sc[nf][1]));
      mx1 = fmaxf(mx1, fmaxf(sc[nf][2], sc[nf][3]));
    }
    mx0 = fmaxf(mx0, __shfl_xor_sync(0xffffffffu, mx0, 1));
    mx0 = fmaxf(mx0, __shfl_xor_sync(0xffffffffu, mx0, 2));
    mx1 = fmaxf(mx1, __shfl_xor_sync(0xffffffffu, mx1, 1));
    mx1 = fmaxf(mx1, __shfl_xor_sync(0xffffffffu, mx1, 2));
    float mn0 = fmaxf(m_[0], mx0);
    float mn1 = fmaxf(m_[1], mx1);
    float c0 = exp2_poly(m_[0] - mn0);
    float c1 = exp2_poly(m_[1] - mn1);
    m_[0] = mn0;
    m_[1] = mn1;

    float s0 = 0.0f, s1 = 0.0f;
#pragma unroll
    for (int nf = 0; nf < 8; nf++) {
      float p0 = exp2_poly(sc[nf][0] - mn0);
      float p1 = exp2_poly(sc[nf][1] - mn0);
      float p2 = exp2_poly(sc[nf][2] - mn1);
      float p3 = exp2_poly(sc[nf][3] - mn1);
      sc[nf][0] = p0; sc[nf][1] = p1; sc[nf][2] = p2; sc[nf][3] = p3;
      s0 += p0 + p1;
      s1 += p2 + p3;
    }
    l_[0] = l_[0] * c0 + s0;
    l_[1] = l_[1] * c1 + s1;
#pragma unroll
    for (int nf = 0; nf < 8; nf++) {
      o[nf][0] *= c0; o[nf][1] *= c0;
      o[nf][2] *= c1; o[nf][3] *= c1;
    }

    const uint32_t vhb = kvb + 2 * KV_TILE * 2;
#pragma unroll
    for (int ks = 0; ks < 4; ks++) {
      uint32_t phi[4], plo[4];
      split_pack2(sc[2 * ks][0], sc[2 * ks][1], phi[0], plo[0]);
      split_pack2(sc[2 * ks][2], sc[2 * ks][3], phi[1], plo[1]);
      split_pack2(sc[2 * ks + 1][0], sc[2 * ks + 1][1], phi[2], plo[2]);
      split_pack2(sc[2 * ks + 1][2], sc[2 * ks + 1][3], phi[3], plo[3]);
#pragma unroll
      for (int dg = 0; dg < 4; dg++) {
        uint32_t va = vhb + (uint32_t)((ks * 16 + a_r) * ARS + dg * 16 + a_c) * 2;
        uint32_t vh[4], vl[4];
        ldsm_x4_trans(vh, va);
        ldsm_x4_trans(vl, va + KV_TILE * 2);
        mma16816(o[dg * 2], phi, vh);
        mma16816(o[dg * 2], phi, vl);
        mma16816(o[dg * 2], plo, vh);
        mma16816(o[dg * 2 + 1], phi, vh + 2);
        mma16816(o[dg * 2 + 1], phi, vl + 2);
        mma16816(o[dg * 2 + 1], plo, vh + 2);
      }
    }
  }

  l_[0] += __shfl_xor_sync(0xffffffffu, l_[0], 1);
  l_[0] += __shfl_xor_sync(0xffffffffu, l_[0], 2);
  l_[1] += __shfl_xor_sync(0xffffffffu, l_[1], 1);
  l_[1] += __shfl_xor_sync(0xffffffffu, l_[1], 2);
  float inv0 = 1.0f / l_[0];
  float inv1 = 1.0f / l_[1];

#pragma unroll
  for (int nf = 0; nf < 8; nf++) {
    int col = h * HD + nf * 8 + tig * 2;
    *(__half2*)(O16 + (size_t)row0 * (H * HD) + col) =
        __floats2half2_rn(o[nf][0] * inv0, o[nf][1] * inv0);
    *(__half2*)(O16 + (size_t)(row0 + 8) * (H * HD) + col) =
        __floats2half2_rn(o[nf][2] * inv1, o[nf][3] * inv1);
  }
}

// ---------------------------------------------------------------------------
// Launch
// ---------------------------------------------------------------------------
extern "C" void kernel_launch(void* const* d_in, const int* in_sizes, int n_in,
                              void* d_out, int out_size) {
  const float* hs = (const float*)d_in[0];
  const float* Wq = (const float*)d_in[1];
  const float* Wk = (const float*)d_in[2];
  const float* Wv = (const float*)d_in[3];
  const float* Wo = (const float*)d_in[4];
  float* out = (float*)d_out;

  __nv_bfloat16 *Xhi, *Xlo, *WqkvThi, *WqkvTlo;
  __nv_bfloat16 *Qhi, *Qlo, *Khi, *Klo, *Vhi, *Vlo;
  __half *O16, *WoT16;
  cudaGetSymbolAddress((void**)&Xhi, g_Xhi);
  cudaGetSymbolAddress((void**)&Xlo, g_Xlo);
  cudaGetSymbolAddress((void**)&WqkvThi, g_WqkvThi);
  cudaGetSymbolAddress((void**)&WqkvTlo, g_WqkvTlo);
  cudaGetSymbolAddress((void**)&Qhi, g_Qhi);
  cudaGetSymbolAddress((void**)&Qlo, g_Qlo);
  cudaGetSymbolAddress((void**)&Khi, g_Khi);
  cudaGetSymbolAddress((void**)&Klo, g_Klo);
  cudaGetSymbolAddress((void**)&Vhi, g_Vhi);
  cudaGetSymbolAddress((void**)&Vlo, g_Vlo);
  cudaGetSymbolAddress((void**)&O16, g_O16);
  cudaGetSymbolAddress((void**)&WoT16, g_WoT16);

  // 1. split activations + rope table
  {
    int n4 = S * D / 4;
    split_kernel<<<(n4 + 255) / 256, 256>>>(hs, Xhi, Xlo, n4);
    rope_table_kernel<<<(S * 32 + 255) / 256, 256>>>();
  }

  // 2. transpose weights
  {
    dim3 blk(32, 8);
    transpose_split_kernel<<<dim3(D / 32, D / 32), blk>>>(Wq, WqkvThi, WqkvTlo, D, D);
    transpose_split_kernel<<<dim3(512 / 32, D / 32), blk>>>(
        Wk, WqkvThi + (size_t)KCOL * D, WqkvTlo + (size_t)KCOL * D, 512, D);
    transpose_split_kernel<<<dim3(512 / 32, D / 32), blk>>>(
        Wv, WqkvThi + (size_t)VCOL * D, WqkvTlo + (size_t)VCOL * D, 512, D);
    transpose_half_kernel<<<dim3(D / 32, D / 32), blk>>>(Wo, WoT16, D, D);
  }

  cudaFuncSetAttribute(gemm_qkv_rope_kernel,
                       cudaFuncAttributeMaxDynamicSharedMemorySize, GEMM_SMEM);
  cudaFuncSetAttribute(gemm_fp16_kernel,
                       cudaFuncAttributeMaxDynamicSharedMemorySize, GEMM16_SMEM);

  // 3. QKV projection + fused RoPE/split (R5 GEMM config)
  {
    dim3 grid(QKV_N / GBN, S / GBM);  // 24 x 16
    gemm_qkv_rope_kernel<<<grid, 256, GEMM_SMEM>>>(Xhi, Xlo, WqkvThi, WqkvTlo);
  }

  // 4. tensor-core flash attention -> fp16 O
  {
    cudaFuncSetAttribute(attn_mma_kernel,
                         cudaFuncAttributeMaxDynamicSharedMemorySize, ATT_SMEM);
    dim3 grid(H, S / ABQ);
    attn_mma_kernel<<<grid, 256, ATT_SMEM>>>(Qhi, Qlo, Khi, Klo, Vhi, Vlo, O16);
  }

  // 5. output projection (fp16)
  {
    dim3 grid(D / FBN, S / FBM);
    gemm_fp16_kernel<<<grid, 256, GEMM16_SMEM>>>(O16, WoT16, out, S, D, D);
  }
}

// round 8
// speedup vs baseline: 1.1605x; 1.0920x over previous
#include <cuda_runtime.h>
#include <cuda_bf16.h>
#include <cuda_fp16.h>
#include <cstdint>
#include <math.h>

#define S 2048
#define D 2048
#define H 32
#define KVH 8
#define HD 64
#define NREP (H / KVH)
#define QKV_N 3072
#define KCOL 2048
#define VCOL 2560

// ---------------------------------------------------------------------------
// Device-global scratch
// ---------------------------------------------------------------------------
__device__ __nv_bfloat16 g_Xhi[S * D], g_Xlo[S * D];
__device__ __nv_bfloat16 g_WqkvThi[QKV_N * D], g_WqkvTlo[QKV_N * D];
__device__ __nv_bfloat16 g_Qhi[S * H * HD], g_Qlo[S * H * HD];
__device__ __nv_bfloat16 g_Khi[S * KVH * HD], g_Klo[S * KVH * HD];
__device__ __half g_V16[S * KVH * HD];  // V stored fp16 (linear path)
__device__ __half g_O16[S * D];
__device__ __half g_WoT16[D * D];
__device__ float g_cos[S * 32], g_sin[S * 32];

// ---------------------------------------------------------------------------
// Helpers
// ---------------------------------------------------------------------------
__device__ __forceinline__ uint32_t smem_u32(const void* p) {
  uint32_t a;
  asm("{ .reg .u64 t; cvta.to.shared.u64 t, %1; cvt.u32.u64 %0, t; }"
      : "=r"(a) : "l"(p));
  return a;
}

__device__ __forceinline__ void ldsm_x4(uint32_t* r, uint32_t addr) {
  asm volatile(
      "ldmatrix.sync.aligned.m8n8.x4.shared.b16 {%0,%1,%2,%3}, [%4];"
      : "=r"(r[0]), "=r"(r[1]), "=r"(r[2]), "=r"(r[3]) : "r"(addr));
}

__device__ __forceinline__ void ldsm_x4_trans(uint32_t* r, uint32_t addr) {
  asm volatile(
      "ldmatrix.sync.aligned.m8n8.x4.trans.shared.b16 {%0,%1,%2,%3}, [%4];"
      : "=r"(r[0]), "=r"(r[1]), "=r"(r[2]), "=r"(r[3]) : "r"(addr));
}

__device__ __forceinline__ void mma16816(float* d, const uint32_t* a,
                                         const uint32_t* b) {
  asm volatile(
      "mma.sync.aligned.m16n8k16.row.col.f32.bf16.bf16.f32 "
      "{%0,%1,%2,%3}, {%4,%5,%6,%7}, {%8,%9}, {%0,%1,%2,%3};"
      : "+f"(d[0]), "+f"(d[1]), "+f"(d[2]), "+f"(d[3])
      : "r"(a[0]), "r"(a[1]), "r"(a[2]), "r"(a[3]), "r"(b[0]), "r"(b[1]));
}

__device__ __forceinline__ void mma16816h(float* d, const uint32_t* a,
                                          const uint32_t* b) {
  asm volatile(
      "mma.sync.aligned.m16n8k16.row.col.f32.f16.f16.f32 "
      "{%0,%1,%2,%3}, {%4,%5,%6,%7}, {%8,%9}, {%0,%1,%2,%3};"
      : "+f"(d[0]), "+f"(d[1]), "+f"(d[2]), "+f"(d[3])
      : "r"(a[0]), "r"(a[1]), "r"(a[2]), "r"(a[3]), "r"(b[0]), "r"(b[1]));
}

__device__ __forceinline__ void cp_async16(uint32_t saddr, const void* gptr) {
  asm volatile("cp.async.cg.shared.global [%0], [%1], 16;" ::
                   "r"(saddr), "l"(__cvta_generic_to_global(gptr)));
}
#define CP_COMMIT() asm volatile("cp.async.commit_group;" ::: "memory")
#define CP_WAIT0() asm volatile("cp.async.wait_group 0;" ::: "memory")

__device__ __forceinline__ float exp2_poly(float x) {
  x = fmaxf(x, -126.0f);
  float fl = floorf(x);
  float f = x - fl;
  float p = 1.5403530393e-4f;
  p = fmaf(p, f, 1.3333558146e-3f);
  p = fmaf(p, f, 9.6181291076e-3f);
  p = fmaf(p, f, 5.5504108665e-2f);
  p = fmaf(p, f, 2.4022650696e-1f);
  p = fmaf(p, f, 6.9314718056e-1f);
  p = fmaf(p, f, 1.0f);
  return p * __int_as_float(((int)fl + 127) << 23);
}

__device__ __forceinline__ void split2(float x, __nv_bfloat16& h, __nv_bfloat16& l) {
  h = __float2bfloat16(x);
  l = __float2bfloat16(x - __bfloat162float(h));
}

__device__ __forceinline__ void split_pack2(float x, float y, uint32_t& h,
                                            uint32_t& l) {
  __nv_bfloat162 hb = __floats2bfloat162_rn(x, y);
  float xr = x - __bfloat162float(hb.x);
  float yr = y - __bfloat162float(hb.y);
  __nv_bfloat162 lb = __floats2bfloat162_rn(xr, yr);
  h = *reinterpret_cast<uint32_t*>(&hb);
  l = *reinterpret_cast<uint32_t*>(&lb);
}

__device__ __forceinline__ uint32_t pack_half2(float x, float y) {
  __half2 v = __floats2half2_rn(x, y);
  return *reinterpret_cast<uint32_t*>(&v);
}

// ---------------------------------------------------------------------------
// Preprocessing
// ---------------------------------------------------------------------------
__global__ void split_kernel(const float* __restrict__ in,
                             __nv_bfloat16* __restrict__ hi,
                             __nv_bfloat16* __restrict__ lo, int n4) {
  int i = blockIdx.x * blockDim.x + threadIdx.x;
  if (i >= n4) return;
  float4 v = ((const float4*)in)[i];
  __nv_bfloat16 h0, l0, h1, l1, h2, l2, h3, l3;
  split2(v.x, h0, l0); split2(v.y, h1, l1);
  split2(v.z, h2, l2); split2(v.w, h3, l3);
  __nv_bfloat162* hp = (__nv_bfloat162*)hi;
  __nv_bfloat162* lp = (__nv_bfloat162*)lo;
  hp[i * 2 + 0] = __halves2bfloat162(h0, h1);
  hp[i * 2 + 1] = __halves2bfloat162(h2, h3);
  lp[i * 2 + 0] = __halves2bfloat162(l0, l1);
  lp[i * 2 + 1] = __halves2bfloat162(l2, l3);
}

__global__ void transpose_split_kernel(const float* __restrict__ W,
                                       __nv_bfloat16* __restrict__ Thi,
                                       __nv_bfloat16* __restrict__ Tlo,
                                       int N, int K) {
  __shared__ float t[32][33];
  int n0 = blockIdx.x * 32, k0 = blockIdx.y * 32;
  int tx = threadIdx.x, ty = threadIdx.y;
#pragma unroll
  for (int i = 0; i < 4; i++)
    t[ty + i * 8][tx] = W[(size_t)(k0 + ty + i * 8) * N + n0 + tx];
  __syncthreads();
#pragma unroll
  for (int i = 0; i < 4; i++) {
    int n = ty + i * 8;
    float x = t[tx][n];
    __nv_bfloat16 h, l;
    split2(x, h, l);
    size_t o = (size_t)(n0 + n) * K + k0 + tx;
    Thi[o] = h;
    Tlo[o] = l;
  }
}

__global__ void transpose_half_kernel(const float* __restrict__ W,
                                      __half* __restrict__ T, int N, int K) {
  __shared__ float t[32][33];
  int n0 = blockIdx.x * 32, k0 = blockIdx.y * 32;
  int tx = threadIdx.x, ty = threadIdx.y;
#pragma unroll
  for (int i = 0; i < 4; i++)
    t[ty + i * 8][tx] = W[(size_t)(k0 + ty + i * 8) * N + n0 + tx];
  __syncthreads();
#pragma unroll
  for (int i = 0; i < 4; i++) {
    int n = ty + i * 8;
    T[(size_t)(n0 + n) * K + k0 + tx] = __float2half(t[tx][n]);
  }
}

__global__ void rope_table_kernel() {
  int idx = blockIdx.x * blockDim.x + threadIdx.x;
  if (idx >= S * 32) return;
  int s = idx >> 5, i = idx & 31;
  float inv = 1.0f / powf(10000.0f, (2.0f * i) / (float)HD);
  float ang = (float)s * inv;
  g_cos[idx] = cosf(ang);
  g_sin[idx] = sinf(ang);
}

// ---------------------------------------------------------------------------
// QKV GEMM (bf16x3) with fused RoPE + split epilogue. V stored fp16.
// ---------------------------------------------------------------------------
#define GBM 128
#define GBN 128
#define GKC 32
#define RS 40
#define TILE_B (128 * RS * 2)
#define STAGE_B (4 * TILE_B)
#define GEMM_SMEM (2 * STAGE_B)

__global__ __launch_bounds__(256, 2) void gemm_qkv_rope_kernel(
    const __nv_bfloat16* __restrict__ Ahi, const __nv_bfloat16* __restrict__ Alo,
    const __nv_bfloat16* __restrict__ Bhi, const __nv_bfloat16* __restrict__ Blo) {
  extern __shared__ char smem[];
  const uint32_t sbase = smem_u32(smem);
  const int tid = threadIdx.x;
  const int wid = tid >> 5;
  const int lane = tid & 31;
  const int m0 = blockIdx.y * GBM;
  const int n0 = blockIdx.x * GBN;
  const int NC = D / GKC;

  const int wm = (wid & 3) * 32;
  const int wn = (wid >> 2) * 64;
  const int lrow = lane & 7;
  const int ltile = lane >> 3;
  const int a_r = (ltile & 1) * 8 + lrow;
  const int a_c = (ltile >> 1) * 8;
  const int b_r = (ltile >> 1) * 8 + lrow;
  const int b_c = (ltile & 1) * 8;

  const __nv_bfloat16* gA[2] = {Ahi + (size_t)m0 * D, Alo + (size_t)m0 * D};
  const __nv_bfloat16* gB[2] = {Bhi + (size_t)n0 * D, Blo + (size_t)n0 * D};

  auto load_stage = [&](int stg, int chunk) {
    const int kc = chunk * GKC;
    uint32_t sb = sbase + stg * STAGE_B;
#pragma unroll
    for (int t = 0; t < 4; t++) {
      const __nv_bfloat16* gp = (t < 2) ? gA[t] : gB[t - 2];
#pragma unroll
      for (int i = 0; i < 2; i++) {
        int v = tid + i * 256;
        int r = v >> 2;
        int c = (v & 3) * 8;
        cp_async16(sb + t * TILE_B + (uint32_t)(r * RS + c) * 2,
                   gp + (size_t)r * D + kc + c);
      }
    }
    CP_COMMIT();
  };

  float acc[2][8][4];
#pragma unroll
  for (int f = 0; f < 2; f++)
#pragma unroll
    for (int g = 0; g < 8; g++)
#pragma unroll
      for (int x = 0; x < 4; x++) acc[f][g][x] = 0.0f;

  load_stage(0, 0);

  for (int c = 0; c < NC; c++) {
    CP_WAIT0();
    __syncthreads();
    if (c + 1 < NC) load_stage((c + 1) & 1, c + 1);

    uint32_t sb = sbase + (c & 1) * STAGE_B;
#pragma unroll
    for (int kk = 0; kk < 2; kk++) {
      const int k0 = kk * 16;
      uint32_t ah[2][4], al[2][4];
#pragma unroll
      for (int f = 0; f < 2; f++) {
        uint32_t ar = (uint32_t)((wm + f * 16 + a_r) * RS + k0 + a_c) * 2;
        ldsm_x4(ah[f], sb + 0 * TILE_B + ar);
        ldsm_x4(al[f], sb + 1 * TILE_B + ar);
      }
#pragma unroll
      for (int g2 = 0; g2 < 4; g2++) {
        uint32_t br = (uint32_t)((wn + g2 * 16 + b_r) * RS + k0 + b_c) * 2;
        uint32_t rh[4], rl[4];
        ldsm_x4(rh, sb + 2 * TILE_B + br);
        ldsm_x4(rl, sb + 3 * TILE_B + br);
#pragma unroll
        for (int sub = 0; sub < 2; sub++) {
          int g = g2 * 2 + sub;
#pragma unroll
          for (int f = 0; f < 2; f++) {
            mma16816(acc[f][g], ah[f], rh + 2 * sub);
            mma16816(acc[f][g], ah[f], rl + 2 * sub);
            mma16816(acc[f][g], al[f], rh + 2 * sub);
          }
        }
      }
    }
    __syncthreads();
  }

  // ---- fused RoPE + split epilogue (uniform region per CTA) ----
  const int gid = lane >> 2, tig = lane & 3;
  const int region = (n0 < KCOL) ? 0 : ((n0 < VCOL) ? 1 : 2);

#pragma unroll
  for (int f = 0; f < 2; f++) {
    int rowA = m0 + wm + f * 16 + gid;
#pragma unroll
    for (int g = 0; g < 8; g++) {
      int C = n0 + wn + g * 8 + tig * 2;
#pragma unroll
      for (int half = 0; half < 2; half++) {
        int s = rowA + half * 8;
        float x = acc[f][g][half * 2 + 0];
        float y = acc[f][g][half * 2 + 1];
        uint32_t hreg, lreg;
        if (region == 0) {  // Q: rope, bf16 hi/lo
          int i = (C & 63) >> 1;
          float cs = g_cos[s * 32 + i], sn = g_sin[s * 32 + i];
          float xr = x * cs - y * sn;
          float xi = x * sn + y * cs;
          split_pack2(xr, xi, hreg, lreg);
          size_t o = (size_t)s * (H * HD) + C;
          *(uint32_t*)(g_Qhi + o) = hreg;
          *(uint32_t*)(g_Qlo + o) = lreg;
        } else if (region == 1) {  // K: rope, bf16 hi/lo
          int off = C - KCOL;
          int i = (off & 63) >> 1;
          float cs = g_cos[s * 32 + i], sn = g_sin[s * 32 + i];
          float xr = x * cs - y * sn;
          float xi = x * sn + y * cs;
          split_pack2(xr, xi, hreg, lreg);
          size_t o = (size_t)s * (KVH * HD) + off;
          *(uint32_t*)(g_Khi + o) = hreg;
          *(uint32_t*)(g_Klo + o) = lreg;
        } else {  // V: fp16 single (linear path)
          int off = C - VCOL;
          size_t o = (size_t)s * (KVH * HD) + off;
          *(uint32_t*)(g_V16 + o) = pack_half2(x, y);
        }
      }
    }
  }
}

// ---------------------------------------------------------------------------
// fp16 single-product GEMM (Wo).
// ---------------------------------------------------------------------------
#define FBM 128
#define FBN 128
#define FTILE_B (128 * RS * 2)
#define FSTAGE_B (2 * FTILE_B)
#define GEMM16_SMEM (2 * FSTAGE_B)

__global__ __launch_bounds__(256, 2) void gemm_fp16_kernel(
    const __half* __restrict__ A, const __half* __restrict__ B,
    float* __restrict__ C, int M, int N, int K) {
  extern __shared__ char smem[];
  const uint32_t sbase = smem_u32(smem);
  const int tid = threadIdx.x;
  const int wid = tid >> 5;
  const int lane = tid & 31;
  const int m0 = blockIdx.y * FBM;
  const int n0 = blockIdx.x * FBN;
  const int NC = K / GKC;

  const int wm = (wid & 3) * 32;
  const int wn = (wid >> 2) * 64;
  const int lrow = lane & 7;
  const int ltile = lane >> 3;
  const int a_r = (ltile & 1) * 8 + lrow;
  const int a_c = (ltile >> 1) * 8;
  const int b_r = (ltile >> 1) * 8 + lrow;
  const int b_c = (ltile & 1) * 8;

  const __half* gA = A + (size_t)m0 * K;
  const __half* gB = B + (size_t)n0 * K;

  auto load_stage = [&](int stg, int chunk) {
    const int kc = chunk * GKC;
    uint32_t sb = sbase + stg * FSTAGE_B;
#pragma unroll
    for (int i = 0; i < 2; i++) {
      int v = tid + i * 256;
      int r = v >> 2;
      int c = (v & 3) * 8;
      cp_async16(sb + (uint32_t)(r * RS + c) * 2, gA + (size_t)r * K + kc + c);
      cp_async16(sb + FTILE_B + (uint32_t)(r * RS + c) * 2,
                 gB + (size_t)r * K + kc + c);
    }
    CP_COMMIT();
  };

  float acc[2][8][4];
#pragma unroll
  for (int f = 0; f < 2; f++)
#pragma unroll
    for (int g = 0; g < 8; g++)
#pragma unroll
      for (int x = 0; x < 4; x++) acc[f][g][x] = 0.0f;

  load_stage(0, 0);

  for (int c = 0; c < NC; c++) {
    CP_WAIT0();
    __syncthreads();
    if (c + 1 < NC) load_stage((c + 1) & 1, c + 1);

    uint32_t sb = sbase + (c & 1) * FSTAGE_B;
#pragma unroll
    for (int kk = 0; kk < 2; kk++) {
      const int k0 = kk * 16;
      uint32_t af[2][4];
#pragma unroll
      for (int f = 0; f < 2; f++) {
        uint32_t ar = (uint32_t)((wm + f * 16 + a_r) * RS + k0 + a_c) * 2;
        ldsm_x4(af[f], sb + ar);
      }
#pragma unroll
      for (int g2 = 0; g2 < 4; g2++) {
        uint32_t br = (uint32_t)((wn + g2 * 16 + b_r) * RS + k0 + b_c) * 2;
        uint32_t r4[4];
        ldsm_x4(r4, sb + FTILE_B + br);
#pragma unroll
        for (int f = 0; f < 2; f++) {
          mma16816h(acc[f][g2 * 2], af[f], r4);
          mma16816h(acc[f][g2 * 2 + 1], af[f], r4 + 2);
        }
      }
    }
    __syncthreads();
  }

  const int gid = lane >> 2, tig = lane & 3;
#pragma unroll
  for (int f = 0; f < 2; f++) {
#pragma unroll
    for (int g = 0; g < 8; g++) {
      int row = m0 + wm + f * 16 + gid;
      int col = n0 + wn + g * 8 + tig * 2;
      *(float2*)(C + (size_t)row * N + col) = make_float2(acc[f][g][0], acc[f][g][1]);
      *(float2*)(C + (size_t)(row + 8) * N + col) = make_float2(acc[f][g][2], acc[f][g][3]);
    }
  }
}

// ---------------------------------------------------------------------------
// Tensor-core flash attention. QK: bf16x3 (3 mma). PV: all-fp16 (1 mma).
// KV stage: Khi, Klo (bf16) + V16 (fp16) = 3 tiles.
// ---------------------------------------------------------------------------
#define ABQ 128
#define ABKV 64
#define ARS 72
#define Q_ELEMS (ABQ * ARS)
#define KV_TILE (ABKV * ARS)
#define KV_STAGE (3 * KV_TILE)
#define ATT_SMEM ((2 * Q_ELEMS + 2 * KV_STAGE) * 2)

__global__ __launch_bounds__(256) void attn_mma_kernel(
    const __nv_bfloat16* __restrict__ Qhi, const __nv_bfloat16* __restrict__ Qlo,
    const __nv_bfloat16* __restrict__ Khi, const __nv_bfloat16* __restrict__ Klo,
    const __half* __restrict__ V16, __half* __restrict__ O16) {
  extern __shared__ char sbuf[];
  const uint32_t sbase = smem_u32(sbuf);
  const int tid = threadIdx.x;
  const int wid = tid >> 5;
  const int lane = tid & 31;
  const int h = blockIdx.x;
  const int kvh = h / NREP;
  const int q0 = ((int)gridDim.y - 1 - (int)blockIdx.y) * ABQ;
  const int wm = wid * 16;

  const int lrow = lane & 7;
  const int ltile = lane >> 3;
  const int a_r = (ltile & 1) * 8 + lrow;
  const int a_c = (ltile >> 1) * 8;
  const int b_r = (ltile >> 1) * 8 + lrow;
  const int b_c = (ltile & 1) * 8;
  const int gid = lane >> 2, tig = lane & 3;

  const uint32_t qhi_s = sbase;
  const uint32_t qlo_s = sbase + Q_ELEMS * 2;

#pragma unroll
  for (int i = 0; i < 4; i++) {
    int v = tid + i * 256;
    int r = v >> 3, c = v & 7;
    size_t g = (size_t)(q0 + r) * (H * HD) + h * HD + c * 8;
    uint32_t so = (uint32_t)(r * ARS + c * 8) * 2;
    cp_async16(qhi_s + so, Qhi + g);
    cp_async16(qlo_s + so, Qlo + g);
  }

  auto load_kv = [&](int stg, int kv0) {
    uint32_t base = sbase + (2 * Q_ELEMS + stg * KV_STAGE) * 2;
#pragma unroll
    for (int i = 0; i < 2; i++) {
      int v = tid + i * 256;
      int r = v >> 3, c = v & 7;
      size_t g = (size_t)(kv0 + r) * (KVH * HD) + kvh * HD + c * 8;
      uint32_t so = (uint32_t)(r * ARS + c * 8) * 2;
      cp_async16(base + 0 * KV_TILE * 2 + so, Khi + g);
      cp_async16(base + 1 * KV_TILE * 2 + so, Klo + g);
      cp_async16(base + 2 * KV_TILE * 2 + so, V16 + g);
    }
    CP_COMMIT();
  };

  load_kv(0, 0);

  const int ntiles = (q0 + ABQ) / ABKV;
  float m_[2] = {-1e30f, -1e30f};
  float l_[2] = {0.0f, 0.0f};
  float o[8][4];
#pragma unroll
  for (int nf = 0; nf < 8; nf++)
#pragma unroll
    for (int j = 0; j < 4; j++) o[nf][j] = 0.0f;

  const float SCL = 0.18033688011112042f;
  const int row0 = q0 + wm + gid;

  for (int t = 0; t < ntiles; t++) {
    const int kv0 = t * ABKV;
    CP_WAIT0();
    __syncthreads();
    if (t + 1 < ntiles) load_kv((t + 1) & 1, kv0 + ABKV);

    const uint32_t kvb = sbase + (2 * Q_ELEMS + (t & 1) * KV_STAGE) * 2;

    float sc[8][4];
#pragma unroll
    for (int nf = 0; nf < 8; nf++)
#pragma unroll
      for (int j = 0; j < 4; j++) sc[nf][j] = 0.0f;

#pragma unroll
    for (int ks = 0; ks < 4; ks++) {
      const int k0 = ks * 16;
      uint32_t ah[4], al[4];
      uint32_t ar = (uint32_t)((wm + a_r) * ARS + k0 + a_c) * 2;
      ldsm_x4(ah, qhi_s + ar);
      ldsm_x4(al, qlo_s + ar);
#pragma unroll
      for (int ng = 0; ng < 4; ng++) {
        uint32_t br = kvb + (uint32_t)((ng * 16 + b_r) * ARS + k0 + b_c) * 2;
        uint32_t rh[4], rl[4];
        ldsm_x4(rh, br);
        ldsm_x4(rl, br + KV_TILE * 2);
        mma16816(sc[ng * 2], ah, rh);
        mma16816(sc[ng * 2], ah, rl);
        mma16816(sc[ng * 2], al, rh);
        mma16816(sc[ng * 2 + 1], ah, rh + 2);
        mma16816(sc[ng * 2 + 1], ah, rl + 2);
        mma16816(sc[ng * 2 + 1], al, rh + 2);
      }
    }

    const bool nomask = (kv0 + ABKV - 1 <= q0 + wm);
    if (nomask) {
#pragma unroll
      for (int nf = 0; nf < 8; nf++)
#pragma unroll
        for (int j = 0; j < 4; j++) sc[nf][j] *= SCL;
    } else {
#pragma unroll
      for (int nf = 0; nf < 8; nf++) {
        int col = kv0 + nf * 8 + tig * 2;
#pragma unroll
        for (int j = 0; j < 4; j++) {
          int cc = col + (j & 1);
          int rr = row0 + ((j >> 1) << 3);
          sc[nf][j] = (cc <= rr) ? sc[nf][j] * SCL : -1e30f;
        }
      }
    }

    float mx0 = -1e30f, mx1 = -1e30f;
#pragma unroll
    for (int nf = 0; nf < 8; nf++) {
      mx0 = fmaxf(mx0, fmaxf(sc[nf][0], sc[nf][1]));
      mx1 = fmaxf(mx1, fmaxf(sc[nf][2], sc[nf][3]));
    }
    mx0 = fmaxf(mx0, __shfl_xor_sync(0xffffffffu, mx0, 1));
    mx0 = fmaxf(mx0, __shfl_xor_sync(0xffffffffu, mx0, 2));
    mx1 = fmaxf(mx1, __shfl_xor_sync(0xffffffffu, mx1, 1));
    mx1 = fmaxf(mx1, __shfl_xor_sync(0xffffffffu, mx1, 2));
    float mn0 = fmaxf(m_[0], mx0);
    float mn1 = fmaxf(m_[1], mx1);
    float c0 = exp2_poly(m_[0] - mn0);
    float c1 = exp2_poly(m_[1] - mn1);
    m_[0] = mn0;
    m_[1] = mn1;

    float s0 = 0.0f, s1 = 0.0f;
#pragma unroll
    for (int nf = 0; nf < 8; nf++) {
      float p0 = exp2_poly(sc[nf][0] - mn0);
      float p1 = exp2_poly(sc[nf][1] - mn0);
      float p2 = exp2_poly(sc[nf][2] - mn1);
      float p3 = exp2_poly(sc[nf][3] - mn1);
      sc[nf][0] = p0; sc[nf][1] = p1; sc[nf][2] = p2; sc[nf][3] = p3;
      s0 += p0 + p1;
      s1 += p2 + p3;
    }
    l_[0] = l_[0] * c0 + s0;
    l_[1] = l_[1] * c1 + s1;
#pragma unroll
    for (int nf = 0; nf < 8; nf++) {
      o[nf][0] *= c0; o[nf][1] *= c0;
      o[nf][2] *= c1; o[nf][3] *= c1;
    }

    // ---- O += P V (all fp16 single product) ----
    const uint32_t vb = kvb + 2 * KV_TILE * 2;
#pragma unroll
    for (int ks = 0; ks < 4; ks++) {
      uint32_t p16[4];
      p16[0] = pack_half2(sc[2 * ks][0], sc[2 * ks][1]);
      p16[1] = pack_half2(sc[2 * ks][2], sc[2 * ks][3]);
      p16[2] = pack_half2(sc[2 * ks + 1][0], sc[2 * ks + 1][1]);
      p16[3] = pack_half2(sc[2 * ks + 1][2], sc[2 * ks + 1][3]);
#pragma unroll
      for (int dg = 0; dg < 4; dg++) {
        uint32_t va = vb + (uint32_t)((ks * 16 + a_r) * ARS + dg * 16 + a_c) * 2;
        uint32_t vh[4];
        ldsm_x4_trans(vh, va);
        mma16816h(o[dg * 2], p16, vh);
        mma16816h(o[dg * 2 + 1], p16, vh + 2);
      }
    }
  }

  l_[0] += __shfl_xor_sync(0xffffffffu, l_[0], 1);
  l_[0] += __shfl_xor_sync(0xffffffffu, l_[0], 2);
  l_[1] += __shfl_xor_sync(0xffffffffu, l_[1], 1);
  l_[1] += __shfl_xor_sync(0xffffffffu, l_[1], 2);
  float inv0 = 1.0f / l_[0];
  float inv1 = 1.0f / l_[1];

#pragma unroll
  for (int nf = 0; nf < 8; nf++) {
    int col = h * HD + nf * 8 + tig * 2;
    *(__half2*)(O16 + (size_t)row0 * (H * HD) + col) =
        __floats2half2_rn(o[nf][0] * inv0, o[nf][1] * inv0);
    *(__half2*)(O16 + (size_t)(row0 + 8) * (H * HD) + col) =
        __floats2half2_rn(o[nf][2] * inv1, o[nf][3] * inv1);
  }
}

// ---------------------------------------------------------------------------
// Launch
// ---------------------------------------------------------------------------
extern "C" void kernel_launch(void* const* d_in, const int* in_sizes, int n_in,
                              void* d_out, int out_size) {
  const float* hs = (const float*)d_in[0];
  const float* Wq = (const float*)d_in[1];
  const float* Wk = (const float*)d_in[2];
  const float* Wv = (const float*)d_in[3];
  const float* Wo = (const float*)d_in[4];
  float* out = (float*)d_out;

  __nv_bfloat16 *Xhi, *Xlo, *WqkvThi, *WqkvTlo;
  __nv_bfloat16 *Qhi, *Qlo, *Khi, *Klo;
  __half *V16, *O16, *WoT16;
  cudaGetSymbolAddress((void**)&Xhi, g_Xhi);
  cudaGetSymbolAddress((void**)&Xlo, g_Xlo);
  cudaGetSymbolAddress((void**)&WqkvThi, g_WqkvThi);
  cudaGetSymbolAddress((void**)&WqkvTlo, g_WqkvTlo);
  cudaGetSymbolAddress((void**)&Qhi, g_Qhi);
  cudaGetSymbolAddress((void**)&Qlo, g_Qlo);
  cudaGetSymbolAddress((void**)&Khi, g_Khi);
  cudaGetSymbolAddress((void**)&Klo, g_Klo);
  cudaGetSymbolAddress((void**)&V16, g_V16);
  cudaGetSymbolAddress((void**)&O16, g_O16);
  cudaGetSymbolAddress((void**)&WoT16, g_WoT16);

  // 1. split activations + rope table
  {
    int n4 = S * D / 4;
    split_kernel<<<(n4 + 255) / 256, 256>>>(hs, Xhi, Xlo, n4);
    rope_table_kernel<<<(S * 32 + 255) / 256, 256>>>();
  }

  // 2. transpose weights
  {
    dim3 blk(32, 8);
    transpose_split_kernel<<<dim3(D / 32, D / 32), blk>>>(Wq, WqkvThi, WqkvTlo, D, D);
    transpose_split_kernel<<<dim3(512 / 32, D / 32), blk>>>(
        Wk, WqkvThi + (size_t)KCOL * D, WqkvTlo + (size_t)KCOL * D, 512, D);
    transpose_split_kernel<<<dim3(512 / 32, D / 32), blk>>>(
        Wv, WqkvThi + (size_t)VCOL * D, WqkvTlo + (size_t)VCOL * D, 512, D);
    transpose_half_kernel<<<dim3(D / 32, D / 32), blk>>>(Wo, WoT16, D, D);
  }

  cudaFuncSetAttribute(gemm_qkv_rope_kernel,
                       cudaFuncAttributeMaxDynamicSharedMemorySize, GEMM_SMEM);
  cudaFuncSetAttribute(gemm_fp16_kernel,
                       cudaFuncAttributeMaxDynamicSharedMemorySize, GEMM16_SMEM);

  // 3. QKV projection + fused RoPE/split
  {
    dim3 grid(QKV_N / GBN, S / GBM);  // 24 x 16
    gemm_qkv_rope_kernel<<<grid, 256, GEMM_SMEM>>>(Xhi, Xlo, WqkvThi, WqkvTlo);
  }

  // 4. tensor-core flash attention (QK bf16x3, PV fp16) -> fp16 O
  {
    cudaFuncSetAttribute(attn_mma_kernel,
                         cudaFuncAttributeMaxDynamicSharedMemorySize, ATT_SMEM);
    dim3 grid(H, S / ABQ);
    attn_mma_kernel<<<grid, 256, ATT_SMEM>>>(Qhi, Qlo, Khi, Klo, V16, O16);
  }

  // 5. output projection (fp16)
  {
    dim3 grid(D / FBN, S / FBM);
    gemm_fp16_kernel<<<grid, 256, GEMM16_SMEM>>>(O16, WoT16, out, S, D, D);
  }
}

// round 9
// speedup vs baseline: 1.1755x; 1.0129x over previous
#include <cuda_runtime.h>
#include <cuda_bf16.h>
#include <cuda_fp16.h>
#include <cstdint>
#include <math.h>

#define S 2048
#define D 2048
#define H 32
#define KVH 8
#define HD 64
#define NREP (H / KVH)
#define QKV_N 3072
#define KCOL 2048
#define VCOL 2560

// ---------------------------------------------------------------------------
// Device-global scratch
// ---------------------------------------------------------------------------
__device__ __nv_bfloat16 g_Xhi[S * D], g_Xlo[S * D];
__device__ __nv_bfloat16 g_WqkvThi[QKV_N * D], g_WqkvTlo[QKV_N * D];
__device__ __nv_bfloat16 g_Qhi[S * H * HD], g_Qlo[S * H * HD];
__device__ __nv_bfloat16 g_Khi[S * KVH * HD], g_Klo[S * KVH * HD];
__device__ __half g_V16[S * KVH * HD];
__device__ __half g_O16[S * D];
__device__ __half g_WoT16[D * D];
__device__ float g_cos[S * 32], g_sin[S * 32];

// ---------------------------------------------------------------------------
// Helpers
// ---------------------------------------------------------------------------
__device__ __forceinline__ uint32_t smem_u32(const void* p) {
  uint32_t a;
  asm("{ .reg .u64 t; cvta.to.shared.u64 t, %1; cvt.u32.u64 %0, t; }"
      : "=r"(a) : "l"(p));
  return a;
}

__device__ __forceinline__ void ldsm_x4(uint32_t* r, uint32_t addr) {
  asm volatile(
      "ldmatrix.sync.aligned.m8n8.x4.shared.b16 {%0,%1,%2,%3}, [%4];"
      : "=r"(r[0]), "=r"(r[1]), "=r"(r[2]), "=r"(r[3]) : "r"(addr));
}

__device__ __forceinline__ void ldsm_x4_trans(uint32_t* r, uint32_t addr) {
  asm volatile(
      "ldmatrix.sync.aligned.m8n8.x4.trans.shared.b16 {%0,%1,%2,%3}, [%4];"
      : "=r"(r[0]), "=r"(r[1]), "=r"(r[2]), "=r"(r[3]) : "r"(addr));
}

__device__ __forceinline__ void mma16816(float* d, const uint32_t* a,
                                         const uint32_t* b) {
  asm volatile(
      "mma.sync.aligned.m16n8k16.row.col.f32.bf16.bf16.f32 "
      "{%0,%1,%2,%3}, {%4,%5,%6,%7}, {%8,%9}, {%0,%1,%2,%3};"
      : "+f"(d[0]), "+f"(d[1]), "+f"(d[2]), "+f"(d[3])
      : "r"(a[0]), "r"(a[1]), "r"(a[2]), "r"(a[3]), "r"(b[0]), "r"(b[1]));
}

__device__ __forceinline__ void mma16816h(float* d, const uint32_t* a,
                                          const uint32_t* b) {
  asm volatile(
      "mma.sync.aligned.m16n8k16.row.col.f32.f16.f16.f32 "
      "{%0,%1,%2,%3}, {%4,%5,%6,%7}, {%8,%9}, {%0,%1,%2,%3};"
      : "+f"(d[0]), "+f"(d[1]), "+f"(d[2]), "+f"(d[3])
      : "r"(a[0]), "r"(a[1]), "r"(a[2]), "r"(a[3]), "r"(b[0]), "r"(b[1]));
}

__device__ __forceinline__ void cp_async16(uint32_t saddr, const void* gptr) {
  asm volatile("cp.async.cg.shared.global [%0], [%1], 16;" ::
                   "r"(saddr), "l"(__cvta_generic_to_global(gptr)));
}
#define CP_COMMIT() asm volatile("cp.async.commit_group;" ::: "memory")
#define CP_WAIT0() asm volatile("cp.async.wait_group 0;" ::: "memory")

__device__ __forceinline__ float exp2_poly(float x) {
  x = fmaxf(x, -126.0f);
  float fl = floorf(x);
  float f = x - fl;
  float p = 1.5403530393e-4f;
  p = fmaf(p, f, 1.3333558146e-3f);
  p = fmaf(p, f, 9.6181291076e-3f);
  p = fmaf(p, f, 5.5504108665e-2f);
  p = fmaf(p, f, 2.4022650696e-1f);
  p = fmaf(p, f, 6.9314718056e-1f);
  p = fmaf(p, f, 1.0f);
  return p * __int_as_float(((int)fl + 127) << 23);
}

__device__ __forceinline__ void split2(float x, __nv_bfloat16& h, __nv_bfloat16& l) {
  h = __float2bfloat16(x);
  l = __float2bfloat16(x - __bfloat162float(h));
}

__device__ __forceinline__ void split_pack2(float x, float y, uint32_t& h,
                                            uint32_t& l) {
  __nv_bfloat162 hb = __floats2bfloat162_rn(x, y);
  float xr = x - __bfloat162float(hb.x);
  float yr = y - __bfloat162float(hb.y);
  __nv_bfloat162 lb = __floats2bfloat162_rn(xr, yr);
  h = *reinterpret_cast<uint32_t*>(&hb);
  l = *reinterpret_cast<uint32_t*>(&lb);
}

__device__ __forceinline__ uint32_t pack_half2(float x, float y) {
  __half2 v = __floats2half2_rn(x, y);
  return *reinterpret_cast<uint32_t*>(&v);
}

// ---------------------------------------------------------------------------
// Preprocessing
// ---------------------------------------------------------------------------
__global__ void split_kernel(const float* __restrict__ in,
                             __nv_bfloat16* __restrict__ hi,
                             __nv_bfloat16* __restrict__ lo, int n4) {
  int i = blockIdx.x * blockDim.x + threadIdx.x;
  if (i >= n4) return;
  float4 v = ((const float4*)in)[i];
  __nv_bfloat16 h0, l0, h1, l1, h2, l2, h3, l3;
  split2(v.x, h0, l0); split2(v.y, h1, l1);
  split2(v.z, h2, l2); split2(v.w, h3, l3);
  __nv_bfloat162* hp = (__nv_bfloat162*)hi;
  __nv_bfloat162* lp = (__nv_bfloat162*)lo;
  hp[i * 2 + 0] = __halves2bfloat162(h0, h1);
  hp[i * 2 + 1] = __halves2bfloat162(h2, h3);
  lp[i * 2 + 0] = __halves2bfloat162(l0, l1);
  lp[i * 2 + 1] = __halves2bfloat162(l2, l3);
}

__global__ void transpose_split_kernel(const float* __restrict__ W,
                                       __nv_bfloat16* __restrict__ Thi,
                                       __nv_bfloat16* __restrict__ Tlo,
                                       int N, int K) {
  __shared__ float t[32][33];
  int n0 = blockIdx.x * 32, k0 = blockIdx.y * 32;
  int tx = threadIdx.x, ty = threadIdx.y;
#pragma unroll
  for (int i = 0; i < 4; i++)
    t[ty + i * 8][tx] = W[(size_t)(k0 + ty + i * 8) * N + n0 + tx];
  __syncthreads();
#pragma unroll
  for (int i = 0; i < 4; i++) {
    int n = ty + i * 8;
    float x = t[tx][n];
    __nv_bfloat16 h, l;
    split2(x, h, l);
    size_t o = (size_t)(n0 + n) * K + k0 + tx;
    Thi[o] = h;
    Tlo[o] = l;
  }
}

__global__ void transpose_half_kernel(const float* __restrict__ W,
                                      __half* __restrict__ T, int N, int K) {
  __shared__ float t[32][33];
  int n0 = blockIdx.x * 32, k0 = blockIdx.y * 32;
  int tx = threadIdx.x, ty = threadIdx.y;
#pragma unroll
  for (int i = 0; i < 4; i++)
    t[ty + i * 8][tx] = W[(size_t)(k0 + ty + i * 8) * N + n0 + tx];
  __syncthreads();
#pragma unroll
  for (int i = 0; i < 4; i++) {
    int n = ty + i * 8;
    T[(size_t)(n0 + n) * K + k0 + tx] = __float2half(t[tx][n]);
  }
}

__global__ void rope_table_kernel() {
  int idx = blockIdx.x * blockDim.x + threadIdx.x;
  if (idx >= S * 32) return;
  int s = idx >> 5, i = idx & 31;
  float inv = 1.0f / powf(10000.0f, (2.0f * i) / (float)HD);
  float ang = (float)s * inv;
  g_cos[idx] = cosf(ang);
  g_sin[idx] = sinf(ang);
}

// ---------------------------------------------------------------------------
// QKV GEMM (bf16x3) + fused RoPE/split epilogue.
// Tile 128x96x32 -> grid 512 CTAs (86% wave util at 2 CTA/SM).
// ---------------------------------------------------------------------------
#define GBM 128
#define GBN 96
#define GKC 32
#define RS 40
#define A_TILE (128 * RS * 2)   // 10240 B
#define B_TILE (96 * RS * 2)    // 7680 B
#define QS_AH 0
#define QS_AL A_TILE
#define QS_BH (2 * A_TILE)
#define QS_BL (2 * A_TILE + B_TILE)
#define STAGE_B (2 * A_TILE + 2 * B_TILE)  // 35840 B
#define GEMM_SMEM (2 * STAGE_B)            // 71680 B

__global__ __launch_bounds__(256, 2) void gemm_qkv_rope_kernel(
    const __nv_bfloat16* __restrict__ Ahi, const __nv_bfloat16* __restrict__ Alo,
    const __nv_bfloat16* __restrict__ Bhi, const __nv_bfloat16* __restrict__ Blo) {
  extern __shared__ char smem[];
  const uint32_t sbase = smem_u32(smem);
  const int tid = threadIdx.x;
  const int wid = tid >> 5;
  const int lane = tid & 31;
  const int m0 = blockIdx.y * GBM;
  const int n0 = blockIdx.x * GBN;
  const int NC = D / GKC;

  const int wm = (wid & 3) * 32;   // 4 warps over M
  const int wn = (wid >> 2) * 48;  // 2 warps over N (48 each)
  const int lrow = lane & 7;
  const int ltile = lane >> 3;
  const int a_r = (ltile & 1) * 8 + lrow;
  const int a_c = (ltile >> 1) * 8;
  const int b_r = (ltile >> 1) * 8 + lrow;
  const int b_c = (ltile & 1) * 8;

  const __nv_bfloat16* gA[2] = {Ahi + (size_t)m0 * D, Alo + (size_t)m0 * D};
  const __nv_bfloat16* gB[2] = {Bhi + (size_t)n0 * D, Blo + (size_t)n0 * D};

  auto load_stage = [&](int stg, int chunk) {
    const int kc = chunk * GKC;
    uint32_t sb = sbase + stg * STAGE_B;
    // A: 128 rows x 4 vec16 = 512 vectors -> 2/thread (hi+lo)
#pragma unroll
    for (int i = 0; i < 2; i++) {
      int v = tid + i * 256;
      int r = v >> 2;
      int c = (v & 3) * 8;
      size_t g = (size_t)r * D + kc + c;
      uint32_t so = (uint32_t)(r * RS + c) * 2;
      cp_async16(sb + QS_AH + so, gA[0] + g);
      cp_async16(sb + QS_AL + so, gA[1] + g);
    }
    // B: 96 rows x 4 vec16 = 384 vectors (hi+lo)
    for (int v = tid; v < 384; v += 256) {
      int r = v >> 2;
      int c = (v & 3) * 8;
      size_t g = (size_t)r * D + kc + c;
      uint32_t so = (uint32_t)(r * RS + c) * 2;
      cp_async16(sb + QS_BH + so, gB[0] + g);
      cp_async16(sb + QS_BL + so, gB[1] + g);
    }
    CP_COMMIT();
  };

  float acc[2][6][4];
#pragma unroll
  for (int f = 0; f < 2; f++)
#pragma unroll
    for (int g = 0; g < 6; g++)
#pragma unroll
      for (int x = 0; x < 4; x++) acc[f][g][x] = 0.0f;

  load_stage(0, 0);

  for (int c = 0; c < NC; c++) {
    CP_WAIT0();
    __syncthreads();
    if (c + 1 < NC) load_stage((c + 1) & 1, c + 1);

    uint32_t sb = sbase + (c & 1) * STAGE_B;
#pragma unroll
    for (int kk = 0; kk < 2; kk++) {
      const int k0 = kk * 16;
      uint32_t ah[2][4], al[2][4];
#pragma unroll
      for (int f = 0; f < 2; f++) {
        uint32_t ar = (uint32_t)((wm + f * 16 + a_r) * RS + k0 + a_c) * 2;
        ldsm_x4(ah[f], sb + QS_AH + ar);
        ldsm_x4(al[f], sb + QS_AL + ar);
      }
#pragma unroll
      for (int g2 = 0; g2 < 3; g2++) {
        uint32_t br = (uint32_t)((wn + g2 * 16 + b_r) * RS + k0 + b_c) * 2;
        uint32_t rh[4], rl[4];
        ldsm_x4(rh, sb + QS_BH + br);
        ldsm_x4(rl, sb + QS_BL + br);
#pragma unroll
        for (int sub = 0; sub < 2; sub++) {
          int g = g2 * 2 + sub;
#pragma unroll
          for (int f = 0; f < 2; f++) {
            mma16816(acc[f][g], ah[f], rh + 2 * sub);
            mma16816(acc[f][g], ah[f], rl + 2 * sub);
            mma16816(acc[f][g], al[f], rh + 2 * sub);
          }
        }
      }
    }
    __syncthreads();
  }

  // ---- fused RoPE + split epilogue (per-element region: 96-col tiles
  //      don't align to the 2048/2560 boundaries) ----
  const int gid = lane >> 2, tig = lane & 3;
#pragma unroll
  for (int f = 0; f < 2; f++) {
    int rowA = m0 + wm + f * 16 + gid;
#pragma unroll
    for (int g = 0; g < 6; g++) {
      int C = n0 + wn + g * 8 + tig * 2;  // even; rope pair never straddles
#pragma unroll
      for (int half = 0; half < 2; half++) {
        int s = rowA + half * 8;
        float x = acc[f][g][half * 2 + 0];
        float y = acc[f][g][half * 2 + 1];
        uint32_t hreg, lreg;
        if (C < KCOL) {  // Q: rope, bf16 hi/lo
          int i = (C & 63) >> 1;
          float cs = g_cos[s * 32 + i], sn = g_sin[s * 32 + i];
          float xr = x * cs - y * sn;
          float xi = x * sn + y * cs;
          split_pack2(xr, xi, hreg, lreg);
          size_t o = (size_t)s * (H * HD) + C;
          *(uint32_t*)(g_Qhi + o) = hreg;
          *(uint32_t*)(g_Qlo + o) = lreg;
        } else if (C < VCOL) {  // K: rope, bf16 hi/lo
          int off = C - KCOL;
          int i = (off & 63) >> 1;
          float cs = g_cos[s * 32 + i], sn = g_sin[s * 32 + i];
          float xr = x * cs - y * sn;
          float xi = x * sn + y * cs;
          split_pack2(xr, xi, hreg, lreg);
          size_t o = (size_t)s * (KVH * HD) + off;
          *(uint32_t*)(g_Khi + o) = hreg;
          *(uint32_t*)(g_Klo + o) = lreg;
        } else {  // V: fp16 single
          int off = C - VCOL;
          size_t o = (size_t)s * (KVH * HD) + off;
          *(uint32_t*)(g_V16 + o) = pack_half2(x, y);
        }
      }
    }
  }
}

// ---------------------------------------------------------------------------
// fp16 single-product GEMM (Wo).
// ---------------------------------------------------------------------------
#define FBM 128
#define FBN 128
#define FTILE_B (128 * RS * 2)
#define FSTAGE_B (2 * FTILE_B)
#define GEMM16_SMEM (2 * FSTAGE_B)

__global__ __launch_bounds__(256, 2) void gemm_fp16_kernel(
    const __half* __restrict__ A, const __half* __restrict__ B,
    float* __restrict__ C, int M, int N, int K) {
  extern __shared__ char smem[];
  const uint32_t sbase = smem_u32(smem);
  const int tid = threadIdx.x;
  const int wid = tid >> 5;
  const int lane = tid & 31;
  const int m0 = blockIdx.y * FBM;
  const int n0 = blockIdx.x * FBN;
  const int NC = K / GKC;

  const int wm = (wid & 3) * 32;
  const int wn = (wid >> 2) * 64;
  const int lrow = lane & 7;
  const int ltile = lane >> 3;
  const int a_r = (ltile & 1) * 8 + lrow;
  const int a_c = (ltile >> 1) * 8;
  const int b_r = (ltile >> 1) * 8 + lrow;
  const int b_c = (ltile & 1) * 8;

  const __half* gA = A + (size_t)m0 * K;
  const __half* gB = B + (size_t)n0 * K;

  auto load_stage = [&](int stg, int chunk) {
    const int kc = chunk * GKC;
    uint32_t sb = sbase + stg * FSTAGE_B;
#pragma unroll
    for (int i = 0; i < 2; i++) {
      int v = tid + i * 256;
      int r = v >> 2;
      int c = (v & 3) * 8;
      cp_async16(sb + (uint32_t)(r * RS + c) * 2, gA + (size_t)r * K + kc + c);
      cp_async16(sb + FTILE_B + (uint32_t)(r * RS + c) * 2,
                 gB + (size_t)r * K + kc + c);
    }
    CP_COMMIT();
  };

  float acc[2][8][4];
#pragma unroll
  for (int f = 0; f < 2; f++)
#pragma unroll
    for (int g = 0; g < 8; g++)
#pragma unroll
      for (int x = 0; x < 4; x++) acc[f][g][x] = 0.0f;

  load_stage(0, 0);

  for (int c = 0; c < NC; c++) {
    CP_WAIT0();
    __syncthreads();
    if (c + 1 < NC) load_stage((c + 1) & 1, c + 1);

    uint32_t sb = sbase + (c & 1) * FSTAGE_B;
#pragma unroll
    for (int kk = 0; kk < 2; kk++) {
      const int k0 = kk * 16;
      uint32_t af[2][4];
#pragma unroll
      for (int f = 0; f < 2; f++) {
        uint32_t ar = (uint32_t)((wm + f * 16 + a_r) * RS + k0 + a_c) * 2;
        ldsm_x4(af[f], sb + ar);
      }
#pragma unroll
      for (int g2 = 0; g2 < 4; g2++) {
        uint32_t br = (uint32_t)((wn + g2 * 16 + b_r) * RS + k0 + b_c) * 2;
        uint32_t r4[4];
        ldsm_x4(r4, sb + FTILE_B + br);
#pragma unroll
        for (int f = 0; f < 2; f++) {
          mma16816h(acc[f][g2 * 2], af[f], r4);
          mma16816h(acc[f][g2 * 2 + 1], af[f], r4 + 2);
        }
      }
    }
    __syncthreads();
  }

  const int gid = lane >> 2, tig = lane & 3;
#pragma unroll
  for (int f = 0; f < 2; f++) {
#pragma unroll
    for (int g = 0; g < 8; g++) {
      int row = m0 + wm + f * 16 + gid;
      int col = n0 + wn + g * 8 + tig * 2;
      *(float2*)(C + (size_t)row * N + col) = make_float2(acc[f][g][0], acc[f][g][1]);
      *(float2*)(C + (size_t)(row + 8) * N + col) = make_float2(acc[f][g][2], acc[f][g][3]);
    }
  }
}

// ---------------------------------------------------------------------------
// Tensor-core flash attention. QK bf16x3, PV fp16. 2 CTAs/SM forced.
// ---------------------------------------------------------------------------
#define ABQ 128
#define ABKV 64
#define ARS 72
#define Q_ELEMS (ABQ * ARS)
#define KV_TILE (ABKV * ARS)
#define KV_STAGE (3 * KV_TILE)
#define ATT_SMEM ((2 * Q_ELEMS + 2 * KV_STAGE) * 2)

__global__ __launch_bounds__(256, 2) void attn_mma_kernel(
    const __nv_bfloat16* __restrict__ Qhi, const __nv_bfloat16* __restrict__ Qlo,
    const __nv_bfloat16* __restrict__ Khi, const __nv_bfloat16* __restrict__ Klo,
    const __half* __restrict__ V16, __half* __restrict__ O16) {
  extern __shared__ char sbuf[];
  const uint32_t sbase = smem_u32(sbuf);
  const int tid = threadIdx.x;
  const int wid = tid >> 5;
  const int lane = tid & 31;
  const int h = blockIdx.x;
  const int kvh = h / NREP;
  const int q0 = ((int)gridDim.y - 1 - (int)blockIdx.y) * ABQ;
  const int wm = wid * 16;

  const int lrow = lane & 7;
  const int ltile = lane >> 3;
  const int a_r = (ltile & 1) * 8 + lrow;
  const int a_c = (ltile >> 1) * 8;
  const int b_r = (ltile >> 1) * 8 + lrow;
  const int b_c = (ltile & 1) * 8;
  const int gid = lane >> 2, tig = lane & 3;

  const uint32_t qhi_s = sbase;
  const uint32_t qlo_s = sbase + Q_ELEMS * 2;

#pragma unroll
  for (int i = 0; i < 4; i++) {
    int v = tid + i * 256;
    int r = v >> 3, c = v & 7;
    size_t g = (size_t)(q0 + r) * (H * HD) + h * HD + c * 8;
    uint32_t so = (uint32_t)(r * ARS + c * 8) * 2;
    cp_async16(qhi_s + so, Qhi + g);
    cp_async16(qlo_s + so, Qlo + g);
  }

  auto load_kv = [&](int stg, int kv0) {
    uint32_t base = sbase + (2 * Q_ELEMS + stg * KV_STAGE) * 2;
#pragma unroll
    for (int i = 0; i < 2; i++) {
      int v = tid + i * 256;
      int r = v >> 3, c = v & 7;
      size_t g = (size_t)(kv0 + r) * (KVH * HD) + kvh * HD + c * 8;
      uint32_t so = (uint32_t)(r * ARS + c * 8) * 2;
      cp_async16(base + 0 * KV_TILE * 2 + so, Khi + g);
      cp_async16(base + 1 * KV_TILE * 2 + so, Klo + g);
      cp_async16(base + 2 * KV_TILE * 2 + so, V16 + g);
    }
    CP_COMMIT();
  };

  load_kv(0, 0);

  const int ntiles = (q0 + ABQ) / ABKV;
  float m_[2] = {-1e30f, -1e30f};
  float l_[2] = {0.0f, 0.0f};
  float o[8][4];
#pragma unroll
  for (int nf = 0; nf < 8; nf++)
#pragma unroll
    for (int j = 0; j < 4; j++) o[nf][j] = 0.0f;

  const float SCL = 0.18033688011112042f;
  const int row0 = q0 + wm + gid;

  for (int t = 0; t < ntiles; t++) {
    const int kv0 = t * ABKV;
    CP_WAIT0();
    __syncthreads();
    if (t + 1 < ntiles) load_kv((t + 1) & 1, kv0 + ABKV);

    const uint32_t kvb = sbase + (2 * Q_ELEMS + (t & 1) * KV_STAGE) * 2;

    float sc[8][4];
#pragma unroll
    for (int nf = 0; nf < 8; nf++)
#pragma unroll
      for (int j = 0; j < 4; j++) sc[nf][j] = 0.0f;

#pragma unroll
    for (int ks = 0; ks < 4; ks++) {
      const int k0 = ks * 16;
      uint32_t ah[4], al[4];
      uint32_t ar = (uint32_t)((wm + a_r) * ARS + k0 + a_c) * 2;
      ldsm_x4(ah, qhi_s + ar);
      ldsm_x4(al, qlo_s + ar);
#pragma unroll
      for (int ng = 0; ng < 4; ng++) {
        uint32_t br = kvb + (uint32_t)((ng * 16 + b_r) * ARS + k0 + b_c) * 2;
        uint32_t rh[4], rl[4];
        ldsm_x4(rh, br);
        ldsm_x4(rl, br + KV_TILE * 2);
        mma16816(sc[ng * 2], ah, rh);
        mma16816(sc[ng * 2], ah, rl);
        mma16816(sc[ng * 2], al, rh);
        mma16816(sc[ng * 2 + 1], ah, rh + 2);
        mma16816(sc[ng * 2 + 1], ah, rl + 2);
        mma16816(sc[ng * 2 + 1], al, rh + 2);
      }
    }

    const bool nomask = (kv0 + ABKV - 1 <= q0 + wm);
    if (nomask) {
#pragma unroll
      for (int nf = 0; nf < 8; nf++)
#pragma unroll
        for (int j = 0; j < 4; j++) sc[nf][j] *= SCL;
    } else {
#pragma unroll
      for (int nf = 0; nf < 8; nf++) {
        int col = kv0 + nf * 8 + tig * 2;
#pragma unroll
        for (int j = 0; j < 4; j++) {
          int cc = col + (j & 1);
          int rr = row0 + ((j >> 1) << 3);
          sc[nf][j] = (cc <= rr) ? sc[nf][j] * SCL : -1e30f;
        }
      }
    }

    float mx0 = -1e30f, mx1 = -1e30f;
#pragma unroll
    for (int nf = 0; nf < 8; nf++) {
      mx0 = fmaxf(mx0, fmaxf(sc[nf][0], sc[nf][1]));
      mx1 = fmaxf(mx1, fmaxf(sc[nf][2], sc[nf][3]));
    }
    mx0 = fmaxf(mx0, __shfl_xor_sync(0xffffffffu, mx0, 1));
    mx0 = fmaxf(mx0, __shfl_xor_sync(0xffffffffu, mx0, 2));
    mx1 = fmaxf(mx1, __shfl_xor_sync(0xffffffffu, mx1, 1));
    mx1 = fmaxf(mx1, __shfl_xor_sync(0xffffffffu, mx1, 2));
    float mn0 = fmaxf(m_[0], mx0);
    float mn1 = fmaxf(m_[1], mx1);
    float c0 = exp2_poly(m_[0] - mn0);
    float c1 = exp2_poly(m_[1] - mn1);
    m_[0] = mn0;
    m_[1] = mn1;

    float s0 = 0.0f, s1 = 0.0f;
#pragma unroll
    for (int nf = 0; nf < 8; nf++) {
      float p0 = exp2_poly(sc[nf][0] - mn0);
      float p1 = exp2_poly(sc[nf][1] - mn0);
      float p2 = exp2_poly(sc[nf][2] - mn1);
      float p3 = exp2_poly(sc[nf][3] - mn1);
      sc[nf][0] = p0; sc[nf][1] = p1; sc[nf][2] = p2; sc[nf][3] = p3;
      s0 += p0 + p1;
      s1 += p2 + p3;
    }
    l_[0] = l_[0] * c0 + s0;
    l_[1] = l_[1] * c1 + s1;
#pragma unroll
    for (int nf = 0; nf < 8; nf++) {
      o[nf][0] *= c0; o[nf][1] *= c0;
      o[nf][2] *= c1; o[nf][3] *= c1;
    }

    const uint32_t vb = kvb + 2 * KV_TILE * 2;
#pragma unroll
    for (int ks = 0; ks < 4; ks++) {
      uint32_t p16[4];
      p16[0] = pack_half2(sc[2 * ks][0], sc[2 * ks][1]);
      p16[1] = pack_half2(sc[2 * ks][2], sc[2 * ks][3]);
      p16[2] = pack_half2(sc[2 * ks + 1][0], sc[2 * ks + 1][1]);
      p16[3] = pack_half2(sc[2 * ks + 1][2], sc[2 * ks + 1][3]);
#pragma unroll
      for (int dg = 0; dg < 4; dg++) {
        uint32_t va = vb + (uint32_t)((ks * 16 + a_r) * ARS + dg * 16 + a_c) * 2;
        uint32_t vh[4];
        ldsm_x4_trans(vh, va);
        mma16816h(o[dg * 2], p16, vh);
        mma16816h(o[dg * 2 + 1], p16, vh + 2);
      }
    }
  }

  l_[0] += __shfl_xor_sync(0xffffffffu, l_[0], 1);
  l_[0] += __shfl_xor_sync(0xffffffffu, l_[0], 2);
  l_[1] += __shfl_xor_sync(0xffffffffu, l_[1], 1);
  l_[1] += __shfl_xor_sync(0xffffffffu, l_[1], 2);
  float inv0 = 1.0f / l_[0];
  float inv1 = 1.0f / l_[1];

#pragma unroll
  for (int nf = 0; nf < 8; nf++) {
    int col = h * HD + nf * 8 + tig * 2;
    *(__half2*)(O16 + (size_t)row0 * (H * HD) + col) =
        __floats2half2_rn(o[nf][0] * inv0, o[nf][1] * inv0);
    *(__half2*)(O16 + (size_t)(row0 + 8) * (H * HD) + col) =
        __floats2half2_rn(o[nf][2] * inv1, o[nf][3] * inv1);
  }
}

// ---------------------------------------------------------------------------
// Launch
// ---------------------------------------------------------------------------
extern "C" void kernel_launch(void* const* d_in, const int* in_sizes, int n_in,
                              void* d_out, int out_size) {
  const float* hs = (const float*)d_in[0];
  const float* Wq = (const float*)d_in[1];
  const float* Wk = (const float*)d_in[2];
  const float* Wv = (const float*)d_in[3];
  const float* Wo = (const float*)d_in[4];
  float* out = (float*)d_out;

  __nv_bfloat16 *Xhi, *Xlo, *WqkvThi, *WqkvTlo;
  __nv_bfloat16 *Qhi, *Qlo, *Khi, *Klo;
  __half *V16, *O16, *WoT16;
  cudaGetSymbolAddress((void**)&Xhi, g_Xhi);
  cudaGetSymbolAddress((void**)&Xlo, g_Xlo);
  cudaGetSymbolAddress((void**)&WqkvThi, g_WqkvThi);
  cudaGetSymbolAddress((void**)&WqkvTlo, g_WqkvTlo);
  cudaGetSymbolAddress((void**)&Qhi, g_Qhi);
  cudaGetSymbolAddress((void**)&Qlo, g_Qlo);
  cudaGetSymbolAddress((void**)&Khi, g_Khi);
  cudaGetSymbolAddress((void**)&Klo, g_Klo);
  cudaGetSymbolAddress((void**)&V16, g_V16);
  cudaGetSymbolAddress((void**)&O16, g_O16);
  cudaGetSymbolAddress((void**)&WoT16, g_WoT16);

  // 1. split activations + rope table
  {
    int n4 = S * D / 4;
    split_kernel<<<(n4 + 255) / 256, 256>>>(hs, Xhi, Xlo, n4);
    rope_table_kernel<<<(S * 32 + 255) / 256, 256>>>();
  }

  // 2. transpose weights
  {
    dim3 blk(32, 8);
    transpose_split_kernel<<<dim3(D / 32, D / 32), blk>>>(Wq, WqkvThi, WqkvTlo, D, D);
    transpose_split_kernel<<<dim3(512 / 32, D / 32), blk>>>(
        Wk, WqkvThi + (size_t)KCOL * D, WqkvTlo + (size_t)KCOL * D, 512, D);
    transpose_split_kernel<<<dim3(512 / 32, D / 32), blk>>>(
        Wv, WqkvThi + (size_t)VCOL * D, WqkvTlo + (size_t)VCOL * D, 512, D);
    transpose_half_kernel<<<dim3(D / 32, D / 32), blk>>>(Wo, WoT16, D, D);
  }

  cudaFuncSetAttribute(gemm_qkv_rope_kernel,
                       cudaFuncAttributeMaxDynamicSharedMemorySize, GEMM_SMEM);
  cudaFuncSetAttribute(gemm_fp16_kernel,
                       cudaFuncAttributeMaxDynamicSharedMemorySize, GEMM16_SMEM);

  // 3. QKV projection + fused RoPE/split (512 CTAs, 86% wave util)
  {
    dim3 grid(QKV_N / GBN, S / GBM);  // 32 x 16
    gemm_qkv_rope_kernel<<<grid, 256, GEMM_SMEM>>>(Xhi, Xlo, WqkvThi, WqkvTlo);
  }

  // 4. tensor-core flash attention (QK bf16x3, PV fp16) -> fp16 O
  {
    cudaFuncSetAttribute(attn_mma_kernel,
                         cudaFuncAttributeMaxDynamicSharedMemorySize, ATT_SMEM);
    dim3 grid(H, S / ABQ);
    attn_mma_kernel<<<grid, 256, ATT_SMEM>>>(Qhi, Qlo, Khi, Klo, V16, O16);
  }

  // 5. output projection (fp16)
  {
    dim3 grid(D / FBN, S / FBM);
    gemm_fp16_kernel<<<grid, 256, GEMM16_SMEM>>>(O16, WoT16, out, S, D, D);
  }
}

// round 10
// speedup vs baseline: 1.2171x; 1.0353x over previous
#include <cuda_runtime.h>
#include <cuda_bf16.h>
#include <cuda_fp16.h>
#include <cstdint>
#include <math.h>

#define S 2048
#define D 2048
#define H 32
#define KVH 8
#define HD 64
#define NREP (H / KVH)
#define QKV_N 3072
#define KCOL 2048
#define VCOL 2560

// ---------------------------------------------------------------------------
// Device-global scratch
// ---------------------------------------------------------------------------
__device__ __nv_bfloat16 g_Xhi[S * D], g_Xlo[S * D];
__device__ __nv_bfloat16 g_WqkvThi[QKV_N * D], g_WqkvTlo[QKV_N * D];
__device__ __half g_Q16[S * H * HD];                          // Q: fp16 single
__device__ __half g_K16hi[S * KVH * HD], g_K16lo[S * KVH * HD];  // K: fp16 hi/lo
__device__ __half g_V16[S * KVH * HD];
__device__ __half g_O16[S * D];
__device__ __half g_WoT16[D * D];
__device__ float g_cos[S * 32], g_sin[S * 32];

// ---------------------------------------------------------------------------
// Helpers
// ---------------------------------------------------------------------------
__device__ __forceinline__ uint32_t smem_u32(const void* p) {
  uint32_t a;
  asm("{ .reg .u64 t; cvta.to.shared.u64 t, %1; cvt.u32.u64 %0, t; }"
      : "=r"(a) : "l"(p));
  return a;
}

__device__ __forceinline__ void ldsm_x4(uint32_t* r, uint32_t addr) {
  asm volatile(
      "ldmatrix.sync.aligned.m8n8.x4.shared.b16 {%0,%1,%2,%3}, [%4];"
      : "=r"(r[0]), "=r"(r[1]), "=r"(r[2]), "=r"(r[3]) : "r"(addr));
}

__device__ __forceinline__ void ldsm_x4_trans(uint32_t* r, uint32_t addr) {
  asm volatile(
      "ldmatrix.sync.aligned.m8n8.x4.trans.shared.b16 {%0,%1,%2,%3}, [%4];"
      : "=r"(r[0]), "=r"(r[1]), "=r"(r[2]), "=r"(r[3]) : "r"(addr));
}

__device__ __forceinline__ void mma16816(float* d, const uint32_t* a,
                                         const uint32_t* b) {
  asm volatile(
      "mma.sync.aligned.m16n8k16.row.col.f32.bf16.bf16.f32 "
      "{%0,%1,%2,%3}, {%4,%5,%6,%7}, {%8,%9}, {%0,%1,%2,%3};"
      : "+f"(d[0]), "+f"(d[1]), "+f"(d[2]), "+f"(d[3])
      : "r"(a[0]), "r"(a[1]), "r"(a[2]), "r"(a[3]), "r"(b[0]), "r"(b[1]));
}

__device__ __forceinline__ void mma16816h(float* d, const uint32_t* a,
                                          const uint32_t* b) {
  asm volatile(
      "mma.sync.aligned.m16n8k16.row.col.f32.f16.f16.f32 "
      "{%0,%1,%2,%3}, {%4,%5,%6,%7}, {%8,%9}, {%0,%1,%2,%3};"
      : "+f"(d[0]), "+f"(d[1]), "+f"(d[2]), "+f"(d[3])
      : "r"(a[0]), "r"(a[1]), "r"(a[2]), "r"(a[3]), "r"(b[0]), "r"(b[1]));
}

__device__ __forceinline__ void cp_async16(uint32_t saddr, const void* gptr) {
  asm volatile("cp.async.cg.shared.global [%0], [%1], 16;" ::
                   "r"(saddr), "l"(__cvta_generic_to_global(gptr)));
}
#define CP_COMMIT() asm volatile("cp.async.commit_group;" ::: "memory")
#define CP_WAIT0() asm volatile("cp.async.wait_group 0;" ::: "memory")

__device__ __forceinline__ float exp2_poly(float x) {
  x = fmaxf(x, -126.0f);
  float fl = floorf(x);
  float f = x - fl;
  float p = 1.5403530393e-4f;
  p = fmaf(p, f, 1.3333558146e-3f);
  p = fmaf(p, f, 9.6181291076e-3f);
  p = fmaf(p, f, 5.5504108665e-2f);
  p = fmaf(p, f, 2.4022650696e-1f);
  p = fmaf(p, f, 6.9314718056e-1f);
  p = fmaf(p, f, 1.0f);
  return p * __int_as_float(((int)fl + 127) << 23);
}

__device__ __forceinline__ void split2(float x, __nv_bfloat16& h, __nv_bfloat16& l) {
  h = __float2bfloat16(x);
  l = __float2bfloat16(x - __bfloat162float(h));
}

__device__ __forceinline__ uint32_t pack_half2(float x, float y) {
  __half2 v = __floats2half2_rn(x, y);
  return *reinterpret_cast<uint32_t*>(&v);
}

// split (x,y) into fp16 hi pair + fp16 residual pair
__device__ __forceinline__ void split_pack2h(float x, float y, uint32_t& h,
                                             uint32_t& l) {
  __half hx = __float2half_rn(x), hy = __float2half_rn(y);
  float xr = x - __half2float(hx), yr = y - __half2float(hy);
  __half2 hb = __halves2half2(hx, hy);
  __half2 lb = __floats2half2_rn(xr, yr);
  h = *reinterpret_cast<uint32_t*>(&hb);
  l = *reinterpret_cast<uint32_t*>(&lb);
}

// ---------------------------------------------------------------------------
// Preprocessing
// ---------------------------------------------------------------------------
__global__ void split_kernel(const float* __restrict__ in,
                             __nv_bfloat16* __restrict__ hi,
                             __nv_bfloat16* __restrict__ lo, int n4) {
  int i = blockIdx.x * blockDim.x + threadIdx.x;
  if (i >= n4) return;
  float4 v = ((const float4*)in)[i];
  __nv_bfloat16 h0, l0, h1, l1, h2, l2, h3, l3;
  split2(v.x, h0, l0); split2(v.y, h1, l1);
  split2(v.z, h2, l2); split2(v.w, h3, l3);
  __nv_bfloat162* hp = (__nv_bfloat162*)hi;
  __nv_bfloat162* lp = (__nv_bfloat162*)lo;
  hp[i * 2 + 0] = __halves2bfloat162(h0, h1);
  hp[i * 2 + 1] = __halves2bfloat162(h2, h3);
  lp[i * 2 + 0] = __halves2bfloat162(l0, l1);
  lp[i * 2 + 1] = __halves2bfloat162(l2, l3);
}

__global__ void rope_table_kernel() {
  int idx = blockIdx.x * blockDim.x + threadIdx.x;
  if (idx >= S * 32) return;
  int s = idx >> 5, i = idx & 31;
  float inv = 1.0f / powf(10000.0f, (2.0f * i) / (float)HD);
  float ang = (float)s * inv;
  g_cos[idx] = cosf(ang);
  g_sin[idx] = sinf(ang);
}

// Fused transpose of all 4 weight matrices (one launch).
// blocks [0,4096): Wq -> WqkvT[0:2048]     bf16 hi/lo
// blocks [4096,5120): Wk -> WqkvT[2048:2560] bf16 hi/lo
// blocks [5120,6144): Wv -> WqkvT[2560:3072] bf16 hi/lo
// blocks [6144,10240): Wo -> WoT16           fp16
__global__ void transpose_all_kernel(const float* __restrict__ Wq,
                                     const float* __restrict__ Wk,
                                     const float* __restrict__ Wv,
                                     const float* __restrict__ Wo) {
  __shared__ float t[32][33];
  int bid = blockIdx.x;
  const float* W;
  __nv_bfloat16 *Thi = nullptr, *Tlo = nullptr;
  __half* Th = nullptr;
  int N, n0, k0;
  if (bid < 4096) {
    W = Wq; Thi = g_WqkvThi; Tlo = g_WqkvTlo; N = 2048;
    n0 = (bid & 63) * 32; k0 = (bid >> 6) * 32;
  } else if (bid < 5120) {
    int b = bid - 4096;
    W = Wk; Thi = g_WqkvThi + (size_t)KCOL * D; Tlo = g_WqkvTlo + (size_t)KCOL * D;
    N = 512; n0 = (b & 15) * 32; k0 = (b >> 4) * 32;
  } else if (bid < 6144) {
    int b = bid - 5120;
    W = Wv; Thi = g_WqkvThi + (size_t)VCOL * D; Tlo = g_WqkvTlo + (size_t)VCOL * D;
    N = 512; n0 = (b & 15) * 32; k0 = (b >> 4) * 32;
  } else {
    int b = bid - 6144;
    W = Wo; Th = g_WoT16; N = 2048;
    n0 = (b & 63) * 32; k0 = (b >> 6) * 32;
  }
  int tx = threadIdx.x, ty = threadIdx.y;
#pragma unroll
  for (int i = 0; i < 4; i++)
    t[ty + i * 8][tx] = W[(size_t)(k0 + ty + i * 8) * N + n0 + tx];
  __syncthreads();
  if (Th) {
#pragma unroll
    for (int i = 0; i < 4; i++) {
      int n = ty + i * 8;
      Th[(size_t)(n0 + n) * D + k0 + tx] = __float2half(t[tx][n]);
    }
  } else {
#pragma unroll
    for (int i = 0; i < 4; i++) {
      int n = ty + i * 8;
      float x = t[tx][n];
      __nv_bfloat16 h, l;
      split2(x, h, l);
      size_t o = (size_t)(n0 + n) * D + k0 + tx;
      Thi[o] = h;
      Tlo[o] = l;
    }
  }
}

// ---------------------------------------------------------------------------
// QKV GEMM (bf16x3) + fused RoPE/split epilogue.
// Q -> fp16 single; K -> fp16 hi/lo; V -> fp16 single.
// ---------------------------------------------------------------------------
#define GBM 128
#define GBN 96
#define GKC 32
#define RS 40
#define A_TILE (128 * RS * 2)
#define B_TILE (96 * RS * 2)
#define QS_AH 0
#define QS_AL A_TILE
#define QS_BH (2 * A_TILE)
#define QS_BL (2 * A_TILE + B_TILE)
#define STAGE_B (2 * A_TILE + 2 * B_TILE)
#define GEMM_SMEM (2 * STAGE_B)

__global__ __launch_bounds__(256, 2) void gemm_qkv_rope_kernel(
    const __nv_bfloat16* __restrict__ Ahi, const __nv_bfloat16* __restrict__ Alo,
    const __nv_bfloat16* __restrict__ Bhi, const __nv_bfloat16* __restrict__ Blo) {
  extern __shared__ char smem[];
  const uint32_t sbase = smem_u32(smem);
  const int tid = threadIdx.x;
  const int wid = tid >> 5;
  const int lane = tid & 31;
  const int m0 = blockIdx.y * GBM;
  const int n0 = blockIdx.x * GBN;
  const int NC = D / GKC;

  const int wm = (wid & 3) * 32;
  const int wn = (wid >> 2) * 48;
  const int lrow = lane & 7;
  const int ltile = lane >> 3;
  const int a_r = (ltile & 1) * 8 + lrow;
  const int a_c = (ltile >> 1) * 8;
  const int b_r = (ltile >> 1) * 8 + lrow;
  const int b_c = (ltile & 1) * 8;

  const __nv_bfloat16* gA[2] = {Ahi + (size_t)m0 * D, Alo + (size_t)m0 * D};
  const __nv_bfloat16* gB[2] = {Bhi + (size_t)n0 * D, Blo + (size_t)n0 * D};

  auto load_stage = [&](int stg, int chunk) {
    const int kc = chunk * GKC;
    uint32_t sb = sbase + stg * STAGE_B;
#pragma unroll
    for (int i = 0; i < 2; i++) {
      int v = tid + i * 256;
      int r = v >> 2;
      int c = (v & 3) * 8;
      size_t g = (size_t)r * D + kc + c;
      uint32_t so = (uint32_t)(r * RS + c) * 2;
      cp_async16(sb + QS_AH + so, gA[0] + g);
      cp_async16(sb + QS_AL + so, gA[1] + g);
    }
    for (int v = tid; v < 384; v += 256) {
      int r = v >> 2;
      int c = (v & 3) * 8;
      size_t g = (size_t)r * D + kc + c;
      uint32_t so = (uint32_t)(r * RS + c) * 2;
      cp_async16(sb + QS_BH + so, gB[0] + g);
      cp_async16(sb + QS_BL + so, gB[1] + g);
    }
    CP_COMMIT();
  };

  float acc[2][6][4];
#pragma unroll
  for (int f = 0; f < 2; f++)
#pragma unroll
    for (int g = 0; g < 6; g++)
#pragma unroll
      for (int x = 0; x < 4; x++) acc[f][g][x] = 0.0f;

  load_stage(0, 0);

  for (int c = 0; c < NC; c++) {
    CP_WAIT0();
    __syncthreads();
    if (c + 1 < NC) load_stage((c + 1) & 1, c + 1);

    uint32_t sb = sbase + (c & 1) * STAGE_B;
#pragma unroll
    for (int kk = 0; kk < 2; kk++) {
      const int k0 = kk * 16;
      uint32_t ah[2][4], al[2][4];
#pragma unroll
      for (int f = 0; f < 2; f++) {
        uint32_t ar = (uint32_t)((wm + f * 16 + a_r) * RS + k0 + a_c) * 2;
        ldsm_x4(ah[f], sb + QS_AH + ar);
        ldsm_x4(al[f], sb + QS_AL + ar);
      }
#pragma unroll
      for (int g2 = 0; g2 < 3; g2++) {
        uint32_t br = (uint32_t)((wn + g2 * 16 + b_r) * RS + k0 + b_c) * 2;
        uint32_t rh[4], rl[4];
        ldsm_x4(rh, sb + QS_BH + br);
        ldsm_x4(rl, sb + QS_BL + br);
#pragma unroll
        for (int sub = 0; sub < 2; sub++) {
          int g = g2 * 2 + sub;
#pragma unroll
          for (int f = 0; f < 2; f++) {
            mma16816(acc[f][g], ah[f], rh + 2 * sub);
            mma16816(acc[f][g], ah[f], rl + 2 * sub);
            mma16816(acc[f][g], al[f], rh + 2 * sub);
          }
        }
      }
    }
    __syncthreads();
  }

  // ---- fused RoPE + split epilogue ----
  const int gid = lane >> 2, tig = lane & 3;
#pragma unroll
  for (int f = 0; f < 2; f++) {
    int rowA = m0 + wm + f * 16 + gid;
#pragma unroll
    for (int g = 0; g < 6; g++) {
      int C = n0 + wn + g * 8 + tig * 2;
#pragma unroll
      for (int half = 0; half < 2; half++) {
        int s = rowA + half * 8;
        float x = acc[f][g][half * 2 + 0];
        float y = acc[f][g][half * 2 + 1];
        if (C < KCOL) {  // Q: rope -> fp16 single
          int i = (C & 63) >> 1;
          float cs = g_cos[s * 32 + i], sn = g_sin[s * 32 + i];
          float xr = x * cs - y * sn;
          float xi = x * sn + y * cs;
          size_t o = (size_t)s * (H * HD) + C;
          *(uint32_t*)(g_Q16 + o) = pack_half2(xr, xi);
        } else if (C < VCOL) {  // K: rope -> fp16 hi/lo
          int off = C - KCOL;
          int i = (off & 63) >> 1;
          float cs = g_cos[s * 32 + i], sn = g_sin[s * 32 + i];
          float xr = x * cs - y * sn;
          float xi = x * sn + y * cs;
          uint32_t hreg, lreg;
          split_pack2h(xr, xi, hreg, lreg);
          size_t o = (size_t)s * (KVH * HD) + off;
          *(uint32_t*)(g_K16hi + o) = hreg;
          *(uint32_t*)(g_K16lo + o) = lreg;
        } else {  // V: fp16 single
          int off = C - VCOL;
          size_t o = (size_t)s * (KVH * HD) + off;
          *(uint32_t*)(g_V16 + o) = pack_half2(x, y);
        }
      }
    }
  }
}

// ---------------------------------------------------------------------------
// fp16 single-product GEMM (Wo).
// ---------------------------------------------------------------------------
#define FBM 128
#define FBN 128
#define FTILE_B (128 * RS * 2)
#define FSTAGE_B (2 * FTILE_B)
#define GEMM16_SMEM (2 * FSTAGE_B)

__global__ __launch_bounds__(256, 2) void gemm_fp16_kernel(
    const __half* __restrict__ A, const __half* __restrict__ B,
    float* __restrict__ C, int M, int N, int K) {
  extern __shared__ char smem[];
  const uint32_t sbase = smem_u32(smem);
  const int tid = threadIdx.x;
  const int wid = tid >> 5;
  const int lane = tid & 31;
  const int m0 = blockIdx.y * FBM;
  const int n0 = blockIdx.x * FBN;
  const int NC = K / GKC;

  const int wm = (wid & 3) * 32;
  const int wn = (wid >> 2) * 64;
  const int lrow = lane & 7;
  const int ltile = lane >> 3;
  const int a_r = (ltile & 1) * 8 + lrow;
  const int a_c = (ltile >> 1) * 8;
  const int b_r = (ltile >> 1) * 8 + lrow;
  const int b_c = (ltile & 1) * 8;

  const __half* gA = A + (size_t)m0 * K;
  const __half* gB = B + (size_t)n0 * K;

  auto load_stage = [&](int stg, int chunk) {
    const int kc = chunk * GKC;
    uint32_t sb = sbase + stg * FSTAGE_B;
#pragma unroll
    for (int i = 0; i < 2; i++) {
      int v = tid + i * 256;
      int r = v >> 2;
      int c = (v & 3) * 8;
      cp_async16(sb + (uint32_t)(r * RS + c) * 2, gA + (size_t)r * K + kc + c);
      cp_async16(sb + FTILE_B + (uint32_t)(r * RS + c) * 2,
                 gB + (size_t)r * K + kc + c);
    }
    CP_COMMIT();
  };

  float acc[2][8][4];
#pragma unroll
  for (int f = 0; f < 2; f++)
#pragma unroll
    for (int g = 0; g < 8; g++)
#pragma unroll
      for (int x = 0; x < 4; x++) acc[f][g][x] = 0.0f;

  load_stage(0, 0);

  for (int c = 0; c < NC; c++) {
    CP_WAIT0();
    __syncthreads();
    if (c + 1 < NC) load_stage((c + 1) & 1, c + 1);

    uint32_t sb = sbase + (c & 1) * FSTAGE_B;
#pragma unroll
    for (int kk = 0; kk < 2; kk++) {
      const int k0 = kk * 16;
      uint32_t af[2][4];
#pragma unroll
      for (int f = 0; f < 2; f++) {
        uint32_t ar = (uint32_t)((wm + f * 16 + a_r) * RS + k0 + a_c) * 2;
        ldsm_x4(af[f], sb + ar);
      }
#pragma unroll
      for (int g2 = 0; g2 < 4; g2++) {
        uint32_t br = (uint32_t)((wn + g2 * 16 + b_r) * RS + k0 + b_c) * 2;
        uint32_t r4[4];
        ldsm_x4(r4, sb + FTILE_B + br);
#pragma unroll
        for (int f = 0; f < 2; f++) {
          mma16816h(acc[f][g2 * 2], af[f], r4);
          mma16816h(acc[f][g2 * 2 + 1], af[f], r4 + 2);
        }
      }
    }
    __syncthreads();
  }

  const int gid = lane >> 2, tig = lane & 3;
#pragma unroll
  for (int f = 0; f < 2; f++) {
#pragma unroll
    for (int g = 0; g < 8; g++) {
      int row = m0 + wm + f * 16 + gid;
      int col = n0 + wn + g * 8 + tig * 2;
      *(float2*)(C + (size_t)row * N + col) = make_float2(acc[f][g][0], acc[f][g][1]);
      *(float2*)(C + (size_t)(row + 8) * N + col) = make_float2(acc[f][g][2], acc[f][g][3]);
    }
  }
}

// ---------------------------------------------------------------------------
// Tensor-core flash attention.
// QK: fp16 1.5-split (Q single, K hi/lo; 2 mma products). PV: fp16 (1 product).
// ---------------------------------------------------------------------------
#define ABQ 128
#define ABKV 64
#define ARS 72
#define Q_ELEMS (ABQ * ARS)
#define KV_TILE (ABKV * ARS)
#define KV_STAGE (3 * KV_TILE)
#define ATT_SMEM ((Q_ELEMS + 2 * KV_STAGE) * 2)

__global__ __launch_bounds__(256, 2) void attn_mma_kernel(
    const __half* __restrict__ Q16,
    const __half* __restrict__ Khi, const __half* __restrict__ Klo,
    const __half* __restrict__ V16, __half* __restrict__ O16) {
  extern __shared__ char sbuf[];
  const uint32_t sbase = smem_u32(sbuf);
  const int tid = threadIdx.x;
  const int wid = tid >> 5;
  const int lane = tid & 31;
  const int h = blockIdx.x;
  const int kvh = h / NREP;
  const int q0 = ((int)gridDim.y - 1 - (int)blockIdx.y) * ABQ;
  const int wm = wid * 16;

  const int lrow = lane & 7;
  const int ltile = lane >> 3;
  const int a_r = (ltile & 1) * 8 + lrow;
  const int a_c = (ltile >> 1) * 8;
  const int b_r = (ltile >> 1) * 8 + lrow;
  const int b_c = (ltile & 1) * 8;
  const int gid = lane >> 2, tig = lane & 3;

  const uint32_t q_s = sbase;

  // Q tile: 128 rows x 64 halves = 1024 vec16 -> 4/thread
#pragma unroll
  for (int i = 0; i < 4; i++) {
    int v = tid + i * 256;
    int r = v >> 3, c = v & 7;
    size_t g = (size_t)(q0 + r) * (H * HD) + h * HD + c * 8;
    cp_async16(q_s + (uint32_t)(r * ARS + c * 8) * 2, Q16 + g);
  }

  auto load_kv = [&](int stg, int kv0) {
    uint32_t base = sbase + (Q_ELEMS + stg * KV_STAGE) * 2;
#pragma unroll
    for (int i = 0; i < 2; i++) {
      int v = tid + i * 256;
      int r = v >> 3, c = v & 7;
      size_t g = (size_t)(kv0 + r) * (KVH * HD) + kvh * HD + c * 8;
      uint32_t so = (uint32_t)(r * ARS + c * 8) * 2;
      cp_async16(base + 0 * KV_TILE * 2 + so, Khi + g);
      cp_async16(base + 1 * KV_TILE * 2 + so, Klo + g);
      cp_async16(base + 2 * KV_TILE * 2 + so, V16 + g);
    }
    CP_COMMIT();
  };

  load_kv(0, 0);

  const int ntiles = (q0 + ABQ) / ABKV;
  float m_[2] = {-1e30f, -1e30f};
  float l_[2] = {0.0f, 0.0f};
  float o[8][4];
#pragma unroll
  for (int nf = 0; nf < 8; nf++)
#pragma unroll
    for (int j = 0; j < 4; j++) o[nf][j] = 0.0f;

  const float SCL = 0.18033688011112042f;
  const int row0 = q0 + wm + gid;

  for (int t = 0; t < ntiles; t++) {
    const int kv0 = t * ABKV;
    CP_WAIT0();
    __syncthreads();
    if (t + 1 < ntiles) load_kv((t + 1) & 1, kv0 + ABKV);

    const uint32_t kvb = sbase + (Q_ELEMS + (t & 1) * KV_STAGE) * 2;

    float sc[8][4];
#pragma unroll
    for (int nf = 0; nf < 8; nf++)
#pragma unroll
      for (int j = 0; j < 4; j++) sc[nf][j] = 0.0f;

    // S = Q K^T : Q fp16 single, K fp16 hi/lo -> 2 products
#pragma unroll
    for (int ks = 0; ks < 4; ks++) {
      const int k0 = ks * 16;
      uint32_t qh[4];
      ldsm_x4(qh, q_s + (uint32_t)((wm + a_r) * ARS + k0 + a_c) * 2);
#pragma unroll
      for (int ng = 0; ng < 4; ng++) {
        uint32_t br = kvb + (uint32_t)((ng * 16 + b_r) * ARS + k0 + b_c) * 2;
        uint32_t rh[4], rl[4];
        ldsm_x4(rh, br);
        ldsm_x4(rl, br + KV_TILE * 2);
        mma16816h(sc[ng * 2], qh, rh);
        mma16816h(sc[ng * 2], qh, rl);
        mma16816h(sc[ng * 2 + 1], qh, rh + 2);
        mma16816h(sc[ng * 2 + 1], qh, rl + 2);
      }
    }

    const bool nomask = (kv0 + ABKV - 1 <= q0 + wm);
    if (nomask) {
#pragma unroll
      for (int nf = 0; nf < 8; nf++)
#pragma unroll
        for (int j = 0; j < 4; j++) sc[nf][j] *= SCL;
    } else {
#pragma unroll
      for (int nf = 0; nf < 8; nf++) {
        int col = kv0 + nf * 8 + tig * 2;
#pragma unroll
        for (int j = 0; j < 4; j++) {
          int cc = col + (j & 1);
          int rr = row0 + ((j >> 1) << 3);
          sc[nf][j] = (cc <= rr) ? sc[nf][j] * SCL : -1e30f;
        }
      }
    }

    float mx0 = -1e30f, mx1 = -1e30f;
#pragma unroll
    for (int nf = 0; nf < 8; nf++) {
      mx0 = fmaxf(mx0, fmaxf(sc[nf][0], sc[nf][1]));
      mx1 = fmaxf(mx1, fmaxf(sc[nf][2], sc[nf][3]));
    }
    mx0 = fmaxf(mx0, __shfl_xor_sync(0xffffffffu, mx0, 1));
    mx0 = fmaxf(mx0, __shfl_xor_sync(0xffffffffu, mx0, 2));
    mx1 = fmaxf(mx1, __shfl_xor_sync(0xffffffffu, mx1, 1));
    mx1 = fmaxf(mx1, __shfl_xor_sync(0xffffffffu, mx1, 2));
    float mn0 = fmaxf(m_[0], mx0);
    float mn1 = fmaxf(m_[1], mx1);
    float c0 = exp2_poly(m_[0] - mn0);
    float c1 = exp2_poly(m_[1] - mn1);
    m_[0] = mn0;
    m_[1] = mn1;

    float s0 = 0.0f, s1 = 0.0f;
#pragma unroll
    for (int nf = 0; nf < 8; nf++) {
      float p0 = exp2_poly(sc[nf][0] - mn0);
      float p1 = exp2_poly(sc[nf][1] - mn0);
      float p2 = exp2_poly(sc[nf][2] - mn1);
      float p3 = exp2_poly(sc[nf][3] - mn1);
      sc[nf][0] = p0; sc[nf][1] = p1; sc[nf][2] = p2; sc[nf][3] = p3;
      s0 += p0 + p1;
      s1 += p2 + p3;
    }
    l_[0] = l_[0] * c0 + s0;
    l_[1] = l_[1] * c1 + s1;
#pragma unroll
    for (int nf = 0; nf < 8; nf++) {
      o[nf][0] *= c0; o[nf][1] *= c0;
      o[nf][2] *= c1; o[nf][3] *= c1;
    }

    // O += P V (fp16 single product)
    const uint32_t vb = kvb + 2 * KV_TILE * 2;
#pragma unroll
    for (int ks = 0; ks < 4; ks++) {
      uint32_t p16[4];
      p16[0] = pack_half2(sc[2 * ks][0], sc[2 * ks][1]);
      p16[1] = pack_half2(sc[2 * ks][2], sc[2 * ks][3]);
      p16[2] = pack_half2(sc[2 * ks + 1][0], sc[2 * ks + 1][1]);
      p16[3] = pack_half2(sc[2 * ks + 1][2], sc[2 * ks + 1][3]);
#pragma unroll
      for (int dg = 0; dg < 4; dg++) {
        uint32_t va = vb + (uint32_t)((ks * 16 + a_r) * ARS + dg * 16 + a_c) * 2;
        uint32_t vh[4];
        ldsm_x4_trans(vh, va);
        mma16816h(o[dg * 2], p16, vh);
        mma16816h(o[dg * 2 + 1], p16, vh + 2);
      }
    }
  }

  l_[0] += __shfl_xor_sync(0xffffffffu, l_[0], 1);
  l_[0] += __shfl_xor_sync(0xffffffffu, l_[0], 2);
  l_[1] += __shfl_xor_sync(0xffffffffu, l_[1], 1);
  l_[1] += __shfl_xor_sync(0xffffffffu, l_[1], 2);
  float inv0 = 1.0f / l_[0];
  float inv1 = 1.0f / l_[1];

#pragma unroll
  for (int nf = 0; nf < 8; nf++) {
    int col = h * HD + nf * 8 + tig * 2;
    *(__half2*)(O16 + (size_t)row0 * (H * HD) + col) =
        __floats2half2_rn(o[nf][0] * inv0, o[nf][1] * inv0);
    *(__half2*)(O16 + (size_t)(row0 + 8) * (H * HD) + col) =
        __floats2half2_rn(o[nf][2] * inv1, o[nf][3] * inv1);
  }
}

// ---------------------------------------------------------------------------
// Launch
// ---------------------------------------------------------------------------
extern "C" void kernel_launch(void* const* d_in, const int* in_sizes, int n_in,
                              void* d_out, int out_size) {
  const float* hs = (const float*)d_in[0];
  const float* Wq = (const float*)d_in[1];
  const float* Wk = (const float*)d_in[2];
  const float* Wv = (const float*)d_in[3];
  const float* Wo = (const float*)d_in[4];
  float* out = (float*)d_out;

  __nv_bfloat16 *Xhi, *Xlo, *WqkvThi, *WqkvTlo;
  __half *Q16, *K16hi, *K16lo, *V16, *O16, *WoT16;
  cudaGetSymbolAddress((void**)&Xhi, g_Xhi);
  cudaGetSymbolAddress((void**)&Xlo, g_Xlo);
  cudaGetSymbolAddress((void**)&WqkvThi, g_WqkvThi);
  cudaGetSymbolAddress((void**)&WqkvTlo, g_WqkvTlo);
  cudaGetSymbolAddress((void**)&Q16, g_Q16);
  cudaGetSymbolAddress((void**)&K16hi, g_K16hi);
  cudaGetSymbolAddress((void**)&K16lo, g_K16lo);
  cudaGetSymbolAddress((void**)&V16, g_V16);
  cudaGetSymbolAddress((void**)&O16, g_O16);
  cudaGetSymbolAddress((void**)&WoT16, g_WoT16);

  // 1. split activations + rope table + fused weight transpose
  {
    int n4 = S * D / 4;
    split_kernel<<<(n4 + 255) / 256, 256>>>(hs, Xhi, Xlo, n4);
    rope_table_kernel<<<(S * 32 + 255) / 256, 256>>>();
    transpose_all_kernel<<<10240, dim3(32, 8)>>>(Wq, Wk, Wv, Wo);
  }

  cudaFuncSetAttribute(gemm_qkv_rope_kernel,
                       cudaFuncAttributeMaxDynamicSharedMemorySize, GEMM_SMEM);
  cudaFuncSetAttribute(gemm_fp16_kernel,
                       cudaFuncAttributeMaxDynamicSharedMemorySize, GEMM16_SMEM);

  // 2. QKV projection + fused RoPE/split
  {
    dim3 grid(QKV_N / GBN, S / GBM);  // 32 x 16
    gemm_qkv_rope_kernel<<<grid, 256, GEMM_SMEM>>>(Xhi, Xlo, WqkvThi, WqkvTlo);
  }

  // 3. tensor-core flash attention (QK fp16 1.5-split, PV fp16) -> fp16 O
  {
    cudaFuncSetAttribute(attn_mma_kernel,
                         cudaFuncAttributeMaxDynamicSharedMemorySize, ATT_SMEM);
    dim3 grid(H, S / ABQ);
    attn_mma_kernel<<<grid, 256, ATT_SMEM>>>(Q16, K16hi, K16lo, V16, O16);
  }

  // 4. output projection (fp16)
  {
    dim3 grid(D / FBN, S / FBM);
    gemm_fp16_kernel<<<grid, 256, GEMM16_SMEM>>>(O16, WoT16, out, S, D, D);
  }
}

// round 11
// speedup vs baseline: 1.2191x; 1.0017x over previous
#include <cuda_runtime.h>
#include <cuda_bf16.h>
#include <cuda_fp16.h>
#include <cstdint>
#include <math.h>

#define S 2048
#define D 2048
#define H 32
#define KVH 8
#define HD 64
#define NREP (H / KVH)
#define QKV_N 3072
#define KCOL 2048
#define VCOL 2560

// ---------------------------------------------------------------------------
// Device-global scratch
// ---------------------------------------------------------------------------
__device__ __nv_bfloat16 g_Xhi[S * D], g_Xlo[S * D];
__device__ __nv_bfloat16 g_WqkvThi[QKV_N * D], g_WqkvTlo[QKV_N * D];
__device__ __half g_Q16[S * H * HD];
__device__ __half g_K16hi[S * KVH * HD], g_K16lo[S * KVH * HD];
__device__ __half g_V16[S * KVH * HD];
__device__ __half g_O16[S * D];
__device__ __half g_WoT16[D * D];
__device__ float g_cos[S * 32], g_sin[S * 32];

// ---------------------------------------------------------------------------
// Helpers
// ---------------------------------------------------------------------------
__device__ __forceinline__ uint32_t smem_u32(const void* p) {
  uint32_t a;
  asm("{ .reg .u64 t; cvta.to.shared.u64 t, %1; cvt.u32.u64 %0, t; }"
      : "=r"(a) : "l"(p));
  return a;
}

__device__ __forceinline__ void ldsm_x4(uint32_t* r, uint32_t addr) {
  asm volatile(
      "ldmatrix.sync.aligned.m8n8.x4.shared.b16 {%0,%1,%2,%3}, [%4];"
      : "=r"(r[0]), "=r"(r[1]), "=r"(r[2]), "=r"(r[3]) : "r"(addr));
}

__device__ __forceinline__ void ldsm_x4_trans(uint32_t* r, uint32_t addr) {
  asm volatile(
      "ldmatrix.sync.aligned.m8n8.x4.trans.shared.b16 {%0,%1,%2,%3}, [%4];"
      : "=r"(r[0]), "=r"(r[1]), "=r"(r[2]), "=r"(r[3]) : "r"(addr));
}

__device__ __forceinline__ void mma16816(float* d, const uint32_t* a,
                                         const uint32_t* b) {
  asm volatile(
      "mma.sync.aligned.m16n8k16.row.col.f32.bf16.bf16.f32 "
      "{%0,%1,%2,%3}, {%4,%5,%6,%7}, {%8,%9}, {%0,%1,%2,%3};"
      : "+f"(d[0]), "+f"(d[1]), "+f"(d[2]), "+f"(d[3])
      : "r"(a[0]), "r"(a[1]), "r"(a[2]), "r"(a[3]), "r"(b[0]), "r"(b[1]));
}

__device__ __forceinline__ void mma16816h(float* d, const uint32_t* a,
                                          const uint32_t* b) {
  asm volatile(
      "mma.sync.aligned.m16n8k16.row.col.f32.f16.f16.f32 "
      "{%0,%1,%2,%3}, {%4,%5,%6,%7}, {%8,%9}, {%0,%1,%2,%3};"
      : "+f"(d[0]), "+f"(d[1]), "+f"(d[2]), "+f"(d[3])
      : "r"(a[0]), "r"(a[1]), "r"(a[2]), "r"(a[3]), "r"(b[0]), "r"(b[1]));
}

__device__ __forceinline__ void cp_async16(uint32_t saddr, const void* gptr) {
  asm volatile("cp.async.cg.shared.global [%0], [%1], 16;" ::
                   "r"(saddr), "l"(__cvta_generic_to_global(gptr)));
}
#define CP_COMMIT() asm volatile("cp.async.commit_group;" ::: "memory")
#define CP_WAIT0() asm volatile("cp.async.wait_group 0;" ::: "memory")
#define CP_WAIT1() asm volatile("cp.async.wait_group 1;" ::: "memory")

__device__ __forceinline__ float exp2_poly(float x) {
  x = fmaxf(x, -126.0f);
  float fl = floorf(x);
  float f = x - fl;
  float p = 1.5403530393e-4f;
  p = fmaf(p, f, 1.3333558146e-3f);
  p = fmaf(p, f, 9.6181291076e-3f);
  p = fmaf(p, f, 5.5504108665e-2f);
  p = fmaf(p, f, 2.4022650696e-1f);
  p = fmaf(p, f, 6.9314718056e-1f);
  p = fmaf(p, f, 1.0f);
  return p * __int_as_float(((int)fl + 127) << 23);
}

__device__ __forceinline__ void split2(float x, __nv_bfloat16& h, __nv_bfloat16& l) {
  h = __float2bfloat16(x);
  l = __float2bfloat16(x - __bfloat162float(h));
}

__device__ __forceinline__ uint32_t pack_half2(float x, float y) {
  __half2 v = __floats2half2_rn(x, y);
  return *reinterpret_cast<uint32_t*>(&v);
}

__device__ __forceinline__ void split_pack2h(float x, float y, uint32_t& h,
                                             uint32_t& l) {
  __half hx = __float2half_rn(x), hy = __float2half_rn(y);
  float xr = x - __half2float(hx), yr = y - __half2float(hy);
  __half2 hb = __halves2half2(hx, hy);
  __half2 lb = __floats2half2_rn(xr, yr);
  h = *reinterpret_cast<uint32_t*>(&hb);
  l = *reinterpret_cast<uint32_t*>(&lb);
}

// ---------------------------------------------------------------------------
// Preprocessing
// ---------------------------------------------------------------------------
__global__ void split_kernel(const float* __restrict__ in,
                             __nv_bfloat16* __restrict__ hi,
                             __nv_bfloat16* __restrict__ lo, int n4) {
  int i = blockIdx.x * blockDim.x + threadIdx.x;
  if (i >= n4) return;
  float4 v = ((const float4*)in)[i];
  __nv_bfloat16 h0, l0, h1, l1, h2, l2, h3, l3;
  split2(v.x, h0, l0); split2(v.y, h1, l1);
  split2(v.z, h2, l2); split2(v.w, h3, l3);
  __nv_bfloat162* hp = (__nv_bfloat162*)hi;
  __nv_bfloat162* lp = (__nv_bfloat162*)lo;
  hp[i * 2 + 0] = __halves2bfloat162(h0, h1);
  hp[i * 2 + 1] = __halves2bfloat162(h2, h3);
  lp[i * 2 + 0] = __halves2bfloat162(l0, l1);
  lp[i * 2 + 1] = __halves2bfloat162(l2, l3);
}

__global__ void rope_table_kernel() {
  int idx = blockIdx.x * blockDim.x + threadIdx.x;
  if (idx >= S * 32) return;
  int s = idx >> 5, i = idx & 31;
  float inv = 1.0f / powf(10000.0f, (2.0f * i) / (float)HD);
  float ang = (float)s * inv;
  g_cos[idx] = cosf(ang);
  g_sin[idx] = sinf(ang);
}

__global__ void transpose_all_kernel(const float* __restrict__ Wq,
                                     const float* __restrict__ Wk,
                                     const float* __restrict__ Wv,
                                     const float* __restrict__ Wo) {
  __shared__ float t[32][33];
  int bid = blockIdx.x;
  const float* W;
  __nv_bfloat16 *Thi = nullptr, *Tlo = nullptr;
  __half* Th = nullptr;
  int N, n0, k0;
  if (bid < 4096) {
    W = Wq; Thi = g_WqkvThi; Tlo = g_WqkvTlo; N = 2048;
    n0 = (bid & 63) * 32; k0 = (bid >> 6) * 32;
  } else if (bid < 5120) {
    int b = bid - 4096;
    W = Wk; Thi = g_WqkvThi + (size_t)KCOL * D; Tlo = g_WqkvTlo + (size_t)KCOL * D;
    N = 512; n0 = (b & 15) * 32; k0 = (b >> 4) * 32;
  } else if (bid < 6144) {
    int b = bid - 5120;
    W = Wv; Thi = g_WqkvThi + (size_t)VCOL * D; Tlo = g_WqkvTlo + (size_t)VCOL * D;
    N = 512; n0 = (b & 15) * 32; k0 = (b >> 4) * 32;
  } else {
    int b = bid - 6144;
    W = Wo; Th = g_WoT16; N = 2048;
    n0 = (b & 63) * 32; k0 = (b >> 6) * 32;
  }
  int tx = threadIdx.x, ty = threadIdx.y;
#pragma unroll
  for (int i = 0; i < 4; i++)
    t[ty + i * 8][tx] = W[(size_t)(k0 + ty + i * 8) * N + n0 + tx];
  __syncthreads();
  if (Th) {
#pragma unroll
    for (int i = 0; i < 4; i++) {
      int n = ty + i * 8;
      Th[(size_t)(n0 + n) * D + k0 + tx] = __float2half(t[tx][n]);
    }
  } else {
#pragma unroll
    for (int i = 0; i < 4; i++) {
      int n = ty + i * 8;
      float x = t[tx][n];
      __nv_bfloat16 h, l;
      split2(x, h, l);
      size_t o = (size_t)(n0 + n) * D + k0 + tx;
      Thi[o] = h;
      Tlo[o] = l;
    }
  }
}

// ---------------------------------------------------------------------------
// QKV GEMM (bf16x3) + fused RoPE/split epilogue. 3-stage cp.async pipeline.
// ---------------------------------------------------------------------------
#define GBM 128
#define GBN 96
#define GKC 32
#define RS 40
#define A_TILE (128 * RS * 2)
#define B_TILE (96 * RS * 2)
#define QS_AH 0
#define QS_AL A_TILE
#define QS_BH (2 * A_TILE)
#define QS_BL (2 * A_TILE + B_TILE)
#define STAGE_B (2 * A_TILE + 2 * B_TILE)  // 35840 B
#define GEMM_SMEM (3 * STAGE_B)            // 107520 B

__global__ __launch_bounds__(256, 2) void gemm_qkv_rope_kernel(
    const __nv_bfloat16* __restrict__ Ahi, const __nv_bfloat16* __restrict__ Alo,
    const __nv_bfloat16* __restrict__ Bhi, const __nv_bfloat16* __restrict__ Blo) {
  extern __shared__ char smem[];
  const uint32_t sbase = smem_u32(smem);
  const int tid = threadIdx.x;
  const int wid = tid >> 5;
  const int lane = tid & 31;
  const int m0 = blockIdx.y * GBM;
  const int n0 = blockIdx.x * GBN;
  const int NC = D / GKC;  // 64

  const int wm = (wid & 3) * 32;
  const int wn = (wid >> 2) * 48;
  const int lrow = lane & 7;
  const int ltile = lane >> 3;
  const int a_r = (ltile & 1) * 8 + lrow;
  const int a_c = (ltile >> 1) * 8;
  const int b_r = (ltile >> 1) * 8 + lrow;
  const int b_c = (ltile & 1) * 8;

  const __nv_bfloat16* gA[2] = {Ahi + (size_t)m0 * D, Alo + (size_t)m0 * D};
  const __nv_bfloat16* gB[2] = {Bhi + (size_t)n0 * D, Blo + (size_t)n0 * D};

  auto load_stage = [&](int stg, int chunk) {
    const int kc = chunk * GKC;
    uint32_t sb = sbase + stg * STAGE_B;
#pragma unroll
    for (int i = 0; i < 2; i++) {
      int v = tid + i * 256;
      int r = v >> 2;
      int c = (v & 3) * 8;
      size_t g = (size_t)r * D + kc + c;
      uint32_t so = (uint32_t)(r * RS + c) * 2;
      cp_async16(sb + QS_AH + so, gA[0] + g);
      cp_async16(sb + QS_AL + so, gA[1] + g);
    }
    for (int v = tid; v < 384; v += 256) {
      int r = v >> 2;
      int c = (v & 3) * 8;
      size_t g = (size_t)r * D + kc + c;
      uint32_t so = (uint32_t)(r * RS + c) * 2;
      cp_async16(sb + QS_BH + so, gB[0] + g);
      cp_async16(sb + QS_BL + so, gB[1] + g);
    }
    CP_COMMIT();
  };

  float acc[2][6][4];
#pragma unroll
  for (int f = 0; f < 2; f++)
#pragma unroll
    for (int g = 0; g < 6; g++)
#pragma unroll
      for (int x = 0; x < 4; x++) acc[f][g][x] = 0.0f;

  load_stage(0, 0);
  load_stage(1, 1);

  for (int c = 0; c < NC; c++) {
    if (c + 1 < NC) { CP_WAIT1(); } else { CP_WAIT0(); }
    __syncthreads();
    if (c + 2 < NC) load_stage((c + 2) % 3, c + 2);

    uint32_t sb = sbase + (c % 3) * STAGE_B;
#pragma unroll
    for (int kk = 0; kk < 2; kk++) {
      const int k0 = kk * 16;
      uint32_t ah[2][4], al[2][4];
#pragma unroll
      for (int f = 0; f < 2; f++) {
        uint32_t ar = (uint32_t)((wm + f * 16 + a_r) * RS + k0 + a_c) * 2;
        ldsm_x4(ah[f], sb + QS_AH + ar);
        ldsm_x4(al[f], sb + QS_AL + ar);
      }
#pragma unroll
      for (int g2 = 0; g2 < 3; g2++) {
        uint32_t br = (uint32_t)((wn + g2 * 16 + b_r) * RS + k0 + b_c) * 2;
        uint32_t rh[4], rl[4];
        ldsm_x4(rh, sb + QS_BH + br);
        ldsm_x4(rl, sb + QS_BL + br);
#pragma unroll
        for (int sub = 0; sub < 2; sub++) {
          int g = g2 * 2 + sub;
#pragma unroll
          for (int f = 0; f < 2; f++) {
            mma16816(acc[f][g], ah[f], rh + 2 * sub);
            mma16816(acc[f][g], ah[f], rl + 2 * sub);
            mma16816(acc[f][g], al[f], rh + 2 * sub);
          }
        }
      }
    }
  }

  // ---- fused RoPE + split epilogue ----
  const int gid = lane >> 2, tig = lane & 3;
#pragma unroll
  for (int f = 0; f < 2; f++) {
    int rowA = m0 + wm + f * 16 + gid;
#pragma unroll
    for (int g = 0; g < 6; g++) {
      int C = n0 + wn + g * 8 + tig * 2;
#pragma unroll
      for (int half = 0; half < 2; half++) {
        int s = rowA + half * 8;
        float x = acc[f][g][half * 2 + 0];
        float y = acc[f][g][half * 2 + 1];
        if (C < KCOL) {  // Q: rope -> fp16 single
          int i = (C & 63) >> 1;
          float cs = g_cos[s * 32 + i], sn = g_sin[s * 32 + i];
          float xr = x * cs - y * sn;
          float xi = x * sn + y * cs;
          size_t o = (size_t)s * (H * HD) + C;
          *(uint32_t*)(g_Q16 + o) = pack_half2(xr, xi);
        } else if (C < VCOL) {  // K: rope -> fp16 hi/lo
          int off = C - KCOL;
          int i = (off & 63) >> 1;
          float cs = g_cos[s * 32 + i], sn = g_sin[s * 32 + i];
          float xr = x * cs - y * sn;
          float xi = x * sn + y * cs;
          uint32_t hreg, lreg;
          split_pack2h(xr, xi, hreg, lreg);
          size_t o = (size_t)s * (KVH * HD) + off;
          *(uint32_t*)(g_K16hi + o) = hreg;
          *(uint32_t*)(g_K16lo + o) = lreg;
        } else {  // V: fp16 single
          int off = C - VCOL;
          size_t o = (size_t)s * (KVH * HD) + off;
          *(uint32_t*)(g_V16 + o) = pack_half2(x, y);
        }
      }
    }
  }
}

// ---------------------------------------------------------------------------
// fp16 single-product GEMM (Wo). 3-stage pipeline.
// ---------------------------------------------------------------------------
#define FBM 128
#define FBN 128
#define FTILE_B (128 * RS * 2)
#define FSTAGE_B (2 * FTILE_B)        // 20480 B
#define GEMM16_SMEM (3 * FSTAGE_B)    // 61440 B

__global__ __launch_bounds__(256, 2) void gemm_fp16_kernel(
    const __half* __restrict__ A, const __half* __restrict__ B,
    float* __restrict__ C, int M, int N, int K) {
  extern __shared__ char smem[];
  const uint32_t sbase = smem_u32(smem);
  const int tid = threadIdx.x;
  const int wid = tid >> 5;
  const int lane = tid & 31;
  const int m0 = blockIdx.y * FBM;
  const int n0 = blockIdx.x * FBN;
  const int NC = K / GKC;

  const int wm = (wid & 3) * 32;
  const int wn = (wid >> 2) * 64;
  const int lrow = lane & 7;
  const int ltile = lane >> 3;
  const int a_r = (ltile & 1) * 8 + lrow;
  const int a_c = (ltile >> 1) * 8;
  const int b_r = (ltile >> 1) * 8 + lrow;
  const int b_c = (ltile & 1) * 8;

  const __half* gA = A + (size_t)m0 * K;
  const __half* gB = B + (size_t)n0 * K;

  auto load_stage = [&](int stg, int chunk) {
    const int kc = chunk * GKC;
    uint32_t sb = sbase + stg * FSTAGE_B;
#pragma unroll
    for (int i = 0; i < 2; i++) {
      int v = tid + i * 256;
      int r = v >> 2;
      int c = (v & 3) * 8;
      cp_async16(sb + (uint32_t)(r * RS + c) * 2, gA + (size_t)r * K + kc + c);
      cp_async16(sb + FTILE_B + (uint32_t)(r * RS + c) * 2,
                 gB + (size_t)r * K + kc + c);
    }
    CP_COMMIT();
  };

  float acc[2][8][4];
#pragma unroll
  for (int f = 0; f < 2; f++)
#pragma unroll
    for (int g = 0; g < 8; g++)
#pragma unroll
      for (int x = 0; x < 4; x++) acc[f][g][x] = 0.0f;

  load_stage(0, 0);
  load_stage(1, 1);

  for (int c = 0; c < NC; c++) {
    if (c + 1 < NC) { CP_WAIT1(); } else { CP_WAIT0(); }
    __syncthreads();
    if (c + 2 < NC) load_stage((c + 2) % 3, c + 2);

    uint32_t sb = sbase + (c % 3) * FSTAGE_B;
#pragma unroll
    for (int kk = 0; kk < 2; kk++) {
      const int k0 = kk * 16;
      uint32_t af[2][4];
#pragma unroll
      for (int f = 0; f < 2; f++) {
        uint32_t ar = (uint32_t)((wm + f * 16 + a_r) * RS + k0 + a_c) * 2;
        ldsm_x4(af[f], sb + ar);
      }
#pragma unroll
      for (int g2 = 0; g2 < 4; g2++) {
        uint32_t br = (uint32_t)((wn + g2 * 16 + b_r) * RS + k0 + b_c) * 2;
        uint32_t r4[4];
        ldsm_x4(r4, sb + FTILE_B + br);
#pragma unroll
        for (int f = 0; f < 2; f++) {
          mma16816h(acc[f][g2 * 2], af[f], r4);
          mma16816h(acc[f][g2 * 2 + 1], af[f], r4 + 2);
        }
      }
    }
  }

  const int gid = lane >> 2, tig = lane & 3;
#pragma unroll
  for (int f = 0; f < 2; f++) {
#pragma unroll
    for (int g = 0; g < 8; g++) {
      int row = m0 + wm + f * 16 + gid;
      int col = n0 + wn + g * 8 + tig * 2;
      *(float2*)(C + (size_t)row * N + col) = make_float2(acc[f][g][0], acc[f][g][1]);
      *(float2*)(C + (size_t)(row + 8) * N + col) = make_float2(acc[f][g][2], acc[f][g][3]);
    }
  }
}

// ---------------------------------------------------------------------------
// Tensor-core flash attention. QK fp16 1.5-split, PV fp16. 3-stage KV pipeline.
// ---------------------------------------------------------------------------
#define ABQ 128
#define ABKV 64
#define ARS 72
#define Q_ELEMS (ABQ * ARS)
#define KV_TILE (ABKV * ARS)
#define KV_STAGE (3 * KV_TILE)
#define ATT_SMEM ((Q_ELEMS + 3 * KV_STAGE) * 2)  // 101376 B

__global__ __launch_bounds__(256, 2) void attn_mma_kernel(
    const __half* __restrict__ Q16,
    const __half* __restrict__ Khi, const __half* __restrict__ Klo,
    const __half* __restrict__ V16, __half* __restrict__ O16) {
  extern __shared__ char sbuf[];
  const uint32_t sbase = smem_u32(sbuf);
  const int tid = threadIdx.x;
  const int wid = tid >> 5;
  const int lane = tid & 31;
  const int h = blockIdx.x;
  const int kvh = h / NREP;
  const int q0 = ((int)gridDim.y - 1 - (int)blockIdx.y) * ABQ;
  const int wm = wid * 16;

  const int lrow = lane & 7;
  const int ltile = lane >> 3;
  const int a_r = (ltile & 1) * 8 + lrow;
  const int a_c = (ltile >> 1) * 8;
  const int b_r = (ltile >> 1) * 8 + lrow;
  const int b_c = (ltile & 1) * 8;
  const int gid = lane >> 2, tig = lane & 3;

  const uint32_t q_s = sbase;

#pragma unroll
  for (int i = 0; i < 4; i++) {
    int v = tid + i * 256;
    int r = v >> 3, c = v & 7;
    size_t g = (size_t)(q0 + r) * (H * HD) + h * HD + c * 8;
    cp_async16(q_s + (uint32_t)(r * ARS + c * 8) * 2, Q16 + g);
  }

  auto load_kv = [&](int stg, int kv0) {
    uint32_t base = sbase + (Q_ELEMS + stg * KV_STAGE) * 2;
#pragma unroll
    for (int i = 0; i < 2; i++) {
      int v = tid + i * 256;
      int r = v >> 3, c = v & 7;
      size_t g = (size_t)(kv0 + r) * (KVH * HD) + kvh * HD + c * 8;
      uint32_t so = (uint32_t)(r * ARS + c * 8) * 2;
      cp_async16(base + 0 * KV_TILE * 2 + so, Khi + g);
      cp_async16(base + 1 * KV_TILE * 2 + so, Klo + g);
      cp_async16(base + 2 * KV_TILE * 2 + so, V16 + g);
    }
    CP_COMMIT();
  };

  const int ntiles = (q0 + ABQ) / ABKV;  // >= 2
  load_kv(0, 0);
  load_kv(1, ABKV);

  float m_[2] = {-1e30f, -1e30f};
  float l_[2] = {0.0f, 0.0f};
  float o[8][4];
#pragma unroll
  for (int nf = 0; nf < 8; nf++)
#pragma unroll
    for (int j = 0; j < 4; j++) o[nf][j] = 0.0f;

  const float SCL = 0.18033688011112042f;
  const int row0 = q0 + wm + gid;

  for (int t = 0; t < ntiles; t++) {
    const int kv0 = t * ABKV;
    if (t + 1 < ntiles) { CP_WAIT1(); } else { CP_WAIT0(); }
    __syncthreads();
    if (t + 2 < ntiles) load_kv((t + 2) % 3, kv0 + 2 * ABKV);

    const uint32_t kvb = sbase + (Q_ELEMS + (t % 3) * KV_STAGE) * 2;

    float sc[8][4];
#pragma unroll
    for (int nf = 0; nf < 8; nf++)
#pragma unroll
      for (int j = 0; j < 4; j++) sc[nf][j] = 0.0f;

#pragma unroll
    for (int ks = 0; ks < 4; ks++) {
      const int k0 = ks * 16;
      uint32_t qh[4];
      ldsm_x4(qh, q_s + (uint32_t)((wm + a_r) * ARS + k0 + a_c) * 2);
#pragma unroll
      for (int ng = 0; ng < 4; ng++) {
        uint32_t br = kvb + (uint32_t)((ng * 16 + b_r) * ARS + k0 + b_c) * 2;
        uint32_t rh[4], rl[4];
        ldsm_x4(rh, br);
        ldsm_x4(rl, br + KV_TILE * 2);
        mma16816h(sc[ng * 2], qh, rh);
        mma16816h(sc[ng * 2], qh, rl);
        mma16816h(sc[ng * 2 + 1], qh, rh + 2);
        mma16816h(sc[ng * 2 + 1], qh, rl + 2);
      }
    }

    const bool nomask = (kv0 + ABKV - 1 <= q0 + wm);
    if (nomask) {
#pragma unroll
      for (int nf = 0; nf < 8; nf++)
#pragma unroll
        for (int j = 0; j < 4; j++) sc[nf][j] *= SCL;
    } else {
#pragma unroll
      for (int nf = 0; nf < 8; nf++) {
        int col = kv0 + nf * 8 + tig * 2;
#pragma unroll
        for (int j = 0; j < 4; j++) {
          int cc = col + (j & 1);
          int rr = row0 + ((j >> 1) << 3);
          sc[nf][j] = (cc <= rr) ? sc[nf][j] * SCL : -1e30f;
        }
      }
    }

    float mx0 = -1e30f, mx1 = -1e30f;
#pragma unroll
    for (int nf = 0; nf < 8; nf++) {
      mx0 = fmaxf(mx0, fmaxf(sc[nf][0], sc[nf][1]));
      mx1 = fmaxf(mx1, fmaxf(sc[nf][2], sc[nf][3]));
    }
    mx0 = fmaxf(mx0, __shfl_xor_sync(0xffffffffu, mx0, 1));
    mx0 = fmaxf(mx0, __shfl_xor_sync(0xffffffffu, mx0, 2));
    mx1 = fmaxf(mx1, __shfl_xor_sync(0xffffffffu, mx1, 1));
    mx1 = fmaxf(mx1, __shfl_xor_sync(0xffffffffu, mx1, 2));
    float mn0 = fmaxf(m_[0], mx0);
    float mn1 = fmaxf(m_[1], mx1);
    float c0 = exp2_poly(m_[0] - mn0);
    float c1 = exp2_poly(m_[1] - mn1);
    m_[0] = mn0;
    m_[1] = mn1;

    float s0 = 0.0f, s1 = 0.0f;
#pragma unroll
    for (int nf = 0; nf < 8; nf++) {
      float p0 = exp2_poly(sc[nf][0] - mn0);
      float p1 = exp2_poly(sc[nf][1] - mn0);
      float p2 = exp2_poly(sc[nf][2] - mn1);
      float p3 = exp2_poly(sc[nf][3] - mn1);
      sc[nf][0] = p0; sc[nf][1] = p1; sc[nf][2] = p2; sc[nf][3] = p3;
      s0 += p0 + p1;
      s1 += p2 + p3;
    }
    l_[0] = l_[0] * c0 + s0;
    l_[1] = l_[1] * c1 + s1;
#pragma unroll
    for (int nf = 0; nf < 8; nf++) {
      o[nf][0] *= c0; o[nf][1] *= c0;
      o[nf][2] *= c1; o[nf][3] *= c1;
    }

    const uint32_t vb = kvb + 2 * KV_TILE * 2;
#pragma unroll
    for (int ks = 0; ks < 4; ks++) {
      uint32_t p16[4];
      p16[0] = pack_half2(sc[2 * ks][0], sc[2 * ks][1]);
      p16[1] = pack_half2(sc[2 * ks][2], sc[2 * ks][3]);
      p16[2] = pack_half2(sc[2 * ks + 1][0], sc[2 * ks + 1][1]);
      p16[3] = pack_half2(sc[2 * ks + 1][2], sc[2 * ks + 1][3]);
#pragma unroll
      for (int dg = 0; dg < 4; dg++) {
        uint32_t va = vb + (uint32_t)((ks * 16 + a_r) * ARS + dg * 16 + a_c) * 2;
        uint32_t vh[4];
        ldsm_x4_trans(vh, va);
        mma16816h(o[dg * 2], p16, vh);
        mma16816h(o[dg * 2 + 1], p16, vh + 2);
      }
    }
  }

  l_[0] += __shfl_xor_sync(0xffffffffu, l_[0], 1);
  l_[0] += __shfl_xor_sync(0xffffffffu, l_[0], 2);
  l_[1] += __shfl_xor_sync(0xffffffffu, l_[1], 1);
  l_[1] += __shfl_xor_sync(0xffffffffu, l_[1], 2);
  float inv0 = 1.0f / l_[0];
  float inv1 = 1.0f / l_[1];

#pragma unroll
  for (int nf = 0; nf < 8; nf++) {
    int col = h * HD + nf * 8 + tig * 2;
    *(__half2*)(O16 + (size_t)row0 * (H * HD) + col) =
        __floats2half2_rn(o[nf][0] * inv0, o[nf][1] * inv0);
    *(__half2*)(O16 + (size_t)(row0 + 8) * (H * HD) + col) =
        __floats2half2_rn(o[nf][2] * inv1, o[nf][3] * inv1);
  }
}

// ---------------------------------------------------------------------------
// Launch
// ---------------------------------------------------------------------------
extern "C" void kernel_launch(void* const* d_in, const int* in_sizes, int n_in,
                              void* d_out, int out_size) {
  const float* hs = (const float*)d_in[0];
  const float* Wq = (const float*)d_in[1];
  const float* Wk = (const float*)d_in[2];
  const float* Wv = (const float*)d_in[3];
  const float* Wo = (const float*)d_in[4];
  float* out = (float*)d_out;

  __nv_bfloat16 *Xhi, *Xlo, *WqkvThi, *WqkvTlo;
  __half *Q16, *K16hi, *K16lo, *V16, *O16, *WoT16;
  cudaGetSymbolAddress((void**)&Xhi, g_Xhi);
  cudaGetSymbolAddress((void**)&Xlo, g_Xlo);
  cudaGetSymbolAddress((void**)&WqkvThi, g_WqkvThi);
  cudaGetSymbolAddress((void**)&WqkvTlo, g_WqkvTlo);
  cudaGetSymbolAddress((void**)&Q16, g_Q16);
  cudaGetSymbolAddress((void**)&K16hi, g_K16hi);
  cudaGetSymbolAddress((void**)&K16lo, g_K16lo);
  cudaGetSymbolAddress((void**)&V16, g_V16);
  cudaGetSymbolAddress((void**)&O16, g_O16);
  cudaGetSymbolAddress((void**)&WoT16, g_WoT16);

  // 1. split activations + rope table + fused weight transpose
  {
    int n4 = S * D / 4;
    split_kernel<<<(n4 + 255) / 256, 256>>>(hs, Xhi, Xlo, n4);
    rope_table_kernel<<<(S * 32 + 255) / 256, 256>>>();
    transpose_all_kernel<<<10240, dim3(32, 8)>>>(Wq, Wk, Wv, Wo);
  }

  cudaFuncSetAttribute(gemm_qkv_rope_kernel,
                       cudaFuncAttributeMaxDynamicSharedMemorySize, GEMM_SMEM);
  cudaFuncSetAttribute(gemm_fp16_kernel,
                       cudaFuncAttributeMaxDynamicSharedMemorySize, GEMM16_SMEM);

  // 2. QKV projection + fused RoPE/split (3-stage pipeline)
  {
    dim3 grid(QKV_N / GBN, S / GBM);  // 32 x 16
    gemm_qkv_rope_kernel<<<grid, 256, GEMM_SMEM>>>(Xhi, Xlo, WqkvThi, WqkvTlo);
  }

  // 3. tensor-core flash attention (3-stage KV pipeline) -> fp16 O
  {
    cudaFuncSetAttribute(attn_mma_kernel,
                         cudaFuncAttributeMaxDynamicSharedMemorySize, ATT_SMEM);
    dim3 grid(H, S / ABQ);
    attn_mma_kernel<<<grid, 256, ATT_SMEM>>>(Q16, K16hi, K16lo, V16, O16);
  }

  // 4. output projection (fp16, 3-stage pipeline)
  {
    dim3 grid(D / FBN, S / FBM);
    gemm_fp16_kernel<<<grid, 256, GEMM16_SMEM>>>(O16, WoT16, out, S, D, D);
  }
}

// round 12
// speedup vs baseline: 1.4871x; 1.2198x over previous
#include <cuda_runtime.h>
#include <cuda_bf16.h>
#include <cuda_fp16.h>
#include <cstdint>
#include <math.h>

#define S 2048
#define D 2048
#define H 32
#define KVH 8
#define HD 64
#define NREP (H / KVH)
#define QKV_N 3072
#define KCOL 2048
#define VCOL 2560

// ---------------------------------------------------------------------------
// Device-global scratch
// ---------------------------------------------------------------------------
__device__ __half g_X16[S * D];                                    // activations fp16
__device__ __half g_WqkvT16hi[QKV_N * D], g_WqkvT16lo[QKV_N * D];  // W fp16 hi/lo
__device__ __half g_Q16[S * H * HD];
__device__ __half g_K16hi[S * KVH * HD], g_K16lo[S * KVH * HD];
__device__ __half g_V16[S * KVH * HD];
__device__ __half g_O16[S * D];
__device__ __half g_WoT16[D * D];
__device__ float g_cos[S * 32], g_sin[S * 32];

// ---------------------------------------------------------------------------
// Helpers
// ---------------------------------------------------------------------------
__device__ __forceinline__ uint32_t smem_u32(const void* p) {
  uint32_t a;
  asm("{ .reg .u64 t; cvta.to.shared.u64 t, %1; cvt.u32.u64 %0, t; }"
      : "=r"(a) : "l"(p));
  return a;
}

__device__ __forceinline__ void ldsm_x4(uint32_t* r, uint32_t addr) {
  asm volatile(
      "ldmatrix.sync.aligned.m8n8.x4.shared.b16 {%0,%1,%2,%3}, [%4];"
      : "=r"(r[0]), "=r"(r[1]), "=r"(r[2]), "=r"(r[3]) : "r"(addr));
}

__device__ __forceinline__ void ldsm_x4_trans(uint32_t* r, uint32_t addr) {
  asm volatile(
      "ldmatrix.sync.aligned.m8n8.x4.trans.shared.b16 {%0,%1,%2,%3}, [%4];"
      : "=r"(r[0]), "=r"(r[1]), "=r"(r[2]), "=r"(r[3]) : "r"(addr));
}

__device__ __forceinline__ void mma16816h(float* d, const uint32_t* a,
                                          const uint32_t* b) {
  asm volatile(
      "mma.sync.aligned.m16n8k16.row.col.f32.f16.f16.f32 "
      "{%0,%1,%2,%3}, {%4,%5,%6,%7}, {%8,%9}, {%0,%1,%2,%3};"
      : "+f"(d[0]), "+f"(d[1]), "+f"(d[2]), "+f"(d[3])
      : "r"(a[0]), "r"(a[1]), "r"(a[2]), "r"(a[3]), "r"(b[0]), "r"(b[1]));
}

__device__ __forceinline__ void cp_async16(uint32_t saddr, const void* gptr) {
  asm volatile("cp.async.cg.shared.global [%0], [%1], 16;" ::
                   "r"(saddr), "l"(__cvta_generic_to_global(gptr)));
}
#define CP_COMMIT() asm volatile("cp.async.commit_group;" ::: "memory")
#define CP_WAIT0() asm volatile("cp.async.wait_group 0;" ::: "memory")
#define CP_WAIT1() asm volatile("cp.async.wait_group 1;" ::: "memory")

__device__ __forceinline__ float exp2_poly(float x) {
  x = fmaxf(x, -126.0f);
  float fl = floorf(x);
  float f = x - fl;
  float p = 1.5403530393e-4f;
  p = fmaf(p, f, 1.3333558146e-3f);
  p = fmaf(p, f, 9.6181291076e-3f);
  p = fmaf(p, f, 5.5504108665e-2f);
  p = fmaf(p, f, 2.4022650696e-1f);
  p = fmaf(p, f, 6.9314718056e-1f);
  p = fmaf(p, f, 1.0f);
  return p * __int_as_float(((int)fl + 127) << 23);
}

__device__ __forceinline__ uint32_t pack_half2(float x, float y) {
  __half2 v = __floats2half2_rn(x, y);
  return *reinterpret_cast<uint32_t*>(&v);
}

__device__ __forceinline__ void split_pack2h(float x, float y, uint32_t& h,
                                             uint32_t& l) {
  __half hx = __float2half_rn(x), hy = __float2half_rn(y);
  float xr = x - __half2float(hx), yr = y - __half2float(hy);
  __half2 hb = __halves2half2(hx, hy);
  __half2 lb = __floats2half2_rn(xr, yr);
  h = *reinterpret_cast<uint32_t*>(&hb);
  l = *reinterpret_cast<uint32_t*>(&lb);
}

// ---------------------------------------------------------------------------
// Preprocessing
// ---------------------------------------------------------------------------
__global__ void tofp16_kernel(const float* __restrict__ in,
                              __half* __restrict__ out, int n4) {
  int i = blockIdx.x * blockDim.x + threadIdx.x;
  if (i >= n4) return;
  float4 v = ((const float4*)in)[i];
  __half2* op = (__half2*)out;
  op[i * 2 + 0] = __floats2half2_rn(v.x, v.y);
  op[i * 2 + 1] = __floats2half2_rn(v.z, v.w);
}

__global__ void rope_table_kernel() {
  int idx = blockIdx.x * blockDim.x + threadIdx.x;
  if (idx >= S * 32) return;
  int s = idx >> 5, i = idx & 31;
  float inv = 1.0f / powf(10000.0f, (2.0f * i) / (float)HD);
  float ang = (float)s * inv;
  g_cos[idx] = cosf(ang);
  g_sin[idx] = sinf(ang);
}

// Fused transpose of all 4 weight matrices (one launch).
// Wq/Wk/Wv -> WqkvT16 fp16 hi/lo ; Wo -> WoT16 fp16 single.
__global__ void transpose_all_kernel(const float* __restrict__ Wq,
                                     const float* __restrict__ Wk,
                                     const float* __restrict__ Wv,
                                     const float* __restrict__ Wo) {
  __shared__ float t[32][33];
  int bid = blockIdx.x;
  const float* W;
  __half *Thi = nullptr, *Tlo = nullptr, *Th = nullptr;
  int N, n0, k0;
  if (bid < 4096) {
    W = Wq; Thi = g_WqkvT16hi; Tlo = g_WqkvT16lo; N = 2048;
    n0 = (bid & 63) * 32; k0 = (bid >> 6) * 32;
  } else if (bid < 5120) {
    int b = bid - 4096;
    W = Wk; Thi = g_WqkvT16hi + (size_t)KCOL * D; Tlo = g_WqkvT16lo + (size_t)KCOL * D;
    N = 512; n0 = (b & 15) * 32; k0 = (b >> 4) * 32;
  } else if (bid < 6144) {
    int b = bid - 5120;
    W = Wv; Thi = g_WqkvT16hi + (size_t)VCOL * D; Tlo = g_WqkvT16lo + (size_t)VCOL * D;
    N = 512; n0 = (b & 15) * 32; k0 = (b >> 4) * 32;
  } else {
    int b = bid - 6144;
    W = Wo; Th = g_WoT16; N = 2048;
    n0 = (b & 63) * 32; k0 = (b >> 6) * 32;
  }
  int tx = threadIdx.x, ty = threadIdx.y;
#pragma unroll
  for (int i = 0; i < 4; i++)
    t[ty + i * 8][tx] = W[(size_t)(k0 + ty + i * 8) * N + n0 + tx];
  __syncthreads();
  if (Th) {
#pragma unroll
    for (int i = 0; i < 4; i++) {
      int n = ty + i * 8;
      Th[(size_t)(n0 + n) * D + k0 + tx] = __float2half(t[tx][n]);
    }
  } else {
#pragma unroll
    for (int i = 0; i < 4; i++) {
      int n = ty + i * 8;
      float x = t[tx][n];
      __half h = __float2half_rn(x);
      __half l = __float2half_rn(x - __half2float(h));
      size_t o = (size_t)(n0 + n) * D + k0 + tx;
      Thi[o] = h;
      Tlo[o] = l;
    }
  }
}

// ---------------------------------------------------------------------------
// QKV GEMM: fp16 1.5-split (X fp16 single, W fp16 hi/lo -> 2 mma products).
// Fused RoPE/split epilogue. 128x96x32, 3-stage pipeline, 2 CTA/SM.
// ---------------------------------------------------------------------------
#define GBM 128
#define GBN 96
#define GKC 32
#define RS 40
#define A_TILE (128 * RS * 2)   // 10240 B
#define B_TILE (96 * RS * 2)    // 7680 B
#define QS_A 0
#define QS_BH A_TILE
#define QS_BL (A_TILE + B_TILE)
#define STAGE_B (A_TILE + 2 * B_TILE)  // 25600 B
#define GEMM_SMEM (3 * STAGE_B)        // 76800 B

__global__ __launch_bounds__(256, 2) void gemm_qkv_rope_kernel(
    const __half* __restrict__ A,
    const __half* __restrict__ Bhi, const __half* __restrict__ Blo) {
  extern __shared__ char smem[];
  const uint32_t sbase = smem_u32(smem);
  const int tid = threadIdx.x;
  const int wid = tid >> 5;
  const int lane = tid & 31;
  const int m0 = blockIdx.y * GBM;
  const int n0 = blockIdx.x * GBN;
  const int NC = D / GKC;  // 64

  const int wm = (wid & 3) * 32;
  const int wn = (wid >> 2) * 48;
  const int lrow = lane & 7;
  const int ltile = lane >> 3;
  const int a_r = (ltile & 1) * 8 + lrow;
  const int a_c = (ltile >> 1) * 8;
  const int b_r = (ltile >> 1) * 8 + lrow;
  const int b_c = (ltile & 1) * 8;

  const __half* gA = A + (size_t)m0 * D;
  const __half* gBh = Bhi + (size_t)n0 * D;
  const __half* gBl = Blo + (size_t)n0 * D;

  auto load_stage = [&](int stg, int chunk) {
    const int kc = chunk * GKC;
    uint32_t sb = sbase + stg * STAGE_B;
    // A: 128 rows x 4 vec16 = 512 -> 2/thread
#pragma unroll
    for (int i = 0; i < 2; i++) {
      int v = tid + i * 256;
      int r = v >> 2;
      int c = (v & 3) * 8;
      cp_async16(sb + QS_A + (uint32_t)(r * RS + c) * 2,
                 gA + (size_t)r * D + kc + c);
    }
    // B hi/lo: 96 rows x 4 vec16 = 384 each
    for (int v = tid; v < 384; v += 256) {
      int r = v >> 2;
      int c = (v & 3) * 8;
      size_t g = (size_t)r * D + kc + c;
      uint32_t so = (uint32_t)(r * RS + c) * 2;
      cp_async16(sb + QS_BH + so, gBh + g);
      cp_async16(sb + QS_BL + so, gBl + g);
    }
    CP_COMMIT();
  };

  float acc[2][6][4];
#pragma unroll
  for (int f = 0; f < 2; f++)
#pragma unroll
    for (int g = 0; g < 6; g++)
#pragma unroll
      for (int x = 0; x < 4; x++) acc[f][g][x] = 0.0f;

  load_stage(0, 0);
  load_stage(1, 1);

  for (int c = 0; c < NC; c++) {
    if (c + 1 < NC) { CP_WAIT1(); } else { CP_WAIT0(); }
    __syncthreads();
    if (c + 2 < NC) load_stage((c + 2) % 3, c + 2);

    uint32_t sb = sbase + (c % 3) * STAGE_B;
#pragma unroll
    for (int kk = 0; kk < 2; kk++) {
      const int k0 = kk * 16;
      uint32_t ah[2][4];
#pragma unroll
      for (int f = 0; f < 2; f++) {
        uint32_t ar = (uint32_t)((wm + f * 16 + a_r) * RS + k0 + a_c) * 2;
        ldsm_x4(ah[f], sb + QS_A + ar);
      }
#pragma unroll
      for (int g2 = 0; g2 < 3; g2++) {
        uint32_t br = (uint32_t)((wn + g2 * 16 + b_r) * RS + k0 + b_c) * 2;
        uint32_t rh[4], rl[4];
        ldsm_x4(rh, sb + QS_BH + br);
        ldsm_x4(rl, sb + QS_BL + br);
#pragma unroll
        for (int sub = 0; sub < 2; sub++) {
          int g = g2 * 2 + sub;
#pragma unroll
          for (int f = 0; f < 2; f++) {
            mma16816h(acc[f][g], ah[f], rh + 2 * sub);
            mma16816h(acc[f][g], ah[f], rl + 2 * sub);
          }
        }
      }
    }
  }

  // ---- fused RoPE + split epilogue ----
  const int gid = lane >> 2, tig = lane & 3;
#pragma unroll
  for (int f = 0; f < 2; f++) {
    int rowA = m0 + wm + f * 16 + gid;
#pragma unroll
    for (int g = 0; g < 6; g++) {
      int C = n0 + wn + g * 8 + tig * 2;
#pragma unroll
      for (int half = 0; half < 2; half++) {
        int s = rowA + half * 8;
        float x = acc[f][g][half * 2 + 0];
        float y = acc[f][g][half * 2 + 1];
        if (C < KCOL) {  // Q: rope -> fp16 single
          int i = (C & 63) >> 1;
          float cs = g_cos[s * 32 + i], sn = g_sin[s * 32 + i];
          float xr = x * cs - y * sn;
          float xi = x * sn + y * cs;
          size_t o = (size_t)s * (H * HD) + C;
          *(uint32_t*)(g_Q16 + o) = pack_half2(xr, xi);
        } else if (C < VCOL) {  // K: rope -> fp16 hi/lo
          int off = C - KCOL;
          int i = (off & 63) >> 1;
          float cs = g_cos[s * 32 + i], sn = g_sin[s * 32 + i];
          float xr = x * cs - y * sn;
          float xi = x * sn + y * cs;
          uint32_t hreg, lreg;
          split_pack2h(xr, xi, hreg, lreg);
          size_t o = (size_t)s * (KVH * HD) + off;
          *(uint32_t*)(g_K16hi + o) = hreg;
          *(uint32_t*)(g_K16lo + o) = lreg;
        } else {  // V: fp16 single
          int off = C - VCOL;
          size_t o = (size_t)s * (KVH * HD) + off;
          *(uint32_t*)(g_V16 + o) = pack_half2(x, y);
        }
      }
    }
  }
}

// ---------------------------------------------------------------------------
// fp16 single-product GEMM (Wo). 3-stage pipeline.
// ---------------------------------------------------------------------------
#define FBM 128
#define FBN 128
#define FTILE_B (128 * RS * 2)
#define FSTAGE_B (2 * FTILE_B)
#define GEMM16_SMEM (3 * FSTAGE_B)

__global__ __launch_bounds__(256, 2) void gemm_fp16_kernel(
    const __half* __restrict__ A, const __half* __restrict__ B,
    float* __restrict__ C, int M, int N, int K) {
  extern __shared__ char smem[];
  const uint32_t sbase = smem_u32(smem);
  const int tid = threadIdx.x;
  const int wid = tid >> 5;
  const int lane = tid & 31;
  const int m0 = blockIdx.y * FBM;
  const int n0 = blockIdx.x * FBN;
  const int NC = K / GKC;

  const int wm = (wid & 3) * 32;
  const int wn = (wid >> 2) * 64;
  const int lrow = lane & 7;
  const int ltile = lane >> 3;
  const int a_r = (ltile & 1) * 8 + lrow;
  const int a_c = (ltile >> 1) * 8;
  const int b_r = (ltile >> 1) * 8 + lrow;
  const int b_c = (ltile & 1) * 8;

  const __half* gA = A + (size_t)m0 * K;
  const __half* gB = B + (size_t)n0 * K;

  auto load_stage = [&](int stg, int chunk) {
    const int kc = chunk * GKC;
    uint32_t sb = sbase + stg * FSTAGE_B;
#pragma unroll
    for (int i = 0; i < 2; i++) {
      int v = tid + i * 256;
      int r = v >> 2;
      int c = (v & 3) * 8;
      cp_async16(sb + (uint32_t)(r * RS + c) * 2, gA + (size_t)r * K + kc + c);
      cp_async16(sb + FTILE_B + (uint32_t)(r * RS + c) * 2,
                 gB + (size_t)r * K + kc + c);
    }
    CP_COMMIT();
  };

  float acc[2][8][4];
#pragma unroll
  for (int f = 0; f < 2; f++)
#pragma unroll
    for (int g = 0; g < 8; g++)
#pragma unroll
      for (int x = 0; x < 4; x++) acc[f][g][x] = 0.0f;

  load_stage(0, 0);
  load_stage(1, 1);

  for (int c = 0; c < NC; c++) {
    if (c + 1 < NC) { CP_WAIT1(); } else { CP_WAIT0(); }
    __syncthreads();
    if (c + 2 < NC) load_stage((c + 2) % 3, c + 2);

    uint32_t sb = sbase + (c % 3) * FSTAGE_B;
#pragma unroll
    for (int kk = 0; kk < 2; kk++) {
      const int k0 = kk * 16;
      uint32_t af[2][4];
#pragma unroll
      for (int f = 0; f < 2; f++) {
        uint32_t ar = (uint32_t)((wm + f * 16 + a_r) * RS + k0 + a_c) * 2;
        ldsm_x4(af[f], sb + ar);
      }
#pragma unroll
      for (int g2 = 0; g2 < 4; g2++) {
        uint32_t br = (uint32_t)((wn + g2 * 16 + b_r) * RS + k0 + b_c) * 2;
        uint32_t r4[4];
        ldsm_x4(r4, sb + FTILE_B + br);
#pragma unroll
        for (int f = 0; f < 2; f++) {
          mma16816h(acc[f][g2 * 2], af[f], r4);
          mma16816h(acc[f][g2 * 2 + 1], af[f], r4 + 2);
        }
      }
    }
  }

  const int gid = lane >> 2, tig = lane & 3;
#pragma unroll
  for (int f = 0; f < 2; f++) {
#pragma unroll
    for (int g = 0; g < 8; g++) {
      int row = m0 + wm + f * 16 + gid;
      int col = n0 + wn + g * 8 + tig * 2;
      *(float2*)(C + (size_t)row * N + col) = make_float2(acc[f][g][0], acc[f][g][1]);
      *(float2*)(C + (size_t)(row + 8) * N + col) = make_float2(acc[f][g][2], acc[f][g][3]);
    }
  }
}

// ---------------------------------------------------------------------------
// Tensor-core flash attention. QK fp16 1.5-split, PV fp16. 3-stage KV pipeline.
// ---------------------------------------------------------------------------
#define ABQ 128
#define ABKV 64
#define ARS 72
#define Q_ELEMS (ABQ * ARS)
#define KV_TILE (ABKV * ARS)
#define KV_STAGE (3 * KV_TILE)
#define ATT_SMEM ((Q_ELEMS + 3 * KV_STAGE) * 2)

__global__ __launch_bounds__(256, 2) void attn_mma_kernel(
    const __half* __restrict__ Q16,
    const __half* __restrict__ Khi, const __half* __restrict__ Klo,
    const __half* __restrict__ V16, __half* __restrict__ O16) {
  extern __shared__ char sbuf[];
  const uint32_t sbase = smem_u32(sbuf);
  const int tid = threadIdx.x;
  const int wid = tid >> 5;
  const int lane = tid & 31;
  const int h = blockIdx.x;
  const int kvh = h / NREP;
  const int q0 = ((int)gridDim.y - 1 - (int)blockIdx.y) * ABQ;
  const int wm = wid * 16;

  const int lrow = lane & 7;
  const int ltile = lane >> 3;
  const int a_r = (ltile & 1) * 8 + lrow;
  const int a_c = (ltile >> 1) * 8;
  const int b_r = (ltile >> 1) * 8 + lrow;
  const int b_c = (ltile & 1) * 8;
  const int gid = lane >> 2, tig = lane & 3;

  const uint32_t q_s = sbase;

#pragma unroll
  for (int i = 0; i < 4; i++) {
    int v = tid + i * 256;
    int r = v >> 3, c = v & 7;
    size_t g = (size_t)(q0 + r) * (H * HD) + h * HD + c * 8;
    cp_async16(q_s + (uint32_t)(r * ARS + c * 8) * 2, Q16 + g);
  }

  auto load_kv = [&](int stg, int kv0) {
    uint32_t base = sbase + (Q_ELEMS + stg * KV_STAGE) * 2;
#pragma unroll
    for (int i = 0; i < 2; i++) {
      int v = tid + i * 256;
      int r = v >> 3, c = v & 7;
      size_t g = (size_t)(kv0 + r) * (KVH * HD) + kvh * HD + c * 8;
      uint32_t so = (uint32_t)(r * ARS + c * 8) * 2;
      cp_async16(base + 0 * KV_TILE * 2 + so, Khi + g);
      cp_async16(base + 1 * KV_TILE * 2 + so, Klo + g);
      cp_async16(base + 2 * KV_TILE * 2 + so, V16 + g);
    }
    CP_COMMIT();
  };

  const int ntiles = (q0 + ABQ) / ABKV;
  load_kv(0, 0);
  load_kv(1, ABKV);

  float m_[2] = {-1e30f, -1e30f};
  float l_[2] = {0.0f, 0.0f};
  float o[8][4];
#pragma unroll
  for (int nf = 0; nf < 8; nf++)
#pragma unroll
    for (int j = 0; j < 4; j++) o[nf][j] = 0.0f;

  const float SCL = 0.18033688011112042f;
  const int row0 = q0 + wm + gid;

  for (int t = 0; t < ntiles; t++) {
    const int kv0 = t * ABKV;
    if (t + 1 < ntiles) { CP_WAIT1(); } else { CP_WAIT0(); }
    __syncthreads();
    if (t + 2 < ntiles) load_kv((t + 2) % 3, kv0 + 2 * ABKV);

    const uint32_t kvb = sbase + (Q_ELEMS + (t % 3) * KV_STAGE) * 2;

    float sc[8][4];
#pragma unroll
    for (int nf = 0; nf < 8; nf++)
#pragma unroll
      for (int j = 0; j < 4; j++) sc[nf][j] = 0.0f;

#pragma unroll
    for (int ks = 0; ks < 4; ks++) {
      const int k0 = ks * 16;
      uint32_t qh[4];
      ldsm_x4(qh, q_s + (uint32_t)((wm + a_r) * ARS + k0 + a_c) * 2);
#pragma unroll
      for (int ng = 0; ng < 4; ng++) {
        uint32_t br = kvb + (uint32_t)((ng * 16 + b_r) * ARS + k0 + b_c) * 2;
        uint32_t rh[4], rl[4];
        ldsm_x4(rh, br);
        ldsm_x4(rl, br + KV_TILE * 2);
        mma16816h(sc[ng * 2], qh, rh);
        mma16816h(sc[ng * 2], qh, rl);
        mma16816h(sc[ng * 2 + 1], qh, rh + 2);
        mma16816h(sc[ng * 2 + 1], qh, rl + 2);
      }
    }

    const bool nomask = (kv0 + ABKV - 1 <= q0 + wm);
    if (nomask) {
#pragma unroll
      for (int nf = 0; nf < 8; nf++)
#pragma unroll
        for (int j = 0; j < 4; j++) sc[nf][j] *= SCL;
    } else {
#pragma unroll
      for (int nf = 0; nf < 8; nf++) {
        int col = kv0 + nf * 8 + tig * 2;
#pragma unroll
        for (int j = 0; j < 4; j++) {
          int cc = col + (j & 1);
          int rr = row0 + ((j >> 1) << 3);
          sc[nf][j] = (cc <= rr) ? sc[nf][j] * SCL : -1e30f;
        }
      }
    }

    float mx0 = -1e30f, mx1 = -1e30f;
#pragma unroll
    for (int nf = 0; nf < 8; nf++) {
      mx0 = fmaxf(mx0, fmaxf(sc[nf][0], sc[nf][1]));
      mx1 = fmaxf(mx1, fmaxf(sc[nf][2], sc[nf][3]));
    }
    mx0 = fmaxf(mx0, __shfl_xor_sync(0xffffffffu, mx0, 1));
    mx0 = fmaxf(mx0, __shfl_xor_sync(0xffffffffu, mx0, 2));
    mx1 = fmaxf(mx1, __shfl_xor_sync(0xffffffffu, mx1, 1));
    mx1 = fmaxf(mx1, __shfl_xor_sync(0xffffffffu, mx1, 2));
    float mn0 = fmaxf(m_[0], mx0);
    float mn1 = fmaxf(m_[1], mx1);
    float c0 = exp2_poly(m_[0] - mn0);
    float c1 = exp2_poly(m_[1] - mn1);
    m_[0] = mn0;
    m_[1] = mn1;

    float s0 = 0.0f, s1 = 0.0f;
#pragma unroll
    for (int nf = 0; nf < 8; nf++) {
      float p0 = exp2_poly(sc[nf][0] - mn0);
      float p1 = exp2_poly(sc[nf][1] - mn0);
      float p2 = exp2_poly(sc[nf][2] - mn1);
      float p3 = exp2_poly(sc[nf][3] - mn1);
      sc[nf][0] = p0; sc[nf][1] = p1; sc[nf][2] = p2; sc[nf][3] = p3;
      s0 += p0 + p1;
      s1 += p2 + p3;
    }
    l_[0] = l_[0] * c0 + s0;
    l_[1] = l_[1] * c1 + s1;
#pragma unroll
    for (int nf = 0; nf < 8; nf++) {
      o[nf][0] *= c0; o[nf][1] *= c0;
      o[nf][2] *= c1; o[nf][3] *= c1;
    }

    const uint32_t vb = kvb + 2 * KV_TILE * 2;
#pragma unroll
    for (int ks = 0; ks < 4; ks++) {
      uint32_t p16[4];
      p16[0] = pack_half2(sc[2 * ks][0], sc[2 * ks][1]);
      p16[1] = pack_half2(sc[2 * ks][2], sc[2 * ks][3]);
      p16[2] = pack_half2(sc[2 * ks + 1][0], sc[2 * ks + 1][1]);
      p16[3] = pack_half2(sc[2 * ks + 1][2], sc[2 * ks + 1][3]);
#pragma unroll
      for (int dg = 0; dg < 4; dg++) {
        uint32_t va = vb + (uint32_t)((ks * 16 + a_r) * ARS + dg * 16 + a_c) * 2;
        uint32_t vh[4];
        ldsm_x4_trans(vh, va);
        mma16816h(o[dg * 2], p16, vh);
        mma16816h(o[dg * 2 + 1], p16, vh + 2);
      }
    }
  }

  l_[0] += __shfl_xor_sync(0xffffffffu, l_[0], 1);
  l_[0] += __shfl_xor_sync(0xffffffffu, l_[0], 2);
  l_[1] += __shfl_xor_sync(0xffffffffu, l_[1], 1);
  l_[1] += __shfl_xor_sync(0xffffffffu, l_[1], 2);
  float inv0 = 1.0f / l_[0];
  float inv1 = 1.0f / l_[1];

#pragma unroll
  for (int nf = 0; nf < 8; nf++) {
    int col = h * HD + nf * 8 + tig * 2;
    *(__half2*)(O16 + (size_t)row0 * (H * HD) + col) =
        __floats2half2_rn(o[nf][0] * inv0, o[nf][1] * inv0);
    *(__half2*)(O16 + (size_t)(row0 + 8) * (H * HD) + col) =
        __floats2half2_rn(o[nf][2] * inv1, o[nf][3] * inv1);
  }
}

// ---------------------------------------------------------------------------
// Launch
// ---------------------------------------------------------------------------
extern "C" void kernel_launch(void* const* d_in, const int* in_sizes, int n_in,
                              void* d_out, int out_size) {
  const float* hs = (const float*)d_in[0];
  const float* Wq = (const float*)d_in[1];
  const float* Wk = (const float*)d_in[2];
  const float* Wv = (const float*)d_in[3];
  const float* Wo = (const float*)d_in[4];
  float* out = (float*)d_out;

  __half *X16, *WqkvT16hi, *WqkvT16lo;
  __half *Q16, *K16hi, *K16lo, *V16, *O16, *WoT16;
  cudaGetSymbolAddress((void**)&X16, g_X16);
  cudaGetSymbolAddress((void**)&WqkvT16hi, g_WqkvT16hi);
  cudaGetSymbolAddress((void**)&WqkvT16lo, g_WqkvT16lo);
  cudaGetSymbolAddress((void**)&Q16, g_Q16);
  cudaGetSymbolAddress((void**)&K16hi, g_K16hi);
  cudaGetSymbolAddress((void**)&K16lo, g_K16lo);
  cudaGetSymbolAddress((void**)&V16, g_V16);
  cudaGetSymbolAddress((void**)&O16, g_O16);
  cudaGetSymbolAddress((void**)&WoT16, g_WoT16);

  // 1. activations -> fp16, rope table, fused weight transpose
  {
    int n4 = S * D / 4;
    tofp16_kernel<<<(n4 + 255) / 256, 256>>>(hs, X16, n4);
    rope_table_kernel<<<(S * 32 + 255) / 256, 256>>>();
    transpose_all_kernel<<<10240, dim3(32, 8)>>>(Wq, Wk, Wv, Wo);
  }

  cudaFuncSetAttribute(gemm_qkv_rope_kernel,
                       cudaFuncAttributeMaxDynamicSharedMemorySize, GEMM_SMEM);
  cudaFuncSetAttribute(gemm_fp16_kernel,
                       cudaFuncAttributeMaxDynamicSharedMemorySize, GEMM16_SMEM);

  // 2. QKV projection (fp16 1.5-split) + fused RoPE/split
  {
    dim3 grid(QKV_N / GBN, S / GBM);  // 32 x 16
    gemm_qkv_rope_kernel<<<grid, 256, GEMM_SMEM>>>(X16, WqkvT16hi, WqkvT16lo);
  }

  // 3. tensor-core flash attention -> fp16 O
  {
    cudaFuncSetAttribute(attn_mma_kernel,
                         cudaFuncAttributeMaxDynamicSharedMemorySize, ATT_SMEM);
    dim3 grid(H, S / ABQ);
    attn_mma_kernel<<<grid, 256, ATT_SMEM>>>(Q16, K16hi, K16lo, V16, O16);
  }

  // 4. output projection (fp16)
  {
    dim3 grid(D / FBN, S / FBM);
    gemm_fp16_kernel<<<grid, 256, GEMM16_SMEM>>>(O16, WoT16, out, S, D, D);
  }
}

// round 13
// speedup vs baseline: 1.7866x; 1.2014x over previous
#include <cuda_runtime.h>
#include <cuda_bf16.h>
#include <cuda_fp16.h>
#include <cstdint>
#include <math.h>

#define S 2048
#define D 2048
#define H 32
#define KVH 8
#define HD 64
#define NREP (H / KVH)
#define QKV_N 3072
#define KCOL 2048
#define VCOL 2560

// ---------------------------------------------------------------------------
// Device-global scratch
// ---------------------------------------------------------------------------
__device__ __half g_X16[S * D];
__device__ __half g_WqkvT16[QKV_N * D];  // W fp16 single (transposed)
__device__ __half g_Q16[S * H * HD];
__device__ __half g_K16hi[S * KVH * HD], g_K16lo[S * KVH * HD];
__device__ __half g_V16[S * KVH * HD];
__device__ __half g_O16[S * D];
__device__ __half g_WoT16[D * D];
__device__ float g_cos[S * 32], g_sin[S * 32];

// ---------------------------------------------------------------------------
// Helpers
// ---------------------------------------------------------------------------
__device__ __forceinline__ uint32_t smem_u32(const void* p) {
  uint32_t a;
  asm("{ .reg .u64 t; cvta.to.shared.u64 t, %1; cvt.u32.u64 %0, t; }"
      : "=r"(a) : "l"(p));
  return a;
}

__device__ __forceinline__ void ldsm_x4(uint32_t* r, uint32_t addr) {
  asm volatile(
      "ldmatrix.sync.aligned.m8n8.x4.shared.b16 {%0,%1,%2,%3}, [%4];"
      : "=r"(r[0]), "=r"(r[1]), "=r"(r[2]), "=r"(r[3]) : "r"(addr));
}

__device__ __forceinline__ void ldsm_x4_trans(uint32_t* r, uint32_t addr) {
  asm volatile(
      "ldmatrix.sync.aligned.m8n8.x4.trans.shared.b16 {%0,%1,%2,%3}, [%4];"
      : "=r"(r[0]), "=r"(r[1]), "=r"(r[2]), "=r"(r[3]) : "r"(addr));
}

__device__ __forceinline__ void mma16816h(float* d, const uint32_t* a,
                                          const uint32_t* b) {
  asm volatile(
      "mma.sync.aligned.m16n8k16.row.col.f32.f16.f16.f32 "
      "{%0,%1,%2,%3}, {%4,%5,%6,%7}, {%8,%9}, {%0,%1,%2,%3};"
      : "+f"(d[0]), "+f"(d[1]), "+f"(d[2]), "+f"(d[3])
      : "r"(a[0]), "r"(a[1]), "r"(a[2]), "r"(a[3]), "r"(b[0]), "r"(b[1]));
}

__device__ __forceinline__ void cp_async16(uint32_t saddr, const void* gptr) {
  asm volatile("cp.async.cg.shared.global [%0], [%1], 16;" ::
                   "r"(saddr), "l"(__cvta_generic_to_global(gptr)));
}
#define CP_COMMIT() asm volatile("cp.async.commit_group;" ::: "memory")
#define CP_WAIT0() asm volatile("cp.async.wait_group 0;" ::: "memory")
#define CP_WAIT1() asm volatile("cp.async.wait_group 1;" ::: "memory")

__device__ __forceinline__ float exp2_poly(float x) {
  x = fmaxf(x, -126.0f);
  float fl = floorf(x);
  float f = x - fl;
  float p = 1.5403530393e-4f;
  p = fmaf(p, f, 1.3333558146e-3f);
  p = fmaf(p, f, 9.6181291076e-3f);
  p = fmaf(p, f, 5.5504108665e-2f);
  p = fmaf(p, f, 2.4022650696e-1f);
  p = fmaf(p, f, 6.9314718056e-1f);
  p = fmaf(p, f, 1.0f);
  return p * __int_as_float(((int)fl + 127) << 23);
}

__device__ __forceinline__ uint32_t pack_half2(float x, float y) {
  __half2 v = __floats2half2_rn(x, y);
  return *reinterpret_cast<uint32_t*>(&v);
}

__device__ __forceinline__ void split_pack2h(float x, float y, uint32_t& h,
                                             uint32_t& l) {
  __half hx = __float2half_rn(x), hy = __float2half_rn(y);
  float xr = x - __half2float(hx), yr = y - __half2float(hy);
  __half2 hb = __halves2half2(hx, hy);
  __half2 lb = __floats2half2_rn(xr, yr);
  h = *reinterpret_cast<uint32_t*>(&hb);
  l = *reinterpret_cast<uint32_t*>(&lb);
}

// ---------------------------------------------------------------------------
// Preprocessing
// ---------------------------------------------------------------------------
__global__ void tofp16_kernel(const float* __restrict__ in,
                              __half* __restrict__ out, int n4) {
  int i = blockIdx.x * blockDim.x + threadIdx.x;
  if (i >= n4) return;
  float4 v = ((const float4*)in)[i];
  __half2* op = (__half2*)out;
  op[i * 2 + 0] = __floats2half2_rn(v.x, v.y);
  op[i * 2 + 1] = __floats2half2_rn(v.z, v.w);
}

__global__ void rope_table_kernel() {
  int idx = blockIdx.x * blockDim.x + threadIdx.x;
  if (idx >= S * 32) return;
  int s = idx >> 5, i = idx & 31;
  float inv = 1.0f / powf(10000.0f, (2.0f * i) / (float)HD);
  float ang = (float)s * inv;
  g_cos[idx] = cosf(ang);
  g_sin[idx] = sinf(ang);
}

// Fused transpose of all 4 weight matrices -> fp16 single (one launch).
__global__ void transpose_all_kernel(const float* __restrict__ Wq,
                                     const float* __restrict__ Wk,
                                     const float* __restrict__ Wv,
                                     const float* __restrict__ Wo) {
  __shared__ float t[32][33];
  int bid = blockIdx.x;
  const float* W;
  __half* Th;
  int N, n0, k0;
  if (bid < 4096) {
    W = Wq; Th = g_WqkvT16; N = 2048;
    n0 = (bid & 63) * 32; k0 = (bid >> 6) * 32;
  } else if (bid < 5120) {
    int b = bid - 4096;
    W = Wk; Th = g_WqkvT16 + (size_t)KCOL * D;
    N = 512; n0 = (b & 15) * 32; k0 = (b >> 4) * 32;
  } else if (bid < 6144) {
    int b = bid - 5120;
    W = Wv; Th = g_WqkvT16 + (size_t)VCOL * D;
    N = 512; n0 = (b & 15) * 32; k0 = (b >> 4) * 32;
  } else {
    int b = bid - 6144;
    W = Wo; Th = g_WoT16; N = 2048;
    n0 = (b & 63) * 32; k0 = (b >> 6) * 32;
  }
  int tx = threadIdx.x, ty = threadIdx.y;
#pragma unroll
  for (int i = 0; i < 4; i++)
    t[ty + i * 8][tx] = W[(size_t)(k0 + ty + i * 8) * N + n0 + tx];
  __syncthreads();
#pragma unroll
  for (int i = 0; i < 4; i++) {
    int n = ty + i * 8;
    Th[(size_t)(n0 + n) * D + k0 + tx] = __float2half(t[tx][n]);
  }
}

// ---------------------------------------------------------------------------
// QKV GEMM: single-product fp16 + fused RoPE/split epilogue.
// 128x96x32, 3-stage pipeline, 2 CTA/SM.
// ---------------------------------------------------------------------------
#define GBM 128
#define GBN 96
#define GKC 32
#define RS 40
#define A_TILE (128 * RS * 2)   // 10240 B
#define B_TILE (96 * RS * 2)    // 7680 B
#define QS_A 0
#define QS_B A_TILE
#define STAGE_B (A_TILE + B_TILE)  // 17920 B
#define GEMM_SMEM (3 * STAGE_B)    // 53760 B

__global__ __launch_bounds__(256, 2) void gemm_qkv_rope_kernel(
    const __half* __restrict__ A, const __half* __restrict__ B) {
  extern __shared__ char smem[];
  const uint32_t sbase = smem_u32(smem);
  const int tid = threadIdx.x;
  const int wid = tid >> 5;
  const int lane = tid & 31;
  const int m0 = blockIdx.y * GBM;
  const int n0 = blockIdx.x * GBN;
  const int NC = D / GKC;  // 64

  const int wm = (wid & 3) * 32;
  const int wn = (wid >> 2) * 48;
  const int lrow = lane & 7;
  const int ltile = lane >> 3;
  const int a_r = (ltile & 1) * 8 + lrow;
  const int a_c = (ltile >> 1) * 8;
  const int b_r = (ltile >> 1) * 8 + lrow;
  const int b_c = (ltile & 1) * 8;

  const __half* gA = A + (size_t)m0 * D;
  const __half* gB = B + (size_t)n0 * D;

  auto load_stage = [&](int stg, int chunk) {
    const int kc = chunk * GKC;
    uint32_t sb = sbase + stg * STAGE_B;
#pragma unroll
    for (int i = 0; i < 2; i++) {
      int v = tid + i * 256;
      int r = v >> 2;
      int c = (v & 3) * 8;
      cp_async16(sb + QS_A + (uint32_t)(r * RS + c) * 2,
                 gA + (size_t)r * D + kc + c);
    }
    for (int v = tid; v < 384; v += 256) {
      int r = v >> 2;
      int c = (v & 3) * 8;
      cp_async16(sb + QS_B + (uint32_t)(r * RS + c) * 2,
                 gB + (size_t)r * D + kc + c);
    }
    CP_COMMIT();
  };

  float acc[2][6][4];
#pragma unroll
  for (int f = 0; f < 2; f++)
#pragma unroll
    for (int g = 0; g < 6; g++)
#pragma unroll
      for (int x = 0; x < 4; x++) acc[f][g][x] = 0.0f;

  load_stage(0, 0);
  load_stage(1, 1);

  for (int c = 0; c < NC; c++) {
    if (c + 1 < NC) { CP_WAIT1(); } else { CP_WAIT0(); }
    __syncthreads();
    if (c + 2 < NC) load_stage((c + 2) % 3, c + 2);

    uint32_t sb = sbase + (c % 3) * STAGE_B;
#pragma unroll
    for (int kk = 0; kk < 2; kk++) {
      const int k0 = kk * 16;
      uint32_t ah[2][4];
#pragma unroll
      for (int f = 0; f < 2; f++) {
        uint32_t ar = (uint32_t)((wm + f * 16 + a_r) * RS + k0 + a_c) * 2;
        ldsm_x4(ah[f], sb + QS_A + ar);
      }
#pragma unroll
      for (int g2 = 0; g2 < 3; g2++) {
        uint32_t br = (uint32_t)((wn + g2 * 16 + b_r) * RS + k0 + b_c) * 2;
        uint32_t rh[4];
        ldsm_x4(rh, sb + QS_B + br);
#pragma unroll
        for (int sub = 0; sub < 2; sub++) {
          int g = g2 * 2 + sub;
#pragma unroll
          for (int f = 0; f < 2; f++)
            mma16816h(acc[f][g], ah[f], rh + 2 * sub);
        }
      }
    }
  }

  // ---- fused RoPE + split epilogue ----
  const int gid = lane >> 2, tig = lane & 3;
#pragma unroll
  for (int f = 0; f < 2; f++) {
    int rowA = m0 + wm + f * 16 + gid;
#pragma unroll
    for (int g = 0; g < 6; g++) {
      int C = n0 + wn + g * 8 + tig * 2;
#pragma unroll
      for (int half = 0; half < 2; half++) {
        int s = rowA + half * 8;
        float x = acc[f][g][half * 2 + 0];
        float y = acc[f][g][half * 2 + 1];
        if (C < KCOL) {  // Q: rope -> fp16 single
          int i = (C & 63) >> 1;
          float cs = g_cos[s * 32 + i], sn = g_sin[s * 32 + i];
          float xr = x * cs - y * sn;
          float xi = x * sn + y * cs;
          size_t o = (size_t)s * (H * HD) + C;
          *(uint32_t*)(g_Q16 + o) = pack_half2(xr, xi);
        } else if (C < VCOL) {  // K: rope -> fp16 hi/lo
          int off = C - KCOL;
          int i = (off & 63) >> 1;
          float cs = g_cos[s * 32 + i], sn = g_sin[s * 32 + i];
          float xr = x * cs - y * sn;
          float xi = x * sn + y * cs;
          uint32_t hreg, lreg;
          split_pack2h(xr, xi, hreg, lreg);
          size_t o = (size_t)s * (KVH * HD) + off;
          *(uint32_t*)(g_K16hi + o) = hreg;
          *(uint32_t*)(g_K16lo + o) = lreg;
        } else {  // V: fp16 single
          int off = C - VCOL;
          size_t o = (size_t)s * (KVH * HD) + off;
          *(uint32_t*)(g_V16 + o) = pack_half2(x, y);
        }
      }
    }
  }
}

// ---------------------------------------------------------------------------
// fp16 single-product GEMM (Wo). 3-stage pipeline.
// ---------------------------------------------------------------------------
#define FBM 128
#define FBN 128
#define FTILE_B (128 * RS * 2)
#define FSTAGE_B (2 * FTILE_B)
#define GEMM16_SMEM (3 * FSTAGE_B)

__global__ __launch_bounds__(256, 2) void gemm_fp16_kernel(
    const __half* __restrict__ A, const __half* __restrict__ B,
    float* __restrict__ C, int M, int N, int K) {
  extern __shared__ char smem[];
  const uint32_t sbase = smem_u32(smem);
  const int tid = threadIdx.x;
  const int wid = tid >> 5;
  const int lane = tid & 31;
  const int m0 = blockIdx.y * FBM;
  const int n0 = blockIdx.x * FBN;
  const int NC = K / GKC;

  const int wm = (wid & 3) * 32;
  const int wn = (wid >> 2) * 64;
  const int lrow = lane & 7;
  const int ltile = lane >> 3;
  const int a_r = (ltile & 1) * 8 + lrow;
  const int a_c = (ltile >> 1) * 8;
  const int b_r = (ltile >> 1) * 8 + lrow;
  const int b_c = (ltile & 1) * 8;

  const __half* gA = A + (size_t)m0 * K;
  const __half* gB = B + (size_t)n0 * K;

  auto load_stage = [&](int stg, int chunk) {
    const int kc = chunk * GKC;
    uint32_t sb = sbase + stg * FSTAGE_B;
#pragma unroll
    for (int i = 0; i < 2; i++) {
      int v = tid + i * 256;
      int r = v >> 2;
      int c = (v & 3) * 8;
      cp_async16(sb + (uint32_t)(r * RS + c) * 2, gA + (size_t)r * K + kc + c);
      cp_async16(sb + FTILE_B + (uint32_t)(r * RS + c) * 2,
                 gB + (size_t)r * K + kc + c);
    }
    CP_COMMIT();
  };

  float acc[2][8][4];
#pragma unroll
  for (int f = 0; f < 2; f++)
#pragma unroll
    for (int g = 0; g < 8; g++)
#pragma unroll
      for (int x = 0; x < 4; x++) acc[f][g][x] = 0.0f;

  load_stage(0, 0);
  load_stage(1, 1);

  for (int c = 0; c < NC; c++) {
    if (c + 1 < NC) { CP_WAIT1(); } else { CP_WAIT0(); }
    __syncthreads();
    if (c + 2 < NC) load_stage((c + 2) % 3, c + 2);

    uint32_t sb = sbase + (c % 3) * FSTAGE_B;
#pragma unroll
    for (int kk = 0; kk < 2; kk++) {
      const int k0 = kk * 16;
      uint32_t af[2][4];
#pragma unroll
      for (int f = 0; f < 2; f++) {
        uint32_t ar = (uint32_t)((wm + f * 16 + a_r) * RS + k0 + a_c) * 2;
        ldsm_x4(af[f], sb + ar);
      }
#pragma unroll
      for (int g2 = 0; g2 < 4; g2++) {
        uint32_t br = (uint32_t)((wn + g2 * 16 + b_r) * RS + k0 + b_c) * 2;
        uint32_t r4[4];
        ldsm_x4(r4, sb + FTILE_B + br);
#pragma unroll
        for (int f = 0; f < 2; f++) {
          mma16816h(acc[f][g2 * 2], af[f], r4);
          mma16816h(acc[f][g2 * 2 + 1], af[f], r4 + 2);
        }
      }
    }
  }

  const int gid = lane >> 2, tig = lane & 3;
#pragma unroll
  for (int f = 0; f < 2; f++) {
#pragma unroll
    for (int g = 0; g < 8; g++) {
      int row = m0 + wm + f * 16 + gid;
      int col = n0 + wn + g * 8 + tig * 2;
      *(float2*)(C + (size_t)row * N + col) = make_float2(acc[f][g][0], acc[f][g][1]);
      *(float2*)(C + (size_t)(row + 8) * N + col) = make_float2(acc[f][g][2], acc[f][g][3]);
    }
  }
}

// ---------------------------------------------------------------------------
// Tensor-core flash attention. QK fp16 1.5-split, PV fp16. 3-stage KV pipeline.
// ---------------------------------------------------------------------------
#define ABQ 128
#define ABKV 64
#define ARS 72
#define Q_ELEMS (ABQ * ARS)
#define KV_TILE (ABKV * ARS)
#define KV_STAGE (3 * KV_TILE)
#define ATT_SMEM ((Q_ELEMS + 3 * KV_STAGE) * 2)

__global__ __launch_bounds__(256, 2) void attn_mma_kernel(
    const __half* __restrict__ Q16,
    const __half* __restrict__ Khi, const __half* __restrict__ Klo,
    const __half* __restrict__ V16, __half* __restrict__ O16) {
  extern __shared__ char sbuf[];
  const uint32_t sbase = smem_u32(sbuf);
  const int tid = threadIdx.x;
  const int wid = tid >> 5;
  const int lane = tid & 31;
  const int h = blockIdx.x;
  const int kvh = h / NREP;
  const int q0 = ((int)gridDim.y - 1 - (int)blockIdx.y) * ABQ;
  const int wm = wid * 16;

  const int lrow = lane & 7;
  const int ltile = lane >> 3;
  const int a_r = (ltile & 1) * 8 + lrow;
  const int a_c = (ltile >> 1) * 8;
  const int b_r = (ltile >> 1) * 8 + lrow;
  const int b_c = (ltile & 1) * 8;
  const int gid = lane >> 2, tig = lane & 3;

  const uint32_t q_s = sbase;

#pragma unroll
  for (int i = 0; i < 4; i++) {
    int v = tid + i * 256;
    int r = v >> 3, c = v & 7;
    size_t g = (size_t)(q0 + r) * (H * HD) + h * HD + c * 8;
    cp_async16(q_s + (uint32_t)(r * ARS + c * 8) * 2, Q16 + g);
  }

  auto load_kv = [&](int stg, int kv0) {
    uint32_t base = sbase + (Q_ELEMS + stg * KV_STAGE) * 2;
#pragma unroll
    for (int i = 0; i < 2; i++) {
      int v = tid + i * 256;
      int r = v >> 3, c = v & 7;
      size_t g = (size_t)(kv0 + r) * (KVH * HD) + kvh * HD + c * 8;
      uint32_t so = (uint32_t)(r * ARS + c * 8) * 2;
      cp_async16(base + 0 * KV_TILE * 2 + so, Khi + g);
      cp_async16(base + 1 * KV_TILE * 2 + so, Klo + g);
      cp_async16(base + 2 * KV_TILE * 2 + so, V16 + g);
    }
    CP_COMMIT();
  };

  const int ntiles = (q0 + ABQ) / ABKV;
  load_kv(0, 0);
  load_kv(1, ABKV);

  float m_[2] = {-1e30f, -1e30f};
  float l_[2] = {0.0f, 0.0f};
  float o[8][4];
#pragma unroll
  for (int nf = 0; nf < 8; nf++)
#pragma unroll
    for (int j = 0; j < 4; j++) o[nf][j] = 0.0f;

  const float SCL = 0.18033688011112042f;
  const int row0 = q0 + wm + gid;

  for (int t = 0; t < ntiles; t++) {
    const int kv0 = t * ABKV;
    if (t + 1 < ntiles) { CP_WAIT1(); } else { CP_WAIT0(); }
    __syncthreads();
    if (t + 2 < ntiles) load_kv((t + 2) % 3, kv0 + 2 * ABKV);

    const uint32_t kvb = sbase + (Q_ELEMS + (t % 3) * KV_STAGE) * 2;

    float sc[8][4];
#pragma unroll
    for (int nf = 0; nf < 8; nf++)
#pragma unroll
      for (int j = 0; j < 4; j++) sc[nf][j] = 0.0f;

#pragma unroll
    for (int ks = 0; ks < 4; ks++) {
      const int k0 = ks * 16;
      uint32_t qh[4];
      ldsm_x4(qh, q_s + (uint32_t)((wm + a_r) * ARS + k0 + a_c) * 2);
#pragma unroll
      for (int ng = 0; ng < 4; ng++) {
        uint32_t br = kvb + (uint32_t)((ng * 16 + b_r) * ARS + k0 + b_c) * 2;
        uint32_t rh[4], rl[4];
        ldsm_x4(rh, br);
        ldsm_x4(rl, br + KV_TILE * 2);
        mma16816h(sc[ng * 2], qh, rh);
        mma16816h(sc[ng * 2], qh, rl);
        mma16816h(sc[ng * 2 + 1], qh, rh + 2);
        mma16816h(sc[ng * 2 + 1], qh, rl + 2);
      }
    }

    const bool nomask = (kv0 + ABKV - 1 <= q0 + wm);
    if (nomask) {
#pragma unroll
      for (int nf = 0; nf < 8; nf++)
#pragma unroll
        for (int j = 0; j < 4; j++) sc[nf][j] *= SCL;
    } else {
#pragma unroll
      for (int nf = 0; nf < 8; nf++) {
        int col = kv0 + nf * 8 + tig * 2;
#pragma unroll
        for (int j = 0; j < 4; j++) {
          int cc = col + (j & 1);
          int rr = row0 + ((j >> 1) << 3);
          sc[nf][j] = (cc <= rr) ? sc[nf][j] * SCL : -1e30f;
        }
      }
    }

    float mx0 = -1e30f, mx1 = -1e30f;
#pragma unroll
    for (int nf = 0; nf < 8; nf++) {
      mx0 = fmaxf(mx0, fmaxf(sc[nf][0], sc[nf][1]));
      mx1 = fmaxf(mx1, fmaxf(sc[nf][2], sc[nf][3]));
    }
    mx0 = fmaxf(mx0, __shfl_xor_sync(0xffffffffu, mx0, 1));
    mx0 = fmaxf(mx0, __shfl_xor_sync(0xffffffffu, mx0, 2));
    mx1 = fmaxf(mx1, __shfl_xor_sync(0xffffffffu, mx1, 1));
    mx1 = fmaxf(mx1, __shfl_xor_sync(0xffffffffu, mx1, 2));
    float mn0 = fmaxf(m_[0], mx0);
    float mn1 = fmaxf(m_[1], mx1);
    float c0 = exp2_poly(m_[0] - mn0);
    float c1 = exp2_poly(m_[1] - mn1);
    m_[0] = mn0;
    m_[1] = mn1;

    float s0 = 0.0f, s1 = 0.0f;
#pragma unroll
    for (int nf = 0; nf < 8; nf++) {
      float p0 = exp2_poly(sc[nf][0] - mn0);
      float p1 = exp2_poly(sc[nf][1] - mn0);
      float p2 = exp2_poly(sc[nf][2] - mn1);
      float p3 = exp2_poly(sc[nf][3] - mn1);
      sc[nf][0] = p0; sc[nf][1] = p1; sc[nf][2] = p2; sc[nf][3] = p3;
      s0 += p0 + p1;
      s1 += p2 + p3;
    }
    l_[0] = l_[0] * c0 + s0;
    l_[1] = l_[1] * c1 + s1;
#pragma unroll
    for (int nf = 0; nf < 8; nf++) {
      o[nf][0] *= c0; o[nf][1] *= c0;
      o[nf][2] *= c1; o[nf][3] *= c1;
    }

    const uint32_t vb = kvb + 2 * KV_TILE * 2;
#pragma unroll
    for (int ks = 0; ks < 4; ks++) {
      uint32_t p16[4];
      p16[0] = pack_half2(sc[2 * ks][0], sc[2 * ks][1]);
      p16[1] = pack_half2(sc[2 * ks][2], sc[2 * ks][3]);
      p16[2] = pack_half2(sc[2 * ks + 1][0], sc[2 * ks + 1][1]);
      p16[3] = pack_half2(sc[2 * ks + 1][2], sc[2 * ks + 1][3]);
#pragma unroll
      for (int dg = 0; dg < 4; dg++) {
        uint32_t va = vb + (uint32_t)((ks * 16 + a_r) * ARS + dg * 16 + a_c) * 2;
        uint32_t vh[4];
        ldsm_x4_trans(vh, va);
        mma16816h(o[dg * 2], p16, vh);
        mma16816h(o[dg * 2 + 1], p16, vh + 2);
      }
    }
  }

  l_[0] += __shfl_xor_sync(0xffffffffu, l_[0], 1);
  l_[0] += __shfl_xor_sync(0xffffffffu, l_[0], 2);
  l_[1] += __shfl_xor_sync(0xffffffffu, l_[1], 1);
  l_[1] += __shfl_xor_sync(0xffffffffu, l_[1], 2);
  float inv0 = 1.0f / l_[0];
  float inv1 = 1.0f / l_[1];

#pragma unroll
  for (int nf = 0; nf < 8; nf++) {
    int col = h * HD + nf * 8 + tig * 2;
    *(__half2*)(O16 + (size_t)row0 * (H * HD) + col) =
        __floats2half2_rn(o[nf][0] * inv0, o[nf][1] * inv0);
    *(__half2*)(O16 + (size_t)(row0 + 8) * (H * HD) + col) =
        __floats2half2_rn(o[nf][2] * inv1, o[nf][3] * inv1);
  }
}

// ---------------------------------------------------------------------------
// Launch
// ---------------------------------------------------------------------------
extern "C" void kernel_launch(void* const* d_in, const int* in_sizes, int n_in,
                              void* d_out, int out_size) {
  const float* hs = (const float*)d_in[0];
  const float* Wq = (const float*)d_in[1];
  const float* Wk = (const float*)d_in[2];
  const float* Wv = (const float*)d_in[3];
  const float* Wo = (const float*)d_in[4];
  float* out = (float*)d_out;

  __half *X16, *WqkvT16;
  __half *Q16, *K16hi, *K16lo, *V16, *O16, *WoT16;
  cudaGetSymbolAddress((void**)&X16, g_X16);
  cudaGetSymbolAddress((void**)&WqkvT16, g_WqkvT16);
  cudaGetSymbolAddress((void**)&Q16, g_Q16);
  cudaGetSymbolAddress((void**)&K16hi, g_K16hi);
  cudaGetSymbolAddress((void**)&K16lo, g_K16lo);
  cudaGetSymbolAddress((void**)&V16, g_V16);
  cudaGetSymbolAddress((void**)&O16, g_O16);
  cudaGetSymbolAddress((void**)&WoT16, g_WoT16);

  // 1. activations -> fp16, rope table, fused weight transpose
  {
    int n4 = S * D / 4;
    tofp16_kernel<<<(n4 + 255) / 256, 256>>>(hs, X16, n4);
    rope_table_kernel<<<(S * 32 + 255) / 256, 256>>>();
    transpose_all_kernel<<<10240, dim3(32, 8)>>>(Wq, Wk, Wv, Wo);
  }

  cudaFuncSetAttribute(gemm_qkv_rope_kernel,
                       cudaFuncAttributeMaxDynamicSharedMemorySize, GEMM_SMEM);
  cudaFuncSetAttribute(gemm_fp16_kernel,
                       cudaFuncAttributeMaxDynamicSharedMemorySize, GEMM16_SMEM);

  // 2. QKV projection (single fp16) + fused RoPE/split
  {
    dim3 grid(QKV_N / GBN, S / GBM);  // 32 x 16
    gemm_qkv_rope_kernel<<<grid, 256, GEMM_SMEM>>>(X16, WqkvT16);
  }

  // 3. tensor-core flash attention -> fp16 O
  {
    cudaFuncSetAttribute(attn_mma_kernel,
                         cudaFuncAttributeMaxDynamicSharedMemorySize, ATT_SMEM);
    dim3 grid(H, S / ABQ);
    attn_mma_kernel<<<grid, 256, ATT_SMEM>>>(Q16, K16hi, K16lo, V16, O16);
  }

  // 4. output projection (fp16)
  {
    dim3 grid(D / FBN, S / FBM);
    gemm_fp16_kernel<<<grid, 256, GEMM16_SMEM>>>(O16, WoT16, out, S, D, D);
  }
}

// round 14
// speedup vs baseline: 1.9168x; 1.0729x over previous
#include <cuda_runtime.h>
#include <cuda_bf16.h>
#include <cuda_fp16.h>
#include <cstdint>
#include <math.h>

#define S 2048
#define D 2048
#define H 32
#define KVH 8
#define HD 64
#define NREP (H / KVH)
#define QKV_N 3072
#define KCOL 2048
#define VCOL 2560

// ---------------------------------------------------------------------------
// Device-global scratch
// ---------------------------------------------------------------------------
__device__ __half g_X16[S * D];
__device__ __half g_WqkvT16[QKV_N * D];
__device__ __half g_Q16[S * H * HD];
__device__ __half g_K16[S * KVH * HD];
__device__ __half g_V16[S * KVH * HD];
__device__ __half g_O16[S * D];
__device__ __half g_WoT16[D * D];
__device__ float g_cos[S * 32], g_sin[S * 32];

// ---------------------------------------------------------------------------
// Helpers
// ---------------------------------------------------------------------------
__device__ __forceinline__ uint32_t smem_u32(const void* p) {
  uint32_t a;
  asm("{ .reg .u64 t; cvta.to.shared.u64 t, %1; cvt.u32.u64 %0, t; }"
      : "=r"(a) : "l"(p));
  return a;
}

__device__ __forceinline__ void ldsm_x4(uint32_t* r, uint32_t addr) {
  asm volatile(
      "ldmatrix.sync.aligned.m8n8.x4.shared.b16 {%0,%1,%2,%3}, [%4];"
      : "=r"(r[0]), "=r"(r[1]), "=r"(r[2]), "=r"(r[3]) : "r"(addr));
}

__device__ __forceinline__ void ldsm_x4_trans(uint32_t* r, uint32_t addr) {
  asm volatile(
      "ldmatrix.sync.aligned.m8n8.x4.trans.shared.b16 {%0,%1,%2,%3}, [%4];"
      : "=r"(r[0]), "=r"(r[1]), "=r"(r[2]), "=r"(r[3]) : "r"(addr));
}

__device__ __forceinline__ void mma16816h(float* d, const uint32_t* a,
                                          const uint32_t* b) {
  asm volatile(
      "mma.sync.aligned.m16n8k16.row.col.f32.f16.f16.f32 "
      "{%0,%1,%2,%3}, {%4,%5,%6,%7}, {%8,%9}, {%0,%1,%2,%3};"
      : "+f"(d[0]), "+f"(d[1]), "+f"(d[2]), "+f"(d[3])
      : "r"(a[0]), "r"(a[1]), "r"(a[2]), "r"(a[3]), "r"(b[0]), "r"(b[1]));
}

__device__ __forceinline__ void cp_async16(uint32_t saddr, const void* gptr) {
  asm volatile("cp.async.cg.shared.global [%0], [%1], 16;" ::
                   "r"(saddr), "l"(__cvta_generic_to_global(gptr)));
}
#define CP_COMMIT() asm volatile("cp.async.commit_group;" ::: "memory")
#define CP_WAIT0() asm volatile("cp.async.wait_group 0;" ::: "memory")
#define CP_WAIT1() asm volatile("cp.async.wait_group 1;" ::: "memory")

__device__ __forceinline__ float exp2_poly(float x) {
  x = fmaxf(x, -126.0f);
  float fl = floorf(x);
  float f = x - fl;
  float p = 1.5403530393e-4f;
  p = fmaf(p, f, 1.3333558146e-3f);
  p = fmaf(p, f, 9.6181291076e-3f);
  p = fmaf(p, f, 5.5504108665e-2f);
  p = fmaf(p, f, 2.4022650696e-1f);
  p = fmaf(p, f, 6.9314718056e-1f);
  p = fmaf(p, f, 1.0f);
  return p * __int_as_float(((int)fl + 127) << 23);
}

__device__ __forceinline__ uint32_t pack_half2(float x, float y) {
  __half2 v = __floats2half2_rn(x, y);
  return *reinterpret_cast<uint32_t*>(&v);
}

// ---------------------------------------------------------------------------
// Preprocessing
// ---------------------------------------------------------------------------
__global__ void tofp16_kernel(const float* __restrict__ in,
                              __half* __restrict__ out, int n4) {
  int i = blockIdx.x * blockDim.x + threadIdx.x;
  if (i >= n4) return;
  float4 v = ((const float4*)in)[i];
  __half2* op = (__half2*)out;
  op[i * 2 + 0] = __floats2half2_rn(v.x, v.y);
  op[i * 2 + 1] = __floats2half2_rn(v.z, v.w);
}

__global__ void rope_table_kernel() {
  int idx = blockIdx.x * blockDim.x + threadIdx.x;
  if (idx >= S * 32) return;
  int s = idx >> 5, i = idx & 31;
  float inv = 1.0f / powf(10000.0f, (2.0f * i) / (float)HD);
  float ang = (float)s * inv;
  g_cos[idx] = cosf(ang);
  g_sin[idx] = sinf(ang);
}

__global__ void transpose_all_kernel(const float* __restrict__ Wq,
                                     const float* __restrict__ Wk,
                                     const float* __restrict__ Wv,
                                     const float* __restrict__ Wo) {
  __shared__ float t[32][33];
  int bid = blockIdx.x;
  const float* W;
  __half* Th;
  int N, n0, k0;
  if (bid < 4096) {
    W = Wq; Th = g_WqkvT16; N = 2048;
    n0 = (bid & 63) * 32; k0 = (bid >> 6) * 32;
  } else if (bid < 5120) {
    int b = bid - 4096;
    W = Wk; Th = g_WqkvT16 + (size_t)KCOL * D;
    N = 512; n0 = (b & 15) * 32; k0 = (b >> 4) * 32;
  } else if (bid < 6144) {
    int b = bid - 5120;
    W = Wv; Th = g_WqkvT16 + (size_t)VCOL * D;
    N = 512; n0 = (b & 15) * 32; k0 = (b >> 4) * 32;
  } else {
    int b = bid - 6144;
    W = Wo; Th = g_WoT16; N = 2048;
    n0 = (b & 63) * 32; k0 = (b >> 6) * 32;
  }
  int tx = threadIdx.x, ty = threadIdx.y;
#pragma unroll
  for (int i = 0; i < 4; i++)
    t[ty + i * 8][tx] = W[(size_t)(k0 + ty + i * 8) * N + n0 + tx];
  __syncthreads();
#pragma unroll
  for (int i = 0; i < 4; i++) {
    int n = ty + i * 8;
    Th[(size_t)(n0 + n) * D + k0 + tx] = __float2half(t[tx][n]);
  }
}

// ---------------------------------------------------------------------------
// QKV GEMM: single-product fp16 + fused RoPE/split epilogue.
// ---------------------------------------------------------------------------
#define GBM 128
#define GBN 96
#define GKC 32
#define RS 40
#define A_TILE (128 * RS * 2)
#define B_TILE (96 * RS * 2)
#define QS_A 0
#define QS_B A_TILE
#define STAGE_B (A_TILE + B_TILE)
#define GEMM_SMEM (3 * STAGE_B)

__global__ __launch_bounds__(256, 2) void gemm_qkv_rope_kernel(
    const __half* __restrict__ A, const __half* __restrict__ B) {
  extern __shared__ char smem[];
  const uint32_t sbase = smem_u32(smem);
  const int tid = threadIdx.x;
  const int wid = tid >> 5;
  const int lane = tid & 31;
  const int m0 = blockIdx.y * GBM;
  const int n0 = blockIdx.x * GBN;
  const int NC = D / GKC;

  const int wm = (wid & 3) * 32;
  const int wn = (wid >> 2) * 48;
  const int lrow = lane & 7;
  const int ltile = lane >> 3;
  const int a_r = (ltile & 1) * 8 + lrow;
  const int a_c = (ltile >> 1) * 8;
  const int b_r = (ltile >> 1) * 8 + lrow;
  const int b_c = (ltile & 1) * 8;

  const __half* gA = A + (size_t)m0 * D;
  const __half* gB = B + (size_t)n0 * D;

  auto load_stage = [&](int stg, int chunk) {
    const int kc = chunk * GKC;
    uint32_t sb = sbase + stg * STAGE_B;
#pragma unroll
    for (int i = 0; i < 2; i++) {
      int v = tid + i * 256;
      int r = v >> 2;
      int c = (v & 3) * 8;
      cp_async16(sb + QS_A + (uint32_t)(r * RS + c) * 2,
                 gA + (size_t)r * D + kc + c);
    }
    for (int v = tid; v < 384; v += 256) {
      int r = v >> 2;
      int c = (v & 3) * 8;
      cp_async16(sb + QS_B + (uint32_t)(r * RS + c) * 2,
                 gB + (size_t)r * D + kc + c);
    }
    CP_COMMIT();
  };

  float acc[2][6][4];
#pragma unroll
  for (int f = 0; f < 2; f++)
#pragma unroll
    for (int g = 0; g < 6; g++)
#pragma unroll
      for (int x = 0; x < 4; x++) acc[f][g][x] = 0.0f;

  load_stage(0, 0);
  load_stage(1, 1);

  for (int c = 0; c < NC; c++) {
    if (c + 1 < NC) { CP_WAIT1(); } else { CP_WAIT0(); }
    __syncthreads();
    if (c + 2 < NC) load_stage((c + 2) % 3, c + 2);

    uint32_t sb = sbase + (c % 3) * STAGE_B;
#pragma unroll
    for (int kk = 0; kk < 2; kk++) {
      const int k0 = kk * 16;
      uint32_t ah[2][4];
#pragma unroll
      for (int f = 0; f < 2; f++) {
        uint32_t ar = (uint32_t)((wm + f * 16 + a_r) * RS + k0 + a_c) * 2;
        ldsm_x4(ah[f], sb + QS_A + ar);
      }
#pragma unroll
      for (int g2 = 0; g2 < 3; g2++) {
        uint32_t br = (uint32_t)((wn + g2 * 16 + b_r) * RS + k0 + b_c) * 2;
        uint32_t rh[4];
        ldsm_x4(rh, sb + QS_B + br);
#pragma unroll
        for (int sub = 0; sub < 2; sub++) {
          int g = g2 * 2 + sub;
#pragma unroll
          for (int f = 0; f < 2; f++)
            mma16816h(acc[f][g], ah[f], rh + 2 * sub);
        }
      }
    }
  }

  // ---- fused RoPE + fp16 pack epilogue ----
  const int gid = lane >> 2, tig = lane & 3;
#pragma unroll
  for (int f = 0; f < 2; f++) {
    int rowA = m0 + wm + f * 16 + gid;
#pragma unroll
    for (int g = 0; g < 6; g++) {
      int C = n0 + wn + g * 8 + tig * 2;
#pragma unroll
      for (int half = 0; half < 2; half++) {
        int s = rowA + half * 8;
        float x = acc[f][g][half * 2 + 0];
        float y = acc[f][g][half * 2 + 1];
        if (C < KCOL) {  // Q: rope
          int i = (C & 63) >> 1;
          float cs = g_cos[s * 32 + i], sn = g_sin[s * 32 + i];
          float xr = x * cs - y * sn;
          float xi = x * sn + y * cs;
          *(uint32_t*)(g_Q16 + (size_t)s * (H * HD) + C) = pack_half2(xr, xi);
        } else if (C < VCOL) {  // K: rope -> fp16 single
          int off = C - KCOL;
          int i = (off & 63) >> 1;
          float cs = g_cos[s * 32 + i], sn = g_sin[s * 32 + i];
          float xr = x * cs - y * sn;
          float xi = x * sn + y * cs;
          *(uint32_t*)(g_K16 + (size_t)s * (KVH * HD) + off) = pack_half2(xr, xi);
        } else {  // V
          int off = C - VCOL;
          *(uint32_t*)(g_V16 + (size_t)s * (KVH * HD) + off) = pack_half2(x, y);
        }
      }
    }
  }
}

// ---------------------------------------------------------------------------
// fp16 single-product GEMM (Wo). 3-stage pipeline.
// ---------------------------------------------------------------------------
#define FBM 128
#define FBN 128
#define FTILE_B (128 * RS * 2)
#define FSTAGE_B (2 * FTILE_B)
#define GEMM16_SMEM (3 * FSTAGE_B)

__global__ __launch_bounds__(256, 2) void gemm_fp16_kernel(
    const __half* __restrict__ A, const __half* __restrict__ B,
    float* __restrict__ C, int M, int N, int K) {
  extern __shared__ char smem[];
  const uint32_t sbase = smem_u32(smem);
  const int tid = threadIdx.x;
  const int wid = tid >> 5;
  const int lane = tid & 31;
  const int m0 = blockIdx.y * FBM;
  const int n0 = blockIdx.x * FBN;
  const int NC = K / GKC;

  const int wm = (wid & 3) * 32;
  const int wn = (wid >> 2) * 64;
  const int lrow = lane & 7;
  const int ltile = lane >> 3;
  const int a_r = (ltile & 1) * 8 + lrow;
  const int a_c = (ltile >> 1) * 8;
  const int b_r = (ltile >> 1) * 8 + lrow;
  const int b_c = (ltile & 1) * 8;

  const __half* gA = A + (size_t)m0 * K;
  const __half* gB = B + (size_t)n0 * K;

  auto load_stage = [&](int stg, int chunk) {
    const int kc = chunk * GKC;
    uint32_t sb = sbase + stg * FSTAGE_B;
#pragma unroll
    for (int i = 0; i < 2; i++) {
      int v = tid + i * 256;
      int r = v >> 2;
      int c = (v & 3) * 8;
      cp_async16(sb + (uint32_t)(r * RS + c) * 2, gA + (size_t)r * K + kc + c);
      cp_async16(sb + FTILE_B + (uint32_t)(r * RS + c) * 2,
                 gB + (size_t)r * K + kc + c);
    }
    CP_COMMIT();
  };

  float acc[2][8][4];
#pragma unroll
  for (int f = 0; f < 2; f++)
#pragma unroll
    for (int g = 0; g < 8; g++)
#pragma unroll
      for (int x = 0; x < 4; x++) acc[f][g][x] = 0.0f;

  load_stage(0, 0);
  load_stage(1, 1);

  for (int c = 0; c < NC; c++) {
    if (c + 1 < NC) { CP_WAIT1(); } else { CP_WAIT0(); }
    __syncthreads();
    if (c + 2 < NC) load_stage((c + 2) % 3, c + 2);

    uint32_t sb = sbase + (c % 3) * FSTAGE_B;
#pragma unroll
    for (int kk = 0; kk < 2; kk++) {
      const int k0 = kk * 16;
      uint32_t af[2][4];
#pragma unroll
      for (int f = 0; f < 2; f++) {
        uint32_t ar = (uint32_t)((wm + f * 16 + a_r) * RS + k0 + a_c) * 2;
        ldsm_x4(af[f], sb + ar);
      }
#pragma unroll
      for (int g2 = 0; g2 < 4; g2++) {
        uint32_t br = (uint32_t)((wn + g2 * 16 + b_r) * RS + k0 + b_c) * 2;
        uint32_t r4[4];
        ldsm_x4(r4, sb + FTILE_B + br);
#pragma unroll
        for (int f = 0; f < 2; f++) {
          mma16816h(acc[f][g2 * 2], af[f], r4);
          mma16816h(acc[f][g2 * 2 + 1], af[f], r4 + 2);
        }
      }
    }
  }

  const int gid = lane >> 2, tig = lane & 3;
#pragma unroll
  for (int f = 0; f < 2; f++) {
#pragma unroll
    for (int g = 0; g < 8; g++) {
      int row = m0 + wm + f * 16 + gid;
      int col = n0 + wn + g * 8 + tig * 2;
      *(float2*)(C + (size_t)row * N + col) = make_float2(acc[f][g][0], acc[f][g][1]);
      *(float2*)(C + (size_t)(row + 8) * N + col) = make_float2(acc[f][g][2], acc[f][g][3]);
    }
  }
}

// ---------------------------------------------------------------------------
// Tensor-core flash attention. QK fp16 single, PV fp16. 3-stage KV pipeline.
// ---------------------------------------------------------------------------
#define ABQ 128
#define ABKV 64
#define ARS 72
#define Q_ELEMS (ABQ * ARS)
#define KV_TILE (ABKV * ARS)
#define KV_STAGE (2 * KV_TILE)
#define ATT_SMEM ((Q_ELEMS + 3 * KV_STAGE) * 2)  // 73728 B

__global__ __launch_bounds__(256, 2) void attn_mma_kernel(
    const __half* __restrict__ Q16, const __half* __restrict__ K16,
    const __half* __restrict__ V16, __half* __restrict__ O16) {
  extern __shared__ char sbuf[];
  const uint32_t sbase = smem_u32(sbuf);
  const int tid = threadIdx.x;
  const int wid = tid >> 5;
  const int lane = tid & 31;
  const int h = blockIdx.x;
  const int kvh = h / NREP;
  const int q0 = ((int)gridDim.y - 1 - (int)blockIdx.y) * ABQ;
  const int wm = wid * 16;

  const int lrow = lane & 7;
  const int ltile = lane >> 3;
  const int a_r = (ltile & 1) * 8 + lrow;
  const int a_c = (ltile >> 1) * 8;
  const int b_r = (ltile >> 1) * 8 + lrow;
  const int b_c = (ltile & 1) * 8;
  const int gid = lane >> 2, tig = lane & 3;

  const uint32_t q_s = sbase;

#pragma unroll
  for (int i = 0; i < 4; i++) {
    int v = tid + i * 256;
    int r = v >> 3, c = v & 7;
    size_t g = (size_t)(q0 + r) * (H * HD) + h * HD + c * 8;
    cp_async16(q_s + (uint32_t)(r * ARS + c * 8) * 2, Q16 + g);
  }

  auto load_kv = [&](int stg, int kv0) {
    uint32_t base = sbase + (Q_ELEMS + stg * KV_STAGE) * 2;
#pragma unroll
    for (int i = 0; i < 2; i++) {
      int v = tid + i * 256;
      int r = v >> 3, c = v & 7;
      size_t g = (size_t)(kv0 + r) * (KVH * HD) + kvh * HD + c * 8;
      uint32_t so = (uint32_t)(r * ARS + c * 8) * 2;
      cp_async16(base + 0 * KV_TILE * 2 + so, K16 + g);
      cp_async16(base + 1 * KV_TILE * 2 + so, V16 + g);
    }
    CP_COMMIT();
  };

  const int ntiles = (q0 + ABQ) / ABKV;
  load_kv(0, 0);
  load_kv(1, ABKV);

  float m_[2] = {-1e30f, -1e30f};
  float l_[2] = {0.0f, 0.0f};
  float o[8][4];
#pragma unroll
  for (int nf = 0; nf < 8; nf++)
#pragma unroll
    for (int j = 0; j < 4; j++) o[nf][j] = 0.0f;

  const float SCL = 0.18033688011112042f;
  const int row0 = q0 + wm + gid;

  for (int t = 0; t < ntiles; t++) {
    const int kv0 = t * ABKV;
    if (t + 1 < ntiles) { CP_WAIT1(); } else { CP_WAIT0(); }
    __syncthreads();
    if (t + 2 < ntiles) load_kv((t + 2) % 3, kv0 + 2 * ABKV);

    const uint32_t kvb = sbase + (Q_ELEMS + (t % 3) * KV_STAGE) * 2;

    float sc[8][4];
#pragma unroll
    for (int nf = 0; nf < 8; nf++)
#pragma unroll
      for (int j = 0; j < 4; j++) sc[nf][j] = 0.0f;

#pragma unroll
    for (int ks = 0; ks < 4; ks++) {
      const int k0 = ks * 16;
      uint32_t qh[4];
      ldsm_x4(qh, q_s + (uint32_t)((wm + a_r) * ARS + k0 + a_c) * 2);
#pragma unroll
      for (int ng = 0; ng < 4; ng++) {
        uint32_t br = kvb + (uint32_t)((ng * 16 + b_r) * ARS + k0 + b_c) * 2;
        uint32_t rh[4];
        ldsm_x4(rh, br);
        mma16816h(sc[ng * 2], qh, rh);
        mma16816h(sc[ng * 2 + 1], qh, rh + 2);
      }
    }

    const bool nomask = (kv0 + ABKV - 1 <= q0 + wm);
    if (nomask) {
#pragma unroll
      for (int nf = 0; nf < 8; nf++)
#pragma unroll
        for (int j = 0; j < 4; j++) sc[nf][j] *= SCL;
    } else {
#pragma unroll
      for (int nf = 0; nf < 8; nf++) {
        int col = kv0 + nf * 8 + tig * 2;
#pragma unroll
        for (int j = 0; j < 4; j++) {
          int cc = col + (j & 1);
          int rr = row0 + ((j >> 1) << 3);
          sc[nf][j] = (cc <= rr) ? sc[nf][j] * SCL : -1e30f;
        }
      }
    }

    float mx0 = -1e30f, mx1 = -1e30f;
#pragma unroll
    for (int nf = 0; nf < 8; nf++) {
      mx0 = fmaxf(mx0, fmaxf(sc[nf][0], sc[nf][1]));
      mx1 = fmaxf(mx1, fmaxf(sc[nf][2], sc[nf][3]));
    }
    mx0 = fmaxf(mx0, __shfl_xor_sync(0xffffffffu, mx0, 1));
    mx0 = fmaxf(mx0, __shfl_xor_sync(0xffffffffu, mx0, 2));
    mx1 = fmaxf(mx1, __shfl_xor_sync(0xffffffffu, mx1, 1));
    mx1 = fmaxf(mx1, __shfl_xor_sync(0xffffffffu, mx1, 2));
    float mn0 = fmaxf(m_[0], mx0);
    float mn1 = fmaxf(m_[1], mx1);
    float c0 = exp2_poly(m_[0] - mn0);
    float c1 = exp2_poly(m_[1] - mn1);
    m_[0] = mn0;
    m_[1] = mn1;

    float s0 = 0.0f, s1 = 0.0f;
#pragma unroll
    for (int nf = 0; nf < 8; nf++) {
      float p0 = exp2_poly(sc[nf][0] - mn0);
      float p1 = exp2_poly(sc[nf][1] - mn0);
      float p2 = exp2_poly(sc[nf][2] - mn1);
      float p3 = exp2_poly(sc[nf][3] - mn1);
      sc[nf][0] = p0; sc[nf][1] = p1; sc[nf][2] = p2; sc[nf][3] = p3;
      s0 += p0 + p1;
      s1 += p2 + p3;
    }
    l_[0] = l_[0] * c0 + s0;
    l_[1] = l_[1] * c1 + s1;
#pragma unroll
    for (int nf = 0; nf < 8; nf++) {
      o[nf][0] *= c0; o[nf][1] *= c0;
      o[nf][2] *= c1; o[nf][3] *= c1;
    }

    const uint32_t vb = kvb + KV_TILE * 2;
#pragma unroll
    for (int ks = 0; ks < 4; ks++) {
      uint32_t p16[4];
      p16[0] = pack_half2(sc[2 * ks][0], sc[2 * ks][1]);
      p16[1] = pack_half2(sc[2 * ks][2], sc[2 * ks][3]);
      p16[2] = pack_half2(sc[2 * ks + 1][0], sc[2 * ks + 1][1]);
      p16[3] = pack_half2(sc[2 * ks + 1][2], sc[2 * ks + 1][3]);
#pragma unroll
      for (int dg = 0; dg < 4; dg++) {
        uint32_t va = vb + (uint32_t)((ks * 16 + a_r) * ARS + dg * 16 + a_c) * 2;
        uint32_t vh[4];
        ldsm_x4_trans(vh, va);
        mma16816h(o[dg * 2], p16, vh);
        mma16816h(o[dg * 2 + 1], p16, vh + 2);
      }
    }
  }

  l_[0] += __shfl_xor_sync(0xffffffffu, l_[0], 1);
  l_[0] += __shfl_xor_sync(0xffffffffu, l_[0], 2);
  l_[1] += __shfl_xor_sync(0xffffffffu, l_[1], 1);
  l_[1] += __shfl_xor_sync(0xffffffffu, l_[1], 2);
  float inv0 = 1.0f / l_[0];
  float inv1 = 1.0f / l_[1];

#pragma unroll
  for (int nf = 0; nf < 8; nf++) {
    int col = h * HD + nf * 8 + tig * 2;
    *(__half2*)(O16 + (size_t)row0 * (H * HD) + col) =
        __floats2half2_rn(o[nf][0] * inv0, o[nf][1] * inv0);
    *(__half2*)(O16 + (size_t)(row0 + 8) * (H * HD) + col) =
        __floats2half2_rn(o[nf][2] * inv1, o[nf][3] * inv1);
  }
}

// ---------------------------------------------------------------------------
// Launch
// ---------------------------------------------------------------------------
extern "C" void kernel_launch(void* const* d_in, const int* in_sizes, int n_in,
                              void* d_out, int out_size) {
  const float* hs = (const float*)d_in[0];
  const float* Wq = (const float*)d_in[1];
  const float* Wk = (const float*)d_in[2];
  const float* Wv = (const float*)d_in[3];
  const float* Wo = (const float*)d_in[4];
  float* out = (float*)d_out;

  __half *X16, *WqkvT16, *Q16, *K16, *V16, *O16, *WoT16;
  cudaGetSymbolAddress((void**)&X16, g_X16);
  cudaGetSymbolAddress((void**)&WqkvT16, g_WqkvT16);
  cudaGetSymbolAddress((void**)&Q16, g_Q16);
  cudaGetSymbolAddress((void**)&K16, g_K16);
  cudaGetSymbolAddress((void**)&V16, g_V16);
  cudaGetSymbolAddress((void**)&O16, g_O16);
  cudaGetSymbolAddress((void**)&WoT16, g_WoT16);

  // 1. activations -> fp16, rope table, fused weight transpose
  {
    int n4 = S * D / 4;
    tofp16_kernel<<<(n4 + 255) / 256, 256>>>(hs, X16, n4);
    rope_table_kernel<<<(S * 32 + 255) / 256, 256>>>();
    transpose_all_kernel<<<10240, dim3(32, 8)>>>(Wq, Wk, Wv, Wo);
  }

  cudaFuncSetAttribute(gemm_qkv_rope_kernel,
                       cudaFuncAttributeMaxDynamicSharedMemorySize, GEMM_SMEM);
  cudaFuncSetAttribute(gemm_fp16_kernel,
                       cudaFuncAttributeMaxDynamicSharedMemorySize, GEMM16_SMEM);

  // 2. QKV projection (single fp16) + fused RoPE
  {
    dim3 grid(QKV_N / GBN, S / GBM);
    gemm_qkv_rope_kernel<<<grid, 256, GEMM_SMEM>>>(X16, WqkvT16);
  }

  // 3. tensor-core flash attention (QK fp16 single, PV fp16) -> fp16 O
  {
    cudaFuncSetAttribute(attn_mma_kernel,
                         cudaFuncAttributeMaxDynamicSharedMemorySize, ATT_SMEM);
    dim3 grid(H, S / ABQ);
    attn_mma_kernel<<<grid, 256, ATT_SMEM>>>(Q16, K16, V16, O16);
  }

  // 4. output projection (fp16)
  {
    dim3 grid(D / FBN, S / FBM);
    gemm_fp16_kernel<<<grid, 256, GEMM16_SMEM>>>(O16, WoT16, out, S, D, D);
  }
}

// round 15
// speedup vs baseline: 1.9810x; 1.0335x over previous
#include <cuda_runtime.h>
#include <cuda_bf16.h>
#include <cuda_fp16.h>
#include <cstdint>
#include <math.h>

#define S 2048
#define D 2048
#define H 32
#define KVH 8
#define HD 64
#define NREP (H / KVH)
#define QKV_N 3072
#define KCOL 2048
#define VCOL 2560

// ---------------------------------------------------------------------------
// Device-global scratch
// ---------------------------------------------------------------------------
__device__ __half g_X16[S * D];
__device__ __half g_WqkvT16[QKV_N * D];
__device__ __half g_Q16[S * H * HD];
__device__ __half g_K16[S * KVH * HD];
__device__ __half g_V16[S * KVH * HD];
__device__ __half g_O16[S * D];
__device__ __half g_WoT16[D * D];
__device__ float g_cos[S * 32], g_sin[S * 32];

// ---------------------------------------------------------------------------
// Helpers
// ---------------------------------------------------------------------------
__device__ __forceinline__ uint32_t smem_u32(const void* p) {
  uint32_t a;
  asm("{ .reg .u64 t; cvta.to.shared.u64 t, %1; cvt.u32.u64 %0, t; }"
      : "=r"(a) : "l"(p));
  return a;
}

__device__ __forceinline__ void ldsm_x4(uint32_t* r, uint32_t addr) {
  asm volatile(
      "ldmatrix.sync.aligned.m8n8.x4.shared.b16 {%0,%1,%2,%3}, [%4];"
      : "=r"(r[0]), "=r"(r[1]), "=r"(r[2]), "=r"(r[3]) : "r"(addr));
}

__device__ __forceinline__ void ldsm_x4_trans(uint32_t* r, uint32_t addr) {
  asm volatile(
      "ldmatrix.sync.aligned.m8n8.x4.trans.shared.b16 {%0,%1,%2,%3}, [%4];"
      : "=r"(r[0]), "=r"(r[1]), "=r"(r[2]), "=r"(r[3]) : "r"(addr));
}

__device__ __forceinline__ void mma16816h(float* d, const uint32_t* a,
                                          const uint32_t* b) {
  asm volatile(
      "mma.sync.aligned.m16n8k16.row.col.f32.f16.f16.f32 "
      "{%0,%1,%2,%3}, {%4,%5,%6,%7}, {%8,%9}, {%0,%1,%2,%3};"
      : "+f"(d[0]), "+f"(d[1]), "+f"(d[2]), "+f"(d[3])
      : "r"(a[0]), "r"(a[1]), "r"(a[2]), "r"(a[3]), "r"(b[0]), "r"(b[1]));
}

__device__ __forceinline__ void cp_async16(uint32_t saddr, const void* gptr) {
  asm volatile("cp.async.cg.shared.global [%0], [%1], 16;" ::
                   "r"(saddr), "l"(__cvta_generic_to_global(gptr)));
}
#define CP_COMMIT() asm volatile("cp.async.commit_group;" ::: "memory")
#define CP_WAIT0() asm volatile("cp.async.wait_group 0;" ::: "memory")
#define CP_WAIT1() asm volatile("cp.async.wait_group 1;" ::: "memory")

__device__ __forceinline__ float exp2_poly(float x) {
  x = fmaxf(x, -126.0f);
  float fl = floorf(x);
  float f = x - fl;
  float p = 1.5403530393e-4f;
  p = fmaf(p, f, 1.3333558146e-3f);
  p = fmaf(p, f, 9.6181291076e-3f);
  p = fmaf(p, f, 5.5504108665e-2f);
  p = fmaf(p, f, 2.4022650696e-1f);
  p = fmaf(p, f, 6.9314718056e-1f);
  p = fmaf(p, f, 1.0f);
  return p * __int_as_float(((int)fl + 127) << 23);
}

__device__ __forceinline__ uint32_t pack_half2(float x, float y) {
  __half2 v = __floats2half2_rn(x, y);
  return *reinterpret_cast<uint32_t*>(&v);
}

// ---------------------------------------------------------------------------
// Preprocessing
// ---------------------------------------------------------------------------
__global__ void tofp16_kernel(const float* __restrict__ in,
                              __half* __restrict__ out, int n4) {
  int i = blockIdx.x * blockDim.x + threadIdx.x;
  if (i >= n4) return;
  float4 v = ((const float4*)in)[i];
  __half2* op = (__half2*)out;
  op[i * 2 + 0] = __floats2half2_rn(v.x, v.y);
  op[i * 2 + 1] = __floats2half2_rn(v.z, v.w);
}

__global__ void rope_table_kernel() {
  int idx = blockIdx.x * blockDim.x + threadIdx.x;
  if (idx >= S * 32) return;
  int s = idx >> 5, i = idx & 31;
  float inv = 1.0f / powf(10000.0f, (2.0f * i) / (float)HD);
  float ang = (float)s * inv;
  g_cos[idx] = cosf(ang);
  g_sin[idx] = sinf(ang);
}

__global__ void transpose_all_kernel(const float* __restrict__ Wq,
                                     const float* __restrict__ Wk,
                                     const float* __restrict__ Wv,
                                     const float* __restrict__ Wo) {
  __shared__ float t[32][33];
  int bid = blockIdx.x;
  const float* W;
  __half* Th;
  int N, n0, k0;
  if (bid < 4096) {
    W = Wq; Th = g_WqkvT16; N = 2048;
    n0 = (bid & 63) * 32; k0 = (bid >> 6) * 32;
  } else if (bid < 5120) {
    int b = bid - 4096;
    W = Wk; Th = g_WqkvT16 + (size_t)KCOL * D;
    N = 512; n0 = (b & 15) * 32; k0 = (b >> 4) * 32;
  } else if (bid < 6144) {
    int b = bid - 5120;
    W = Wv; Th = g_WqkvT16 + (size_t)VCOL * D;
    N = 512; n0 = (b & 15) * 32; k0 = (b >> 4) * 32;
  } else {
    int b = bid - 6144;
    W = Wo; Th = g_WoT16; N = 2048;
    n0 = (b & 63) * 32; k0 = (b >> 6) * 32;
  }
  int tx = threadIdx.x, ty = threadIdx.y;
#pragma unroll
  for (int i = 0; i < 4; i++)
    t[ty + i * 8][tx] = W[(size_t)(k0 + ty + i * 8) * N + n0 + tx];
  __syncthreads();
#pragma unroll
  for (int i = 0; i < 4; i++) {
    int n = ty + i * 8;
    Th[(size_t)(n0 + n) * D + k0 + tx] = __float2half(t[tx][n]);
  }
}

// ---------------------------------------------------------------------------
// QKV GEMM: single fp16 + fused RoPE epilogue.
// 128x96xK64 tiles, 3-stage pipeline, 2 CTA/SM. 32 mainloop iterations.
// ---------------------------------------------------------------------------
#define GBM 128
#define GBN 96
#define GKC 64
#define KRS 72
#define A_TILE (128 * KRS * 2)   // 18432 B
#define B_TILE (96 * KRS * 2)    // 13824 B
#define QS_A 0
#define QS_B A_TILE
#define STAGE_B (A_TILE + B_TILE)  // 32256 B
#define GEMM_SMEM (3 * STAGE_B)    // 96768 B

__global__ __launch_bounds__(256, 2) void gemm_qkv_rope_kernel(
    const __half* __restrict__ A, const __half* __restrict__ B) {
  extern __shared__ char smem[];
  const uint32_t sbase = smem_u32(smem);
  const int tid = threadIdx.x;
  const int wid = tid >> 5;
  const int lane = tid & 31;
  const int m0 = blockIdx.y * GBM;
  const int n0 = blockIdx.x * GBN;
  const int NC = D / GKC;  // 32

  const int wm = (wid & 3) * 32;
  const int wn = (wid >> 2) * 48;
  const int lrow = lane & 7;
  const int ltile = lane >> 3;
  const int a_r = (ltile & 1) * 8 + lrow;
  const int a_c = (ltile >> 1) * 8;
  const int b_r = (ltile >> 1) * 8 + lrow;
  const int b_c = (ltile & 1) * 8;

  const __half* gA = A + (size_t)m0 * D;
  const __half* gB = B + (size_t)n0 * D;

  auto load_stage = [&](int stg, int chunk) {
    const int kc = chunk * GKC;
    uint32_t sb = sbase + stg * STAGE_B;
    // A: 128 rows x 8 vec16 = 1024 -> 4/thread
#pragma unroll
    for (int i = 0; i < 4; i++) {
      int v = tid + i * 256;
      int r = v >> 3;
      int c = (v & 7) * 8;
      cp_async16(sb + QS_A + (uint32_t)(r * KRS + c) * 2,
                 gA + (size_t)r * D + kc + c);
    }
    // B: 96 rows x 8 vec16 = 768 -> 3/thread
#pragma unroll
    for (int i = 0; i < 3; i++) {
      int v = tid + i * 256;
      int r = v >> 3;
      int c = (v & 7) * 8;
      cp_async16(sb + QS_B + (uint32_t)(r * KRS + c) * 2,
                 gB + (size_t)r * D + kc + c);
    }
    CP_COMMIT();
  };

  float acc[2][6][4];
#pragma unroll
  for (int f = 0; f < 2; f++)
#pragma unroll
    for (int g = 0; g < 6; g++)
#pragma unroll
      for (int x = 0; x < 4; x++) acc[f][g][x] = 0.0f;

  load_stage(0, 0);
  load_stage(1, 1);

  for (int c = 0; c < NC; c++) {
    if (c + 1 < NC) { CP_WAIT1(); } else { CP_WAIT0(); }
    __syncthreads();
    if (c + 2 < NC) load_stage((c + 2) % 3, c + 2);

    uint32_t sb = sbase + (c % 3) * STAGE_B;
#pragma unroll
    for (int kk = 0; kk < 4; kk++) {
      const int k0 = kk * 16;
      uint32_t ah[2][4];
#pragma unroll
      for (int f = 0; f < 2; f++) {
        uint32_t ar = (uint32_t)((wm + f * 16 + a_r) * KRS + k0 + a_c) * 2;
        ldsm_x4(ah[f], sb + QS_A + ar);
      }
#pragma unroll
      for (int g2 = 0; g2 < 3; g2++) {
        uint32_t br = (uint32_t)((wn + g2 * 16 + b_r) * KRS + k0 + b_c) * 2;
        uint32_t rh[4];
        ldsm_x4(rh, sb + QS_B + br);
#pragma unroll
        for (int sub = 0; sub < 2; sub++) {
          int g = g2 * 2 + sub;
#pragma unroll
          for (int f = 0; f < 2; f++)
            mma16816h(acc[f][g], ah[f], rh + 2 * sub);
        }
      }
    }
  }

  // ---- fused RoPE + fp16 pack epilogue ----
  const int gid = lane >> 2, tig = lane & 3;
#pragma unroll
  for (int f = 0; f < 2; f++) {
    int rowA = m0 + wm + f * 16 + gid;
#pragma unroll
    for (int g = 0; g < 6; g++) {
      int C = n0 + wn + g * 8 + tig * 2;
#pragma unroll
      for (int half = 0; half < 2; half++) {
        int s = rowA + half * 8;
        float x = acc[f][g][half * 2 + 0];
        float y = acc[f][g][half * 2 + 1];
        if (C < KCOL) {  // Q: rope
          int i = (C & 63) >> 1;
          float cs = g_cos[s * 32 + i], sn = g_sin[s * 32 + i];
          float xr = x * cs - y * sn;
          float xi = x * sn + y * cs;
          *(uint32_t*)(g_Q16 + (size_t)s * (H * HD) + C) = pack_half2(xr, xi);
        } else if (C < VCOL) {  // K: rope
          int off = C - KCOL;
          int i = (off & 63) >> 1;
          float cs = g_cos[s * 32 + i], sn = g_sin[s * 32 + i];
          float xr = x * cs - y * sn;
          float xi = x * sn + y * cs;
          *(uint32_t*)(g_K16 + (size_t)s * (KVH * HD) + off) = pack_half2(xr, xi);
        } else {  // V
          int off = C - VCOL;
          *(uint32_t*)(g_V16 + (size_t)s * (KVH * HD) + off) = pack_half2(x, y);
        }
      }
    }
  }
}

// ---------------------------------------------------------------------------
// fp16 single-product GEMM (Wo). 128x128xK64, 3-stage pipeline.
// ---------------------------------------------------------------------------
#define FBM 128
#define FBN 128
#define FTILE_B (128 * KRS * 2)     // 18432 B
#define FSTAGE_B (2 * FTILE_B)      // 36864 B
#define GEMM16_SMEM (3 * FSTAGE_B)  // 110592 B

__global__ __launch_bounds__(256, 2) void gemm_fp16_kernel(
    const __half* __restrict__ A, const __half* __restrict__ B,
    float* __restrict__ C, int M, int N, int K) {
  extern __shared__ char smem[];
  const uint32_t sbase = smem_u32(smem);
  const int tid = threadIdx.x;
  const int wid = tid >> 5;
  const int lane = tid & 31;
  const int m0 = blockIdx.y * FBM;
  const int n0 = blockIdx.x * FBN;
  const int NC = K / GKC;  // 32

  const int wm = (wid & 3) * 32;
  const int wn = (wid >> 2) * 64;
  const int lrow = lane & 7;
  const int ltile = lane >> 3;
  const int a_r = (ltile & 1) * 8 + lrow;
  const int a_c = (ltile >> 1) * 8;
  const int b_r = (ltile >> 1) * 8 + lrow;
  const int b_c = (ltile & 1) * 8;

  const __half* gA = A + (size_t)m0 * K;
  const __half* gB = B + (size_t)n0 * K;

  auto load_stage = [&](int stg, int chunk) {
    const int kc = chunk * GKC;
    uint32_t sb = sbase + stg * FSTAGE_B;
#pragma unroll
    for (int i = 0; i < 4; i++) {
      int v = tid + i * 256;
      int r = v >> 3;
      int c = (v & 7) * 8;
      cp_async16(sb + (uint32_t)(r * KRS + c) * 2, gA + (size_t)r * K + kc + c);
      cp_async16(sb + FTILE_B + (uint32_t)(r * KRS + c) * 2,
                 gB + (size_t)r * K + kc + c);
    }
    CP_COMMIT();
  };

  float acc[2][8][4];
#pragma unroll
  for (int f = 0; f < 2; f++)
#pragma unroll
    for (int g = 0; g < 8; g++)
#pragma unroll
      for (int x = 0; x < 4; x++) acc[f][g][x] = 0.0f;

  load_stage(0, 0);
  load_stage(1, 1);

  for (int c = 0; c < NC; c++) {
    if (c + 1 < NC) { CP_WAIT1(); } else { CP_WAIT0(); }
    __syncthreads();
    if (c + 2 < NC) load_stage((c + 2) % 3, c + 2);

    uint32_t sb = sbase + (c % 3) * FSTAGE_B;
#pragma unroll
    for (int kk = 0; kk < 4; kk++) {
      const int k0 = kk * 16;
      uint32_t af[2][4];
#pragma unroll
      for (int f = 0; f < 2; f++) {
        uint32_t ar = (uint32_t)((wm + f * 16 + a_r) * KRS + k0 + a_c) * 2;
        ldsm_x4(af[f], sb + ar);
      }
#pragma unroll
      for (int g2 = 0; g2 < 4; g2++) {
        uint32_t br = (uint32_t)((wn + g2 * 16 + b_r) * KRS + k0 + b_c) * 2;
        uint32_t r4[4];
        ldsm_x4(r4, sb + FTILE_B + br);
#pragma unroll
        for (int f = 0; f < 2; f++) {
          mma16816h(acc[f][g2 * 2], af[f], r4);
          mma16816h(acc[f][g2 * 2 + 1], af[f], r4 + 2);
        }
      }
    }
  }

  const int gid = lane >> 2, tig = lane & 3;
#pragma unroll
  for (int f = 0; f < 2; f++) {
#pragma unroll
    for (int g = 0; g < 8; g++) {
      int row = m0 + wm + f * 16 + gid;
      int col = n0 + wn + g * 8 + tig * 2;
      *(float2*)(C + (size_t)row * N + col) = make_float2(acc[f][g][0], acc[f][g][1]);
      *(float2*)(C + (size_t)(row + 8) * N + col) = make_float2(acc[f][g][2], acc[f][g][3]);
    }
  }
}

// ---------------------------------------------------------------------------
// Tensor-core flash attention (unchanged from R14).
// ---------------------------------------------------------------------------
#define ABQ 128
#define ABKV 64
#define ARS 72
#define Q_ELEMS (ABQ * ARS)
#define KV_TILE (ABKV * ARS)
#define KV_STAGE (2 * KV_TILE)
#define ATT_SMEM ((Q_ELEMS + 3 * KV_STAGE) * 2)

__global__ __launch_bounds__(256, 2) void attn_mma_kernel(
    const __half* __restrict__ Q16, const __half* __restrict__ K16,
    const __half* __restrict__ V16, __half* __restrict__ O16) {
  extern __shared__ char sbuf[];
  const uint32_t sbase = smem_u32(sbuf);
  const int tid = threadIdx.x;
  const int wid = tid >> 5;
  const int lane = tid & 31;
  const int h = blockIdx.x;
  const int kvh = h / NREP;
  const int q0 = ((int)gridDim.y - 1 - (int)blockIdx.y) * ABQ;
  const int wm = wid * 16;

  const int lrow = lane & 7;
  const int ltile = lane >> 3;
  const int a_r = (ltile & 1) * 8 + lrow;
  const int a_c = (ltile >> 1) * 8;
  const int b_r = (ltile >> 1) * 8 + lrow;
  const int b_c = (ltile & 1) * 8;
  const int gid = lane >> 2, tig = lane & 3;

  const uint32_t q_s = sbase;

#pragma unroll
  for (int i = 0; i < 4; i++) {
    int v = tid + i * 256;
    int r = v >> 3, c = v & 7;
    size_t g = (size_t)(q0 + r) * (H * HD) + h * HD + c * 8;
    cp_async16(q_s + (uint32_t)(r * ARS + c * 8) * 2, Q16 + g);
  }

  auto load_kv = [&](int stg, int kv0) {
    uint32_t base = sbase + (Q_ELEMS + stg * KV_STAGE) * 2;
#pragma unroll
    for (int i = 0; i < 2; i++) {
      int v = tid + i * 256;
      int r = v >> 3, c = v & 7;
      size_t g = (size_t)(kv0 + r) * (KVH * HD) + kvh * HD + c * 8;
      uint32_t so = (uint32_t)(r * ARS + c * 8) * 2;
      cp_async16(base + 0 * KV_TILE * 2 + so, K16 + g);
      cp_async16(base + 1 * KV_TILE * 2 + so, V16 + g);
    }
    CP_COMMIT();
  };

  const int ntiles = (q0 + ABQ) / ABKV;
  load_kv(0, 0);
  load_kv(1, ABKV);

  float m_[2] = {-1e30f, -1e30f};
  float l_[2] = {0.0f, 0.0f};
  float o[8][4];
#pragma unroll
  for (int nf = 0; nf < 8; nf++)
#pragma unroll
    for (int j = 0; j < 4; j++) o[nf][j] = 0.0f;

  const float SCL = 0.18033688011112042f;
  const int row0 = q0 + wm + gid;

  for (int t = 0; t < ntiles; t++) {
    const int kv0 = t * ABKV;
    if (t + 1 < ntiles) { CP_WAIT1(); } else { CP_WAIT0(); }
    __syncthreads();
    if (t + 2 < ntiles) load_kv((t + 2) % 3, kv0 + 2 * ABKV);

    const uint32_t kvb = sbase + (Q_ELEMS + (t % 3) * KV_STAGE) * 2;

    float sc[8][4];
#pragma unroll
    for (int nf = 0; nf < 8; nf++)
#pragma unroll
      for (int j = 0; j < 4; j++) sc[nf][j] = 0.0f;

#pragma unroll
    for (int ks = 0; ks < 4; ks++) {
      const int k0 = ks * 16;
      uint32_t qh[4];
      ldsm_x4(qh, q_s + (uint32_t)((wm + a_r) * ARS + k0 + a_c) * 2);
#pragma unroll
      for (int ng = 0; ng < 4; ng++) {
        uint32_t br = kvb + (uint32_t)((ng * 16 + b_r) * ARS + k0 + b_c) * 2;
        uint32_t rh[4];
        ldsm_x4(rh, br);
        mma16816h(sc[ng * 2], qh, rh);
        mma16816h(sc[ng * 2 + 1], qh, rh + 2);
      }
    }

    const bool nomask = (kv0 + ABKV - 1 <= q0 + wm);
    if (nomask) {
#pragma unroll
      for (int nf = 0; nf < 8; nf++)
#pragma unroll
        for (int j = 0; j < 4; j++) sc[nf][j] *= SCL;
    } else {
#pragma unroll
      for (int nf = 0; nf < 8; nf++) {
        int col = kv0 + nf * 8 + tig * 2;
#pragma unroll
        for (int j = 0; j < 4; j++) {
          int cc = col + (j & 1);
          int rr = row0 + ((j >> 1) << 3);
          sc[nf][j] = (cc <= rr) ? sc[nf][j] * SCL : -1e30f;
        }
      }
    }

    float mx0 = -1e30f, mx1 = -1e30f;
#pragma unroll
    for (int nf = 0; nf < 8; nf++) {
      mx0 = fmaxf(mx0, fmaxf(sc[nf][0], sc[nf][1]));
      mx1 = fmaxf(mx1, fmaxf(sc[nf][2], sc[nf][3]));
    }
    mx0 = fmaxf(mx0, __shfl_xor_sync(0xffffffffu, mx0, 1));
    mx0 = fmaxf(mx0, __shfl_xor_sync(0xffffffffu, mx0, 2));
    mx1 = fmaxf(mx1, __shfl_xor_sync(0xffffffffu, mx1, 1));
    mx1 = fmaxf(mx1, __shfl_xor_sync(0xffffffffu, mx1, 2));
    float mn0 = fmaxf(m_[0], mx0);
    float mn1 = fmaxf(m_[1], mx1);
    float c0 = exp2_poly(m_[0] - mn0);
    float c1 = exp2_poly(m_[1] - mn1);
    m_[0] = mn0;
    m_[1] = mn1;

    float s0 = 0.0f, s1 = 0.0f;
#pragma unroll
    for (int nf = 0; nf < 8; nf++) {
      float p0 = exp2_poly(sc[nf][0] - mn0);
      float p1 = exp2_poly(sc[nf][1] - mn0);
      float p2 = exp2_poly(sc[nf][2] - mn1);
      float p3 = exp2_poly(sc[nf][3] - mn1);
      sc[nf][0] = p0; sc[nf][1] = p1; sc[nf][2] = p2; sc[nf][3] = p3;
      s0 += p0 + p1;
      s1 += p2 + p3;
    }
    l_[0] = l_[0] * c0 + s0;
    l_[1] = l_[1] * c1 + s1;
#pragma unroll
    for (int nf = 0; nf < 8; nf++) {
      o[nf][0] *= c0; o[nf][1] *= c0;
      o[nf][2] *= c1; o[nf][3] *= c1;
    }

    const uint32_t vb = kvb + KV_TILE * 2;
#pragma unroll
    for (int ks = 0; ks < 4; ks++) {
      uint32_t p16[4];
      p16[0] = pack_half2(sc[2 * ks][0], sc[2 * ks][1]);
      p16[1] = pack_half2(sc[2 * ks][2], sc[2 * ks][3]);
      p16[2] = pack_half2(sc[2 * ks + 1][0], sc[2 * ks + 1][1]);
      p16[3] = pack_half2(sc[2 * ks + 1][2], sc[2 * ks + 1][3]);
#pragma unroll
      for (int dg = 0; dg < 4; dg++) {
        uint32_t va = vb + (uint32_t)((ks * 16 + a_r) * ARS + dg * 16 + a_c) * 2;
        uint32_t vh[4];
        ldsm_x4_trans(vh, va);
        mma16816h(o[dg * 2], p16, vh);
        mma16816h(o[dg * 2 + 1], p16, vh + 2);
      }
    }
  }

  l_[0] += __shfl_xor_sync(0xffffffffu, l_[0], 1);
  l_[0] += __shfl_xor_sync(0xffffffffu, l_[0], 2);
  l_[1] += __shfl_xor_sync(0xffffffffu, l_[1], 1);
  l_[1] += __shfl_xor_sync(0xffffffffu, l_[1], 2);
  float inv0 = 1.0f / l_[0];
  float inv1 = 1.0f / l_[1];

#pragma unroll
  for (int nf = 0; nf < 8; nf++) {
    int col = h * HD + nf * 8 + tig * 2;
    *(__half2*)(O16 + (size_t)row0 * (H * HD) + col) =
        __floats2half2_rn(o[nf][0] * inv0, o[nf][1] * inv0);
    *(__half2*)(O16 + (size_t)(row0 + 8) * (H * HD) + col) =
        __floats2half2_rn(o[nf][2] * inv1, o[nf][3] * inv1);
  }
}

// ---------------------------------------------------------------------------
// Launch
// ---------------------------------------------------------------------------
extern "C" void kernel_launch(void* const* d_in, const int* in_sizes, int n_in,
                              void* d_out, int out_size) {
  const float* hs = (const float*)d_in[0];
  const float* Wq = (const float*)d_in[1];
  const float* Wk = (const float*)d_in[2];
  const float* Wv = (const float*)d_in[3];
  const float* Wo = (const float*)d_in[4];
  float* out = (float*)d_out;

  __half *X16, *WqkvT16, *Q16, *K16, *V16, *O16, *WoT16;
  cudaGetSymbolAddress((void**)&X16, g_X16);
  cudaGetSymbolAddress((void**)&WqkvT16, g_WqkvT16);
  cudaGetSymbolAddress((void**)&Q16, g_Q16);
  cudaGetSymbolAddress((void**)&K16, g_K16);
  cudaGetSymbolAddress((void**)&V16, g_V16);
  cudaGetSymbolAddress((void**)&O16, g_O16);
  cudaGetSymbolAddress((void**)&WoT16, g_WoT16);

  // 1. activations -> fp16, rope table, fused weight transpose
  {
    int n4 = S * D / 4;
    tofp16_kernel<<<(n4 + 255) / 256, 256>>>(hs, X16, n4);
    rope_table_kernel<<<(S * 32 + 255) / 256, 256>>>();
    transpose_all_kernel<<<10240, dim3(32, 8)>>>(Wq, Wk, Wv, Wo);
  }

  cudaFuncSetAttribute(gemm_qkv_rope_kernel,
                       cudaFuncAttributeMaxDynamicSharedMemorySize, GEMM_SMEM);
  cudaFuncSetAttribute(gemm_fp16_kernel,
                       cudaFuncAttributeMaxDynamicSharedMemorySize, GEMM16_SMEM);

  // 2. QKV projection (single fp16, K-chunk 64) + fused RoPE
  {
    dim3 grid(QKV_N / GBN, S / GBM);
    gemm_qkv_rope_kernel<<<grid, 256, GEMM_SMEM>>>(X16, WqkvT16);
  }

  // 3. tensor-core flash attention -> fp16 O
  {
    cudaFuncSetAttribute(attn_mma_kernel,
                         cudaFuncAttributeMaxDynamicSharedMemorySize, ATT_SMEM);
    dim3 grid(H, S / ABQ);
    attn_mma_kernel<<<grid, 256, ATT_SMEM>>>(Q16, K16, V16, O16);
  }

  // 4. output projection (fp16, K-chunk 64)
  {
    dim3 grid(D / FBN, S / FBM);
    gemm_fp16_kernel<<<grid, 256, GEMM16_SMEM>>>(O16, WoT16, out, S, D, D);
  }
}

// round 16
// speedup vs baseline: 2.0394x; 1.0295x over previous
#include <cuda_runtime.h>
#include <cuda_bf16.h>
#include <cuda_fp16.h>
#include <cstdint>
#include <math.h>

#define S 2048
#define D 2048
#define H 32
#define KVH 8
#define HD 64
#define NREP (H / KVH)
#define QKV_N 3072
#define KCOL 2048
#define VCOL 2560

// ---------------------------------------------------------------------------
// Device-global scratch
// ---------------------------------------------------------------------------
__device__ __half g_X16[S * D];
__device__ __half g_WqkvT16[QKV_N * D];
__device__ __half g_Q16[S * H * HD];
__device__ __half g_K16[S * KVH * HD];
__device__ __half g_V16[S * KVH * HD];
__device__ __half g_O16[S * D];
__device__ __half g_WoT16[D * D];
__device__ float g_cos[S * 32], g_sin[S * 32];

// ---------------------------------------------------------------------------
// Helpers
// ---------------------------------------------------------------------------
__device__ __forceinline__ uint32_t smem_u32(const void* p) {
  uint32_t a;
  asm("{ .reg .u64 t; cvta.to.shared.u64 t, %1; cvt.u32.u64 %0, t; }"
      : "=r"(a) : "l"(p));
  return a;
}

__device__ __forceinline__ void ldsm_x4(uint32_t* r, uint32_t addr) {
  asm volatile(
      "ldmatrix.sync.aligned.m8n8.x4.shared.b16 {%0,%1,%2,%3}, [%4];"
      : "=r"(r[0]), "=r"(r[1]), "=r"(r[2]), "=r"(r[3]) : "r"(addr));
}

__device__ __forceinline__ void ldsm_x4_trans(uint32_t* r, uint32_t addr) {
  asm volatile(
      "ldmatrix.sync.aligned.m8n8.x4.trans.shared.b16 {%0,%1,%2,%3}, [%4];"
      : "=r"(r[0]), "=r"(r[1]), "=r"(r[2]), "=r"(r[3]) : "r"(addr));
}

__device__ __forceinline__ void mma16816h(float* d, const uint32_t* a,
                                          const uint32_t* b) {
  asm volatile(
      "mma.sync.aligned.m16n8k16.row.col.f32.f16.f16.f32 "
      "{%0,%1,%2,%3}, {%4,%5,%6,%7}, {%8,%9}, {%0,%1,%2,%3};"
      : "+f"(d[0]), "+f"(d[1]), "+f"(d[2]), "+f"(d[3])
      : "r"(a[0]), "r"(a[1]), "r"(a[2]), "r"(a[3]), "r"(b[0]), "r"(b[1]));
}

__device__ __forceinline__ void cp_async16(uint32_t saddr, const void* gptr) {
  asm volatile("cp.async.cg.shared.global [%0], [%1], 16;" ::
                   "r"(saddr), "l"(__cvta_generic_to_global(gptr)));
}
#define CP_COMMIT() asm volatile("cp.async.commit_group;" ::: "memory")
#define CP_WAIT0() asm volatile("cp.async.wait_group 0;" ::: "memory")
#define CP_WAIT1() asm volatile("cp.async.wait_group 1;" ::: "memory")

__device__ __forceinline__ float exp2_poly(float x) {
  x = fmaxf(x, -126.0f);
  float fl = floorf(x);
  float f = x - fl;
  float p = 1.5403530393e-4f;
  p = fmaf(p, f, 1.3333558146e-3f);
  p = fmaf(p, f, 9.6181291076e-3f);
  p = fmaf(p, f, 5.5504108665e-2f);
  p = fmaf(p, f, 2.4022650696e-1f);
  p = fmaf(p, f, 6.9314718056e-1f);
  p = fmaf(p, f, 1.0f);
  return p * __int_as_float(((int)fl + 127) << 23);
}

__device__ __forceinline__ uint32_t pack_half2(float x, float y) {
  __half2 v = __floats2half2_rn(x, y);
  return *reinterpret_cast<uint32_t*>(&v);
}

// ---------------------------------------------------------------------------
// Fused preprocessing (one launch): X->fp16, rope table, weight transposes.
// Block = (32,8). Region dispatch by blockIdx.x.
//   [0, 4096):            tofp16 of X (4096 * 256 * 4 elems)
//   [4096, 4352):         rope table (65536 entries)
//   [4352, 4352+10240):   transposes (Wq 4096, Wk 1024, Wv 1024, Wo 4096)
// ---------------------------------------------------------------------------
#define PRE_X_BLOCKS 4096
#define PRE_ROPE_BLOCKS 256
#define PRE_T_BLOCKS 10240
#define PRE_TOTAL (PRE_X_BLOCKS + PRE_ROPE_BLOCKS + PRE_T_BLOCKS)

__global__ void preprocess_kernel(const float* __restrict__ hs,
                                  const float* __restrict__ Wq,
                                  const float* __restrict__ Wk,
                                  const float* __restrict__ Wv,
                                  const float* __restrict__ Wo) {
  int bid = blockIdx.x;
  int tid = threadIdx.y * 32 + threadIdx.x;

  if (bid < PRE_X_BLOCKS) {
    int i = bid * 256 + tid;  // < S*D/4
    float4 v = ((const float4*)hs)[i];
    __half2* op = (__half2*)g_X16;
    op[i * 2 + 0] = __floats2half2_rn(v.x, v.y);
    op[i * 2 + 1] = __floats2half2_rn(v.z, v.w);
    return;
  }
  if (bid < PRE_X_BLOCKS + PRE_ROPE_BLOCKS) {
    int idx = (bid - PRE_X_BLOCKS) * 256 + tid;  // < S*32
    int s = idx >> 5, i = idx & 31;
    float inv = 1.0f / powf(10000.0f, (2.0f * i) / (float)HD);
    float ang = (float)s * inv;
    g_cos[idx] = cosf(ang);
    g_sin[idx] = sinf(ang);
    return;
  }

  // transpose region
  __shared__ float t[32][33];
  int b = bid - PRE_X_BLOCKS - PRE_ROPE_BLOCKS;
  const float* W;
  __half* Th;
  int N, n0, k0;
  if (b < 4096) {
    W = Wq; Th = g_WqkvT16; N = 2048;
    n0 = (b & 63) * 32; k0 = (b >> 6) * 32;
  } else if (b < 5120) {
    int bb = b - 4096;
    W = Wk; Th = g_WqkvT16 + (size_t)KCOL * D;
    N = 512; n0 = (bb & 15) * 32; k0 = (bb >> 4) * 32;
  } else if (b < 6144) {
    int bb = b - 5120;
    W = Wv; Th = g_WqkvT16 + (size_t)VCOL * D;
    N = 512; n0 = (bb & 15) * 32; k0 = (bb >> 4) * 32;
  } else {
    int bb = b - 6144;
    W = Wo; Th = g_WoT16; N = 2048;
    n0 = (bb & 63) * 32; k0 = (bb >> 6) * 32;
  }
  int tx = threadIdx.x, ty = threadIdx.y;
#pragma unroll
  for (int i = 0; i < 4; i++)
    t[ty + i * 8][tx] = W[(size_t)(k0 + ty + i * 8) * N + n0 + tx];
  __syncthreads();
#pragma unroll
  for (int i = 0; i < 4; i++) {
    int n = ty + i * 8;
    Th[(size_t)(n0 + n) * D + k0 + tx] = __float2half(t[tx][n]);
  }
}

// ---------------------------------------------------------------------------
// QKV GEMM: single fp16 + fused RoPE epilogue.
// 128x128xK64 tiles (warp 32x64), 3-stage pipeline, 2 CTA/SM.
// ---------------------------------------------------------------------------
#define GBM 128
#define GBN 128
#define GKC 64
#define KRS 72
#define A_TILE (128 * KRS * 2)     // 18432 B
#define QS_A 0
#define QS_B A_TILE
#define STAGE_B (2 * A_TILE)       // 36864 B
#define GEMM_SMEM (3 * STAGE_B)    // 110592 B

__global__ __launch_bounds__(256, 2) void gemm_qkv_rope_kernel(
    const __half* __restrict__ A, const __half* __restrict__ B) {
  extern __shared__ char smem[];
  const uint32_t sbase = smem_u32(smem);
  const int tid = threadIdx.x;
  const int wid = tid >> 5;
  const int lane = tid & 31;
  const int m0 = blockIdx.y * GBM;
  const int n0 = blockIdx.x * GBN;
  const int NC = D / GKC;  // 32

  const int wm = (wid & 3) * 32;
  const int wn = (wid >> 2) * 64;
  const int lrow = lane & 7;
  const int ltile = lane >> 3;
  const int a_r = (ltile & 1) * 8 + lrow;
  const int a_c = (ltile >> 1) * 8;
  const int b_r = (ltile >> 1) * 8 + lrow;
  const int b_c = (ltile & 1) * 8;

  const __half* gA = A + (size_t)m0 * D;
  const __half* gB = B + (size_t)n0 * D;

  auto load_stage = [&](int stg, int chunk) {
    const int kc = chunk * GKC;
    uint32_t sb = sbase + stg * STAGE_B;
#pragma unroll
    for (int i = 0; i < 4; i++) {
      int v = tid + i * 256;
      int r = v >> 3;
      int c = (v & 7) * 8;
      cp_async16(sb + QS_A + (uint32_t)(r * KRS + c) * 2,
                 gA + (size_t)r * D + kc + c);
      cp_async16(sb + QS_B + (uint32_t)(r * KRS + c) * 2,
                 gB + (size_t)r * D + kc + c);
    }
    CP_COMMIT();
  };

  float acc[2][8][4];
#pragma unroll
  for (int f = 0; f < 2; f++)
#pragma unroll
    for (int g = 0; g < 8; g++)
#pragma unroll
      for (int x = 0; x < 4; x++) acc[f][g][x] = 0.0f;

  load_stage(0, 0);
  load_stage(1, 1);

  for (int c = 0; c < NC; c++) {
    if (c + 1 < NC) { CP_WAIT1(); } else { CP_WAIT0(); }
    __syncthreads();
    if (c + 2 < NC) load_stage((c + 2) % 3, c + 2);

    uint32_t sb = sbase + (c % 3) * STAGE_B;
#pragma unroll
    for (int kk = 0; kk < 4; kk++) {
      const int k0 = kk * 16;
      uint32_t af[2][4];
#pragma unroll
      for (int f = 0; f < 2; f++) {
        uint32_t ar = (uint32_t)((wm + f * 16 + a_r) * KRS + k0 + a_c) * 2;
        ldsm_x4(af[f], sb + QS_A + ar);
      }
#pragma unroll
      for (int g2 = 0; g2 < 4; g2++) {
        uint32_t br = (uint32_t)((wn + g2 * 16 + b_r) * KRS + k0 + b_c) * 2;
        uint32_t r4[4];
        ldsm_x4(r4, sb + QS_B + br);
#pragma unroll
        for (int f = 0; f < 2; f++) {
          mma16816h(acc[f][g2 * 2], af[f], r4);
          mma16816h(acc[f][g2 * 2 + 1], af[f], r4 + 2);
        }
      }
    }
  }

  // ---- fused RoPE + fp16 pack epilogue (regions 128-aligned: uniform/CTA) ----
  const int gid = lane >> 2, tig = lane & 3;
#pragma unroll
  for (int f = 0; f < 2; f++) {
    int rowA = m0 + wm + f * 16 + gid;
#pragma unroll
    for (int g = 0; g < 8; g++) {
      int C = n0 + wn + g * 8 + tig * 2;
#pragma unroll
      for (int half = 0; half < 2; half++) {
        int s = rowA + half * 8;
        float x = acc[f][g][half * 2 + 0];
        float y = acc[f][g][half * 2 + 1];
        if (C < KCOL) {  // Q: rope
          int i = (C & 63) >> 1;
          float cs = g_cos[s * 32 + i], sn = g_sin[s * 32 + i];
          float xr = x * cs - y * sn;
          float xi = x * sn + y * cs;
          *(uint32_t*)(g_Q16 + (size_t)s * (H * HD) + C) = pack_half2(xr, xi);
        } else if (C < VCOL) {  // K: rope
          int off = C - KCOL;
          int i = (off & 63) >> 1;
          float cs = g_cos[s * 32 + i], sn = g_sin[s * 32 + i];
          float xr = x * cs - y * sn;
          float xi = x * sn + y * cs;
          *(uint32_t*)(g_K16 + (size_t)s * (KVH * HD) + off) = pack_half2(xr, xi);
        } else {  // V
          int off = C - VCOL;
          *(uint32_t*)(g_V16 + (size_t)s * (KVH * HD) + off) = pack_half2(x, y);
        }
      }
    }
  }
}

// ---------------------------------------------------------------------------
// fp16 single-product GEMM (Wo). 128x128xK64, 3-stage pipeline.
// ---------------------------------------------------------------------------
#define FBM 128
#define FBN 128
#define FTILE_B (128 * KRS * 2)
#define FSTAGE_B (2 * FTILE_B)
#define GEMM16_SMEM (3 * FSTAGE_B)

__global__ __launch_bounds__(256, 2) void gemm_fp16_kernel(
    const __half* __restrict__ A, const __half* __restrict__ B,
    float* __restrict__ C, int M, int N, int K) {
  extern __shared__ char smem[];
  const uint32_t sbase = smem_u32(smem);
  const int tid = threadIdx.x;
  const int wid = tid >> 5;
  const int lane = tid & 31;
  const int m0 = blockIdx.y * FBM;
  const int n0 = blockIdx.x * FBN;
  const int NC = K / GKC;

  const int wm = (wid & 3) * 32;
  const int wn = (wid >> 2) * 64;
  const int lrow = lane & 7;
  const int ltile = lane >> 3;
  const int a_r = (ltile & 1) * 8 + lrow;
  const int a_c = (ltile >> 1) * 8;
  const int b_r = (ltile >> 1) * 8 + lrow;
  const int b_c = (ltile & 1) * 8;

  const __half* gA = A + (size_t)m0 * K;
  const __half* gB = B + (size_t)n0 * K;

  auto load_stage = [&](int stg, int chunk) {
    const int kc = chunk * GKC;
    uint32_t sb = sbase + stg * FSTAGE_B;
#pragma unroll
    for (int i = 0; i < 4; i++) {
      int v = tid + i * 256;
      int r = v >> 3;
      int c = (v & 7) * 8;
      cp_async16(sb + (uint32_t)(r * KRS + c) * 2, gA + (size_t)r * K + kc + c);
      cp_async16(sb + FTILE_B + (uint32_t)(r * KRS + c) * 2,
                 gB + (size_t)r * K + kc + c);
    }
    CP_COMMIT();
  };

  float acc[2][8][4];
#pragma unroll
  for (int f = 0; f < 2; f++)
#pragma unroll
    for (int g = 0; g < 8; g++)
#pragma unroll
      for (int x = 0; x < 4; x++) acc[f][g][x] = 0.0f;

  load_stage(0, 0);
  load_stage(1, 1);

  for (int c = 0; c < NC; c++) {
    if (c + 1 < NC) { CP_WAIT1(); } else { CP_WAIT0(); }
    __syncthreads();
    if (c + 2 < NC) load_stage((c + 2) % 3, c + 2);

    uint32_t sb = sbase + (c % 3) * FSTAGE_B;
#pragma unroll
    for (int kk = 0; kk < 4; kk++) {
      const int k0 = kk * 16;
      uint32_t af[2][4];
#pragma unroll
      for (int f = 0; f < 2; f++) {
        uint32_t ar = (uint32_t)((wm + f * 16 + a_r) * KRS + k0 + a_c) * 2;
        ldsm_x4(af[f], sb + ar);
      }
#pragma unroll
      for (int g2 = 0; g2 < 4; g2++) {
        uint32_t br = (uint32_t)((wn + g2 * 16 + b_r) * KRS + k0 + b_c) * 2;
        uint32_t r4[4];
        ldsm_x4(r4, sb + FTILE_B + br);
#pragma unroll
        for (int f = 0; f < 2; f++) {
          mma16816h(acc[f][g2 * 2], af[f], r4);
          mma16816h(acc[f][g2 * 2 + 1], af[f], r4 + 2);
        }
      }
    }
  }

  const int gid = lane >> 2, tig = lane & 3;
#pragma unroll
  for (int f = 0; f < 2; f++) {
#pragma unroll
    for (int g = 0; g < 8; g++) {
      int row = m0 + wm + f * 16 + gid;
      int col = n0 + wn + g * 8 + tig * 2;
      *(float2*)(C + (size_t)row * N + col) = make_float2(acc[f][g][0], acc[f][g][1]);
      *(float2*)(C + (size_t)(row + 8) * N + col) = make_float2(acc[f][g][2], acc[f][g][3]);
    }
  }
}

// ---------------------------------------------------------------------------
// Tensor-core flash attention (unchanged from R15).
// ---------------------------------------------------------------------------
#define ABQ 128
#define ABKV 64
#define ARS 72
#define Q_ELEMS (ABQ * ARS)
#define KV_TILE (ABKV * ARS)
#define KV_STAGE (2 * KV_TILE)
#define ATT_SMEM ((Q_ELEMS + 3 * KV_STAGE) * 2)

__global__ __launch_bounds__(256, 2) void attn_mma_kernel(
    const __half* __restrict__ Q16, const __half* __restrict__ K16,
    const __half* __restrict__ V16, __half* __restrict__ O16) {
  extern __shared__ char sbuf[];
  const uint32_t sbase = smem_u32(sbuf);
  const int tid = threadIdx.x;
  const int wid = tid >> 5;
  const int lane = tid & 31;
  const int h = blockIdx.x;
  const int kvh = h / NREP;
  const int q0 = ((int)gridDim.y - 1 - (int)blockIdx.y) * ABQ;
  const int wm = wid * 16;

  const int lrow = lane & 7;
  const int ltile = lane >> 3;
  const int a_r = (ltile & 1) * 8 + lrow;
  const int a_c = (ltile >> 1) * 8;
  const int b_r = (ltile >> 1) * 8 + lrow;
  const int b_c = (ltile & 1) * 8;
  const int gid = lane >> 2, tig = lane & 3;

  const uint32_t q_s = sbase;

#pragma unroll
  for (int i = 0; i < 4; i++) {
    int v = tid + i * 256;
    int r = v >> 3, c = v & 7;
    size_t g = (size_t)(q0 + r) * (H * HD) + h * HD + c * 8;
    cp_async16(q_s + (uint32_t)(r * ARS + c * 8) * 2, Q16 + g);
  }

  auto load_kv = [&](int stg, int kv0) {
    uint32_t base = sbase + (Q_ELEMS + stg * KV_STAGE) * 2;
#pragma unroll
    for (int i = 0; i < 2; i++) {
      int v = tid + i * 256;
      int r = v >> 3, c = v & 7;
      size_t g = (size_t)(kv0 + r) * (KVH * HD) + kvh * HD + c * 8;
      uint32_t so = (uint32_t)(r * ARS + c * 8) * 2;
      cp_async16(base + 0 * KV_TILE * 2 + so, K16 + g);
      cp_async16(base + 1 * KV_TILE * 2 + so, V16 + g);
    }
    CP_COMMIT();
  };

  const int ntiles = (q0 + ABQ) / ABKV;
  load_kv(0, 0);
  load_kv(1, ABKV);

  float m_[2] = {-1e30f, -1e30f};
  float l_[2] = {0.0f, 0.0f};
  float o[8][4];
#pragma unroll
  for (int nf = 0; nf < 8; nf++)
#pragma unroll
    for (int j = 0; j < 4; j++) o[nf][j] = 0.0f;

  const float SCL = 0.18033688011112042f;
  const int row0 = q0 + wm + gid;

  for (int t = 0; t < ntiles; t++) {
    const int kv0 = t * ABKV;
    if (t + 1 < ntiles) { CP_WAIT1(); } else { CP_WAIT0(); }
    __syncthreads();
    if (t + 2 < ntiles) load_kv((t + 2) % 3, kv0 + 2 * ABKV);

    const uint32_t kvb = sbase + (Q_ELEMS + (t % 3) * KV_STAGE) * 2;

    float sc[8][4];
#pragma unroll
    for (int nf = 0; nf < 8; nf++)
#pragma unroll
      for (int j = 0; j < 4; j++) sc[nf][j] = 0.0f;

#pragma unroll
    for (int ks = 0; ks < 4; ks++) {
      const int k0 = ks * 16;
      uint32_t qh[4];
      ldsm_x4(qh, q_s + (uint32_t)((wm + a_r) * ARS + k0 + a_c) * 2);
#pragma unroll
      for (int ng = 0; ng < 4; ng++) {
        uint32_t br = kvb + (uint32_t)((ng * 16 + b_r) * ARS + k0 + b_c) * 2;
        uint32_t rh[4];
        ldsm_x4(rh, br);
        mma16816h(sc[ng * 2], qh, rh);
        mma16816h(sc[ng * 2 + 1], qh, rh + 2);
      }
    }

    const bool nomask = (kv0 + ABKV - 1 <= q0 + wm);
    if (nomask) {
#pragma unroll
      for (int nf = 0; nf < 8; nf++)
#pragma unroll
        for (int j = 0; j < 4; j++) sc[nf][j] *= SCL;
    } else {
#pragma unroll
      for (int nf = 0; nf < 8; nf++) {
        int col = kv0 + nf * 8 + tig * 2;
#pragma unroll
        for (int j = 0; j < 4; j++) {
          int cc = col + (j & 1);
          int rr = row0 + ((j >> 1) << 3);
          sc[nf][j] = (cc <= rr) ? sc[nf][j] * SCL : -1e30f;
        }
      }
    }

    float mx0 = -1e30f, mx1 = -1e30f;
#pragma unroll
    for (int nf = 0; nf < 8; nf++) {
      mx0 = fmaxf(mx0, fmaxf(sc[nf][0], sc[nf][1]));
      mx1 = fmaxf(mx1, fmaxf(sc[nf][2], sc[nf][3]));
    }
    mx0 = fmaxf(mx0, __shfl_xor_sync(0xffffffffu, mx0, 1));
    mx0 = fmaxf(mx0, __shfl_xor_sync(0xffffffffu, mx0, 2));
    mx1 = fmaxf(mx1, __shfl_xor_sync(0xffffffffu, mx1, 1));
    mx1 = fmaxf(mx1, __shfl_xor_sync(0xffffffffu, mx1, 2));
    float mn0 = fmaxf(m_[0], mx0);
    float mn1 = fmaxf(m_[1], mx1);
    float c0 = exp2_poly(m_[0] - mn0);
    float c1 = exp2_poly(m_[1] - mn1);
    m_[0] = mn0;
    m_[1] = mn1;

    float s0 = 0.0f, s1 = 0.0f;
#pragma unroll
    for (int nf = 0; nf < 8; nf++) {
      float p0 = exp2_poly(sc[nf][0] - mn0);
      float p1 = exp2_poly(sc[nf][1] - mn0);
      float p2 = exp2_poly(sc[nf][2] - mn1);
      float p3 = exp2_poly(sc[nf][3] - mn1);
      sc[nf][0] = p0; sc[nf][1] = p1; sc[nf][2] = p2; sc[nf][3] = p3;
      s0 += p0 + p1;
      s1 += p2 + p3;
    }
    l_[0] = l_[0] * c0 + s0;
    l_[1] = l_[1] * c1 + s1;
#pragma unroll
    for (int nf = 0; nf < 8; nf++) {
      o[nf][0] *= c0; o[nf][1] *= c0;
      o[nf][2] *= c1; o[nf][3] *= c1;
    }

    const uint32_t vb = kvb + KV_TILE * 2;
#pragma unroll
    for (int ks = 0; ks < 4; ks++) {
      uint32_t p16[4];
      p16[0] = pack_half2(sc[2 * ks][0], sc[2 * ks][1]);
      p16[1] = pack_half2(sc[2 * ks][2], sc[2 * ks][3]);
      p16[2] = pack_half2(sc[2 * ks + 1][0], sc[2 * ks + 1][1]);
      p16[3] = pack_half2(sc[2 * ks + 1][2], sc[2 * ks + 1][3]);
#pragma unroll
      for (int dg = 0; dg < 4; dg++) {
        uint32_t va = vb + (uint32_t)((ks * 16 + a_r) * ARS + dg * 16 + a_c) * 2;
        uint32_t vh[4];
        ldsm_x4_trans(vh, va);
        mma16816h(o[dg * 2], p16, vh);
        mma16816h(o[dg * 2 + 1], p16, vh + 2);
      }
    }
  }

  l_[0] += __shfl_xor_sync(0xffffffffu, l_[0], 1);
  l_[0] += __shfl_xor_sync(0xffffffffu, l_[0], 2);
  l_[1] += __shfl_xor_sync(0xffffffffu, l_[1], 1);
  l_[1] += __shfl_xor_sync(0xffffffffu, l_[1], 2);
  float inv0 = 1.0f / l_[0];
  float inv1 = 1.0f / l_[1];

#pragma unroll
  for (int nf = 0; nf < 8; nf++) {
    int col = h * HD + nf * 8 + tig * 2;
    *(__half2*)(O16 + (size_t)row0 * (H * HD) + col) =
        __floats2half2_rn(o[nf][0] * inv0, o[nf][1] * inv0);
    *(__half2*)(O16 + (size_t)(row0 + 8) * (H * HD) + col) =
        __floats2half2_rn(o[nf][2] * inv1, o[nf][3] * inv1);
  }
}

// ---------------------------------------------------------------------------
// Launch
// ---------------------------------------------------------------------------
extern "C" void kernel_launch(void* const* d_in, const int* in_sizes, int n_in,
                              void* d_out, int out_size) {
  const float* hs = (const float*)d_in[0];
  const float* Wq = (const float*)d_in[1];
  const float* Wk = (const float*)d_in[2];
  const float* Wv = (const float*)d_in[3];
  const float* Wo = (const float*)d_in[4];
  float* out = (float*)d_out;

  __half *X16, *WqkvT16, *Q16, *K16, *V16, *O16, *WoT16;
  cudaGetSymbolAddress((void**)&X16, g_X16);
  cudaGetSymbolAddress((void**)&WqkvT16, g_WqkvT16);
  cudaGetSymbolAddress((void**)&Q16, g_Q16);
  cudaGetSymbolAddress((void**)&K16, g_K16);
  cudaGetSymbolAddress((void**)&V16, g_V16);
  cudaGetSymbolAddress((void**)&O16, g_O16);
  cudaGetSymbolAddress((void**)&WoT16, g_WoT16);

  // 1. fused preprocessing (one launch)
  preprocess_kernel<<<PRE_TOTAL, dim3(32, 8)>>>(hs, Wq, Wk, Wv, Wo);

  cudaFuncSetAttribute(gemm_qkv_rope_kernel,
                       cudaFuncAttributeMaxDynamicSharedMemorySize, GEMM_SMEM);
  cudaFuncSetAttribute(gemm_fp16_kernel,
                       cudaFuncAttributeMaxDynamicSharedMemorySize, GEMM16_SMEM);

  // 2. QKV projection (single fp16, 128x128 tile) + fused RoPE
  {
    dim3 grid(QKV_N / GBN, S / GBM);  // 24 x 16
    gemm_qkv_rope_kernel<<<grid, 256, GEMM_SMEM>>>(X16, WqkvT16);
  }

  // 3. tensor-core flash attention -> fp16 O
  {
    cudaFuncSetAttribute(attn_mma_kernel,
                         cudaFuncAttributeMaxDynamicSharedMemorySize, ATT_SMEM);
    dim3 grid(H, S / ABQ);
    attn_mma_kernel<<<grid, 256, ATT_SMEM>>>(Q16, K16, V16, O16);
  }

  // 4. output projection (fp16)
  {
    dim3 grid(D / FBN, S / FBM);
    gemm_fp16_kernel<<<grid, 256, GEMM16_SMEM>>>(O16, WoT16, out, S, D, D);
  }
}

// round 17
// speedup vs baseline: 2.0542x; 1.0072x over previous
#include <cuda_runtime.h>
#include <cuda_bf16.h>
#include <cuda_fp16.h>
#include <cstdint>
#include <math.h>

#define S 2048
#define D 2048
#define H 32
#define KVH 8
#define HD 64
#define NREP (H / KVH)
#define QKV_N 3072
#define KCOL 2048
#define VCOL 2560

// ---------------------------------------------------------------------------
// Device-global scratch
// ---------------------------------------------------------------------------
__device__ __half g_X16[S * D];
__device__ __half g_WqkvT16[QKV_N * D];
__device__ __half g_Q16[S * H * HD];   // stores rope(q) * SCL (pre-scaled)
__device__ __half g_K16[S * KVH * HD];
__device__ __half g_V16[S * KVH * HD];
__device__ __half g_O16[S * D];
__device__ __half g_WoT16[D * D];
__device__ float g_cos[S * 32], g_sin[S * 32];

// ---------------------------------------------------------------------------
// Helpers
// ---------------------------------------------------------------------------
__device__ __forceinline__ uint32_t smem_u32(const void* p) {
  uint32_t a;
  asm("{ .reg .u64 t; cvta.to.shared.u64 t, %1; cvt.u32.u64 %0, t; }"
      : "=r"(a) : "l"(p));
  return a;
}

__device__ __forceinline__ void ldsm_x4(uint32_t* r, uint32_t addr) {
  asm volatile(
      "ldmatrix.sync.aligned.m8n8.x4.shared.b16 {%0,%1,%2,%3}, [%4];"
      : "=r"(r[0]), "=r"(r[1]), "=r"(r[2]), "=r"(r[3]) : "r"(addr));
}

__device__ __forceinline__ void ldsm_x4_trans(uint32_t* r, uint32_t addr) {
  asm volatile(
      "ldmatrix.sync.aligned.m8n8.x4.trans.shared.b16 {%0,%1,%2,%3}, [%4];"
      : "=r"(r[0]), "=r"(r[1]), "=r"(r[2]), "=r"(r[3]) : "r"(addr));
}

__device__ __forceinline__ void mma16816h(float* d, const uint32_t* a,
                                          const uint32_t* b) {
  asm volatile(
      "mma.sync.aligned.m16n8k16.row.col.f32.f16.f16.f32 "
      "{%0,%1,%2,%3}, {%4,%5,%6,%7}, {%8,%9}, {%0,%1,%2,%3};"
      : "+f"(d[0]), "+f"(d[1]), "+f"(d[2]), "+f"(d[3])
      : "r"(a[0]), "r"(a[1]), "r"(a[2]), "r"(a[3]), "r"(b[0]), "r"(b[1]));
}

__device__ __forceinline__ void cp_async16(uint32_t saddr, const void* gptr) {
  asm volatile("cp.async.cg.shared.global [%0], [%1], 16;" ::
                   "r"(saddr), "l"(__cvta_generic_to_global(gptr)));
}
#define CP_COMMIT() asm volatile("cp.async.commit_group;" ::: "memory")
#define CP_WAIT0() asm volatile("cp.async.wait_group 0;" ::: "memory")
#define CP_WAIT1() asm volatile("cp.async.wait_group 1;" ::: "memory")

__device__ __forceinline__ float exp2_poly(float x) {
  x = fmaxf(x, -126.0f);
  float fl = floorf(x);
  float f = x - fl;
  float p = 1.5403530393e-4f;
  p = fmaf(p, f, 1.3333558146e-3f);
  p = fmaf(p, f, 9.6181291076e-3f);
  p = fmaf(p, f, 5.5504108665e-2f);
  p = fmaf(p, f, 2.4022650696e-1f);
  p = fmaf(p, f, 6.9314718056e-1f);
  p = fmaf(p, f, 1.0f);
  return p * __int_as_float(((int)fl + 127) << 23);
}

__device__ __forceinline__ uint32_t pack_half2(float x, float y) {
  __half2 v = __floats2half2_rn(x, y);
  return *reinterpret_cast<uint32_t*>(&v);
}

// ---------------------------------------------------------------------------
// Fused preprocessing (one launch)
// ---------------------------------------------------------------------------
#define PRE_X_BLOCKS 4096
#define PRE_ROPE_BLOCKS 256
#define PRE_T_BLOCKS 10240
#define PRE_TOTAL (PRE_X_BLOCKS + PRE_ROPE_BLOCKS + PRE_T_BLOCKS)

__global__ void preprocess_kernel(const float* __restrict__ hs,
                                  const float* __restrict__ Wq,
                                  const float* __restrict__ Wk,
                                  const float* __restrict__ Wv,
                                  const float* __restrict__ Wo) {
  int bid = blockIdx.x;
  int tid = threadIdx.y * 32 + threadIdx.x;

  if (bid < PRE_X_BLOCKS) {
    int i = bid * 256 + tid;
    float4 v = ((const float4*)hs)[i];
    __half2* op = (__half2*)g_X16;
    op[i * 2 + 0] = __floats2half2_rn(v.x, v.y);
    op[i * 2 + 1] = __floats2half2_rn(v.z, v.w);
    return;
  }
  if (bid < PRE_X_BLOCKS + PRE_ROPE_BLOCKS) {
    int idx = (bid - PRE_X_BLOCKS) * 256 + tid;
    int s = idx >> 5, i = idx & 31;
    float inv = 1.0f / powf(10000.0f, (2.0f * i) / (float)HD);
    float ang = (float)s * inv;
    g_cos[idx] = cosf(ang);
    g_sin[idx] = sinf(ang);
    return;
  }

  __shared__ float t[32][33];
  int b = bid - PRE_X_BLOCKS - PRE_ROPE_BLOCKS;
  const float* W;
  __half* Th;
  int N, n0, k0;
  if (b < 4096) {
    W = Wq; Th = g_WqkvT16; N = 2048;
    n0 = (b & 63) * 32; k0 = (b >> 6) * 32;
  } else if (b < 5120) {
    int bb = b - 4096;
    W = Wk; Th = g_WqkvT16 + (size_t)KCOL * D;
    N = 512; n0 = (bb & 15) * 32; k0 = (bb >> 4) * 32;
  } else if (b < 6144) {
    int bb = b - 5120;
    W = Wv; Th = g_WqkvT16 + (size_t)VCOL * D;
    N = 512; n0 = (bb & 15) * 32; k0 = (bb >> 4) * 32;
  } else {
    int bb = b - 6144;
    W = Wo; Th = g_WoT16; N = 2048;
    n0 = (bb & 63) * 32; k0 = (bb >> 6) * 32;
  }
  int tx = threadIdx.x, ty = threadIdx.y;
#pragma unroll
  for (int i = 0; i < 4; i++)
    t[ty + i * 8][tx] = W[(size_t)(k0 + ty + i * 8) * N + n0 + tx];
  __syncthreads();
#pragma unroll
  for (int i = 0; i < 4; i++) {
    int n = ty + i * 8;
    Th[(size_t)(n0 + n) * D + k0 + tx] = __float2half(t[tx][n]);
  }
}

// ---------------------------------------------------------------------------
// QKV GEMM: single fp16 + fused RoPE epilogue (Q pre-scaled by SCL).
// ---------------------------------------------------------------------------
#define GBM 128
#define GBN 128
#define GKC 64
#define KRS 72
#define A_TILE (128 * KRS * 2)
#define QS_A 0
#define QS_B A_TILE
#define STAGE_B (2 * A_TILE)
#define GEMM_SMEM (3 * STAGE_B)

__global__ __launch_bounds__(256, 2) void gemm_qkv_rope_kernel(
    const __half* __restrict__ A, const __half* __restrict__ B) {
  extern __shared__ char smem[];
  const uint32_t sbase = smem_u32(smem);
  const int tid = threadIdx.x;
  const int wid = tid >> 5;
  const int lane = tid & 31;
  const int m0 = blockIdx.y * GBM;
  const int n0 = blockIdx.x * GBN;
  const int NC = D / GKC;

  const int wm = (wid & 3) * 32;
  const int wn = (wid >> 2) * 64;
  const int lrow = lane & 7;
  const int ltile = lane >> 3;
  const int a_r = (ltile & 1) * 8 + lrow;
  const int a_c = (ltile >> 1) * 8;
  const int b_r = (ltile >> 1) * 8 + lrow;
  const int b_c = (ltile & 1) * 8;

  const __half* gA = A + (size_t)m0 * D;
  const __half* gB = B + (size_t)n0 * D;

  auto load_stage = [&](int stg, int chunk) {
    const int kc = chunk * GKC;
    uint32_t sb = sbase + stg * STAGE_B;
#pragma unroll
    for (int i = 0; i < 4; i++) {
      int v = tid + i * 256;
      int r = v >> 3;
      int c = (v & 7) * 8;
      cp_async16(sb + QS_A + (uint32_t)(r * KRS + c) * 2,
                 gA + (size_t)r * D + kc + c);
      cp_async16(sb + QS_B + (uint32_t)(r * KRS + c) * 2,
                 gB + (size_t)r * D + kc + c);
    }
    CP_COMMIT();
  };

  float acc[2][8][4];
#pragma unroll
  for (int f = 0; f < 2; f++)
#pragma unroll
    for (int g = 0; g < 8; g++)
#pragma unroll
      for (int x = 0; x < 4; x++) acc[f][g][x] = 0.0f;

  load_stage(0, 0);
  load_stage(1, 1);

  for (int c = 0; c < NC; c++) {
    if (c + 1 < NC) { CP_WAIT1(); } else { CP_WAIT0(); }
    __syncthreads();
    if (c + 2 < NC) load_stage((c + 2) % 3, c + 2);

    uint32_t sb = sbase + (c % 3) * STAGE_B;
#pragma unroll
    for (int kk = 0; kk < 4; kk++) {
      const int k0 = kk * 16;
      uint32_t af[2][4];
#pragma unroll
      for (int f = 0; f < 2; f++) {
        uint32_t ar = (uint32_t)((wm + f * 16 + a_r) * KRS + k0 + a_c) * 2;
        ldsm_x4(af[f], sb + QS_A + ar);
      }
#pragma unroll
      for (int g2 = 0; g2 < 4; g2++) {
        uint32_t br = (uint32_t)((wn + g2 * 16 + b_r) * KRS + k0 + b_c) * 2;
        uint32_t r4[4];
        ldsm_x4(r4, sb + QS_B + br);
#pragma unroll
        for (int f = 0; f < 2; f++) {
          mma16816h(acc[f][g2 * 2], af[f], r4);
          mma16816h(acc[f][g2 * 2 + 1], af[f], r4 + 2);
        }
      }
    }
  }

  // ---- fused RoPE + fp16 pack epilogue (Q scaled by SCL) ----
  const float SCL = 0.18033688011112042f;  // (1/8) * log2(e)
  const int gid = lane >> 2, tig = lane & 3;
#pragma unroll
  for (int f = 0; f < 2; f++) {
    int rowA = m0 + wm + f * 16 + gid;
#pragma unroll
    for (int g = 0; g < 8; g++) {
      int C = n0 + wn + g * 8 + tig * 2;
#pragma unroll
      for (int half = 0; half < 2; half++) {
        int s = rowA + half * 8;
        float x = acc[f][g][half * 2 + 0];
        float y = acc[f][g][half * 2 + 1];
        if (C < KCOL) {  // Q: rope, pre-scaled
          int i = (C & 63) >> 1;
          float cs = g_cos[s * 32 + i], sn = g_sin[s * 32 + i];
          float xr = (x * cs - y * sn) * SCL;
          float xi = (x * sn + y * cs) * SCL;
          *(uint32_t*)(g_Q16 + (size_t)s * (H * HD) + C) = pack_half2(xr, xi);
        } else if (C < VCOL) {  // K: rope
          int off = C - KCOL;
          int i = (off & 63) >> 1;
          float cs = g_cos[s * 32 + i], sn = g_sin[s * 32 + i];
          float xr = x * cs - y * sn;
          float xi = x * sn + y * cs;
          *(uint32_t*)(g_K16 + (size_t)s * (KVH * HD) + off) = pack_half2(xr, xi);
        } else {  // V
          int off = C - VCOL;
          *(uint32_t*)(g_V16 + (size_t)s * (KVH * HD) + off) = pack_half2(x, y);
        }
      }
    }
  }
}

// ---------------------------------------------------------------------------
// fp16 single-product GEMM (Wo). 128x128xK64, 3-stage pipeline.
// ---------------------------------------------------------------------------
#define FBM 128
#define FBN 128
#define FTILE_B (128 * KRS * 2)
#define FSTAGE_B (2 * FTILE_B)
#define GEMM16_SMEM (3 * FSTAGE_B)

__global__ __launch_bounds__(256, 2) void gemm_fp16_kernel(
    const __half* __restrict__ A, const __half* __restrict__ B,
    float* __restrict__ C, int M, int N, int K) {
  extern __shared__ char smem[];
  const uint32_t sbase = smem_u32(smem);
  const int tid = threadIdx.x;
  const int wid = tid >> 5;
  const int lane = tid & 31;
  const int m0 = blockIdx.y * FBM;
  const int n0 = blockIdx.x * FBN;
  const int NC = K / GKC;

  const int wm = (wid & 3) * 32;
  const int wn = (wid >> 2) * 64;
  const int lrow = lane & 7;
  const int ltile = lane >> 3;
  const int a_r = (ltile & 1) * 8 + lrow;
  const int a_c = (ltile >> 1) * 8;
  const int b_r = (ltile >> 1) * 8 + lrow;
  const int b_c = (ltile & 1) * 8;

  const __half* gA = A + (size_t)m0 * K;
  const __half* gB = B + (size_t)n0 * K;

  auto load_stage = [&](int stg, int chunk) {
    const int kc = chunk * GKC;
    uint32_t sb = sbase + stg * FSTAGE_B;
#pragma unroll
    for (int i = 0; i < 4; i++) {
      int v = tid + i * 256;
      int r = v >> 3;
      int c = (v & 7) * 8;
      cp_async16(sb + (uint32_t)(r * KRS + c) * 2, gA + (size_t)r * K + kc + c);
      cp_async16(sb + FTILE_B + (uint32_t)(r * KRS + c) * 2,
                 gB + (size_t)r * K + kc + c);
    }
    CP_COMMIT();
  };

  float acc[2][8][4];
#pragma unroll
  for (int f = 0; f < 2; f++)
#pragma unroll
    for (int g = 0; g < 8; g++)
#pragma unroll
      for (int x = 0; x < 4; x++) acc[f][g][x] = 0.0f;

  load_stage(0, 0);
  load_stage(1, 1);

  for (int c = 0; c < NC; c++) {
    if (c + 1 < NC) { CP_WAIT1(); } else { CP_WAIT0(); }
    __syncthreads();
    if (c + 2 < NC) load_stage((c + 2) % 3, c + 2);

    uint32_t sb = sbase + (c % 3) * FSTAGE_B;
#pragma unroll
    for (int kk = 0; kk < 4; kk++) {
      const int k0 = kk * 16;
      uint32_t af[2][4];
#pragma unroll
      for (int f = 0; f < 2; f++) {
        uint32_t ar = (uint32_t)((wm + f * 16 + a_r) * KRS + k0 + a_c) * 2;
        ldsm_x4(af[f], sb + ar);
      }
#pragma unroll
      for (int g2 = 0; g2 < 4; g2++) {
        uint32_t br = (uint32_t)((wn + g2 * 16 + b_r) * KRS + k0 + b_c) * 2;
        uint32_t r4[4];
        ldsm_x4(r4, sb + FTILE_B + br);
#pragma unroll
        for (int f = 0; f < 2; f++) {
          mma16816h(acc[f][g2 * 2], af[f], r4);
          mma16816h(acc[f][g2 * 2 + 1], af[f], r4 + 2);
        }
      }
    }
  }

  const int gid = lane >> 2, tig = lane & 3;
#pragma unroll
  for (int f = 0; f < 2; f++) {
#pragma unroll
    for (int g = 0; g < 8; g++) {
      int row = m0 + wm + f * 16 + gid;
      int col = n0 + wn + g * 8 + tig * 2;
      *(float2*)(C + (size_t)row * N + col) = make_float2(acc[f][g][0], acc[f][g][1]);
      *(float2*)(C + (size_t)(row + 8) * N + col) = make_float2(acc[f][g][2], acc[f][g][3]);
    }
  }
}

// ---------------------------------------------------------------------------
// Tensor-core flash attention. Q pre-scaled; Q fragments hoisted to registers.
// ---------------------------------------------------------------------------
#define ABQ 128
#define ABKV 64
#define ARS 72
#define Q_ELEMS (ABQ * ARS)
#define KV_TILE (ABKV * ARS)
#define KV_STAGE (2 * KV_TILE)
#define ATT_SMEM ((Q_ELEMS + 3 * KV_STAGE) * 2)

__global__ __launch_bounds__(256, 2) void attn_mma_kernel(
    const __half* __restrict__ Q16, const __half* __restrict__ K16,
    const __half* __restrict__ V16, __half* __restrict__ O16) {
  extern __shared__ char sbuf[];
  const uint32_t sbase = smem_u32(sbuf);
  const int tid = threadIdx.x;
  const int wid = tid >> 5;
  const int lane = tid & 31;
  const int h = blockIdx.x;
  const int kvh = h / NREP;
  const int q0 = ((int)gridDim.y - 1 - (int)blockIdx.y) * ABQ;
  const int wm = wid * 16;

  const int lrow = lane & 7;
  const int ltile = lane >> 3;
  const int a_r = (ltile & 1) * 8 + lrow;
  const int a_c = (ltile >> 1) * 8;
  const int b_r = (ltile >> 1) * 8 + lrow;
  const int b_c = (ltile & 1) * 8;
  const int gid = lane >> 2, tig = lane & 3;

  const uint32_t q_s = sbase;

#pragma unroll
  for (int i = 0; i < 4; i++) {
    int v = tid + i * 256;
    int r = v >> 3, c = v & 7;
    size_t g = (size_t)(q0 + r) * (H * HD) + h * HD + c * 8;
    cp_async16(q_s + (uint32_t)(r * ARS + c * 8) * 2, Q16 + g);
  }

  auto load_kv = [&](int stg, int kv0) {
    uint32_t base = sbase + (Q_ELEMS + stg * KV_STAGE) * 2;
#pragma unroll
    for (int i = 0; i < 2; i++) {
      int v = tid + i * 256;
      int r = v >> 3, c = v & 7;
      size_t g = (size_t)(kv0 + r) * (KVH * HD) + kvh * HD + c * 8;
      uint32_t so = (uint32_t)(r * ARS + c * 8) * 2;
      cp_async16(base + 0 * KV_TILE * 2 + so, K16 + g);
      cp_async16(base + 1 * KV_TILE * 2 + so, V16 + g);
    }
    CP_COMMIT();
  };

  const int ntiles = (q0 + ABQ) / ABKV;
  load_kv(0, 0);   // group 0 includes the Q loads above
  load_kv(1, ABKV);

  // Hoist Q fragments into registers (Q smem never overwritten).
  CP_WAIT1();  // group 0 (Q + KV tile 0) complete
  __syncthreads();
  uint32_t qh[4][4];
#pragma unroll
  for (int ks = 0; ks < 4; ks++)
    ldsm_x4(qh[ks], q_s + (uint32_t)((wm + a_r) * ARS + ks * 16 + a_c) * 2);

  float m_[2] = {-1e30f, -1e30f};
  float l_[2] = {0.0f, 0.0f};
  float o[8][4];
#pragma unroll
  for (int nf = 0; nf < 8; nf++)
#pragma unroll
    for (int j = 0; j < 4; j++) o[nf][j] = 0.0f;

  const int row0 = q0 + wm + gid;

  for (int t = 0; t < ntiles; t++) {
    const int kv0 = t * ABKV;
    if (t + 1 < ntiles) { CP_WAIT1(); } else { CP_WAIT0(); }
    __syncthreads();
    if (t + 2 < ntiles) load_kv((t + 2) % 3, kv0 + 2 * ABKV);

    const uint32_t kvb = sbase + (Q_ELEMS + (t % 3) * KV_STAGE) * 2;

    float sc[8][4];
#pragma unroll
    for (int nf = 0; nf < 8; nf++)
#pragma unroll
      for (int j = 0; j < 4; j++) sc[nf][j] = 0.0f;

#pragma unroll
    for (int ks = 0; ks < 4; ks++) {
      const int k0 = ks * 16;
#pragma unroll
      for (int ng = 0; ng < 4; ng++) {
        uint32_t br = kvb + (uint32_t)((ng * 16 + b_r) * ARS + k0 + b_c) * 2;
        uint32_t rh[4];
        ldsm_x4(rh, br);
        mma16816h(sc[ng * 2], qh[ks], rh);
        mma16816h(sc[ng * 2 + 1], qh[ks], rh + 2);
      }
    }

    // causal mask (scale already folded into Q)
    const bool needmask = !(kv0 + ABKV - 1 <= q0 + wm);
    if (needmask) {
#pragma unroll
      for (int nf = 0; nf < 8; nf++) {
        int col = kv0 + nf * 8 + tig * 2;
#pragma unroll
        for (int j = 0; j < 4; j++) {
          int cc = col + (j & 1);
          int rr = row0 + ((j >> 1) << 3);
          if (cc > rr) sc[nf][j] = -1e30f;
        }
      }
    }

    float mx0 = -1e30f, mx1 = -1e30f;
#pragma unroll
    for (int nf = 0; nf < 8; nf++) {
      mx0 = fmaxf(mx0, fmaxf(sc[nf][0], sc[nf][1]));
      mx1 = fmaxf(mx1, fmaxf(sc[nf][2], sc[nf][3]));
    }
    mx0 = fmaxf(mx0, __shfl_xor_sync(0xffffffffu, mx0, 1));
    mx0 = fmaxf(mx0, __shfl_xor_sync(0xffffffffu, mx0, 2));
    mx1 = fmaxf(mx1, __shfl_xor_sync(0xffffffffu, mx1, 1));
    mx1 = fmaxf(mx1, __shfl_xor_sync(0xffffffffu, mx1, 2));
    float mn0 = fmaxf(m_[0], mx0);
    float mn1 = fmaxf(m_[1], mx1);
    float c0 = exp2_poly(m_[0] - mn0);
    float c1 = exp2_poly(m_[1] - mn1);
    m_[0] = mn0;
    m_[1] = mn1;

    float s0 = 0.0f, s1 = 0.0f;
#pragma unroll
    for (int nf = 0; nf < 8; nf++) {
      float p0 = exp2_poly(sc[nf][0] - mn0);
      float p1 = exp2_poly(sc[nf][1] - mn0);
      float p2 = exp2_poly(sc[nf][2] - mn1);
      float p3 = exp2_poly(sc[nf][3] - mn1);
      sc[nf][0] = p0; sc[nf][1] = p1; sc[nf][2] = p2; sc[nf][3] = p3;
      s0 += p0 + p1;
      s1 += p2 + p3;
    }
    l_[0] = l_[0] * c0 + s0;
    l_[1] = l_[1] * c1 + s1;
#pragma unroll
    for (int nf = 0; nf < 8; nf++) {
      o[nf][0] *= c0; o[nf][1] *= c0;
      o[nf][2] *= c1; o[nf][3] *= c1;
    }

    const uint32_t vb = kvb + KV_TILE * 2;
#pragma unroll
    for (int ks = 0; ks < 4; ks++) {
      uint32_t p16[4];
      p16[0] = pack_half2(sc[2 * ks][0], sc[2 * ks][1]);
      p16[1] = pack_half2(sc[2 * ks][2], sc[2 * ks][3]);
      p16[2] = pack_half2(sc[2 * ks + 1][0], sc[2 * ks + 1][1]);
      p16[3] = pack_half2(sc[2 * ks + 1][2], sc[2 * ks + 1][3]);
#pragma unroll
      for (int dg = 0; dg < 4; dg++) {
        uint32_t va = vb + (uint32_t)((ks * 16 + a_r) * ARS + dg * 16 + a_c) * 2;
        uint32_t vh[4];
        ldsm_x4_trans(vh, va);
        mma16816h(o[dg * 2], p16, vh);
        mma16816h(o[dg * 2 + 1], p16, vh + 2);
      }
    }
  }

  l_[0] += __shfl_xor_sync(0xffffffffu, l_[0], 1);
  l_[0] += __shfl_xor_sync(0xffffffffu, l_[0], 2);
  l_[1] += __shfl_xor_sync(0xffffffffu, l_[1], 1);
  l_[1] += __shfl_xor_sync(0xffffffffu, l_[1], 2);
  float inv0 = 1.0f / l_[0];
  float inv1 = 1.0f / l_[1];

#pragma unroll
  for (int nf = 0; nf < 8; nf++) {
    int col = h * HD + nf * 8 + tig * 2;
    *(__half2*)(O16 + (size_t)row0 * (H * HD) + col) =
        __floats2half2_rn(o[nf][0] * inv0, o[nf][1] * inv0);
    *(__half2*)(O16 + (size_t)(row0 + 8) * (H * HD) + col) =
        __floats2half2_rn(o[nf][2] * inv1, o[nf][3] * inv1);
  }
}

// ---------------------------------------------------------------------------
// Launch
// ---------------------------------------------------------------------------
extern "C" void kernel_launch(void* const* d_in, const int* in_sizes, int n_in,
                              void* d_out, int out_size) {
  const float* hs = (const float*)d_in[0];
  const float* Wq = (const float*)d_in[1];
  const float* Wk = (const float*)d_in[2];
  const float* Wv = (const float*)d_in[3];
  const float* Wo = (const float*)d_in[4];
  float* out = (float*)d_out;

  __half *X16, *WqkvT16, *Q16, *K16, *V16, *O16, *WoT16;
  cudaGetSymbolAddress((void**)&X16, g_X16);
  cudaGetSymbolAddress((void**)&WqkvT16, g_WqkvT16);
  cudaGetSymbolAddress((void**)&Q16, g_Q16);
  cudaGetSymbolAddress((void**)&K16, g_K16);
  cudaGetSymbolAddress((void**)&V16, g_V16);
  cudaGetSymbolAddress((void**)&O16, g_O16);
  cudaGetSymbolAddress((void**)&WoT16, g_WoT16);

  // 1. fused preprocessing (one launch)
  preprocess_kernel<<<PRE_TOTAL, dim3(32, 8)>>>(hs, Wq, Wk, Wv, Wo);

  cudaFuncSetAttribute(gemm_qkv_rope_kernel,
                       cudaFuncAttributeMaxDynamicSharedMemorySize, GEMM_SMEM);
  cudaFuncSetAttribute(gemm_fp16_kernel,
                       cudaFuncAttributeMaxDynamicSharedMemorySize, GEMM16_SMEM);

  // 2. QKV projection + fused RoPE (Q pre-scaled)
  {
    dim3 grid(QKV_N / GBN, S / GBM);
    gemm_qkv_rope_kernel<<<grid, 256, GEMM_SMEM>>>(X16, WqkvT16);
  }

  // 3. tensor-core flash attention (Q frags hoisted) -> fp16 O
  {
    cudaFuncSetAttribute(attn_mma_kernel,
                         cudaFuncAttributeMaxDynamicSharedMemorySize, ATT_SMEM);
    dim3 grid(H, S / ABQ);
    attn_mma_kernel<<<grid, 256, ATT_SMEM>>>(Q16, K16, V16, O16);
  }

  // 4. output projection (fp16)
  {
    dim3 grid(D / FBN, S / FBM);
    gemm_fp16_kernel<<<grid, 256, GEMM16_SMEM>>>(O16, WoT16, out, S, D, D);
  }
}